// round 8
// baseline (speedup 1.0000x reference)
#include <cuda_runtime.h>
#include <cuda_bf16.h>
#include <cstdint>

#define D 128
#define NPB 32
#define Y_PAD 136
#define NODE_PAD 264
#define MAXN 50000
#define TILE_M 128

// ---------------- device scratch (allocation-free rule) ----------------
__device__ float g_agg[MAXN * D];
__device__ float g_num[MAXN * 3];
__device__ float g_cnt[MAXN];
__device__ float g_U[MAXN * D];   // h @ We1[0:128,:] + be1
__device__ float g_V[MAXN * D];   // h @ We1[128:256,:]
__device__ int   g_is64;
// bf16 weight smem-images, XOR-swizzled [n][k] (256B rows): 0 = We2, 1 = Wx1
__device__ unsigned short g_Bhi[2 * 16384];
__device__ unsigned short g_Blo[2 * 16384];

__device__ __forceinline__ float silu_f(float v) {
    return v * (1.0f / (1.0f + __expf(-v)));
}
__device__ __forceinline__ float f4get(const float4& v, int k) {
    return k == 0 ? v.x : (k == 1 ? v.y : (k == 2 ? v.z : v.w));
}
__device__ __forceinline__ uint32_t smem_u32(const void* p) {
    uint32_t a;
    asm("{ .reg .u64 t; cvta.to.shared.u64 t, %1; cvt.u32.u64 %0, t; }"
        : "=r"(a) : "l"(p));
    return a;
}

#define LDSM_X4(r, addr)                                                        \
    asm volatile("ldmatrix.sync.aligned.m8n8.x4.shared.b16 {%0,%1,%2,%3}, [%4];"\
        : "=r"((r)[0]), "=r"((r)[1]), "=r"((r)[2]), "=r"((r)[3]) : "r"(addr))

#define MMA_BF16(d, a, b0, b1)                                                  \
    asm volatile("mma.sync.aligned.m16n8k16.row.col.f32.bf16.bf16.f32 "         \
        "{%0,%1,%2,%3}, {%4,%5,%6,%7}, {%8,%9}, {%0,%1,%2,%3};"                 \
        : "+f"((d)[0]), "+f"((d)[1]), "+f"((d)[2]), "+f"((d)[3])                \
        : "r"((a)[0]), "r"((a)[1]), "r"((a)[2]), "r"((a)[3]), "r"(b0), "r"(b1))

__device__ __forceinline__ void split2(float v0, float v1, uint32_t& hi, uint32_t& lo) {
    __nv_bfloat16 h0 = __float2bfloat16(v0), h1 = __float2bfloat16(v1);
    float r0 = v0 - __bfloat162float(h0), r1 = v1 - __bfloat162float(h1);
    hi = (uint32_t)__bfloat16_as_ushort(h0) | ((uint32_t)__bfloat16_as_ushort(h1) << 16);
    lo = (uint32_t)__bfloat16_as_ushort(__float2bfloat16(r0))
       | ((uint32_t)__bfloat16_as_ushort(__float2bfloat16(r1)) << 16);
}
__device__ __forceinline__ float blo16(uint32_t u) {
    return __bfloat162float(__ushort_as_bfloat16((unsigned short)(u & 0xffff)));
}
__device__ __forceinline__ float bhi16(uint32_t u) {
    return __bfloat162float(__ushort_as_bfloat16((unsigned short)(u >> 16)));
}

// ---------------- misc small kernels ----------------
__global__ void detect_kernel(const void* eidx_raw, int E, int Nn) {
    const long long* p = (const long long*)eidx_raw;
    int ok = 1;
    for (int i = 0; i < 64 && i < E; i++) {
        long long v = p[i];
        if (v < 0 || v >= (long long)Nn) { ok = 0; break; }
    }
    g_is64 = ok;
}
__device__ __forceinline__ int load_idx(const void* eidx_raw, long long pos, int is64) {
    if (is64) return (int)((const long long*)eidx_raw)[pos];
    return ((const int*)eidx_raw)[pos];
}
__global__ void zero_kernel(int n_nodes) {
    int idx = blockIdx.x * blockDim.x + threadIdx.x;
    if (idx < n_nodes * D) g_agg[idx] = 0.f;
    if (idx < n_nodes * 3) g_num[idx] = 0.f;
    if (idx < n_nodes)     g_cnt[idx] = 0.f;
}

// Build bf16 hi/lo images of We2^T, Wx1^T in swizzled [n][k] layout:
// byte off = n*256 + ((k/8 ^ (n&15))*16) + (k%8)*2
__global__ void prep_weights_kernel(const float* __restrict__ We2,
                                    const float* __restrict__ Wx1) {
    int idx = blockIdx.x * blockDim.x + threadIdx.x;
    if (idx >= 2 * 16384) return;
    int m = idx >> 14;
    int e = idx & 16383;
    int n = e >> 7;
    int k = e & 127;
    const float* W = m ? Wx1 : We2;
    float v = W[k * D + n];
    __nv_bfloat16 hb = __float2bfloat16(v);
    float lo = v - __bfloat162float(hb);
    int off = n * 256 + (((k >> 3) ^ (n & 15)) << 4) + (k & 7) * 2;
    g_Bhi[m * 16384 + (off >> 1)] = __bfloat16_as_ushort(hb);
    g_Blo[m * 16384 + (off >> 1)] = __bfloat16_as_ushort(__float2bfloat16(lo));
}

// ---------------- SMEM layout (bytes) ----------------
#define SM_W1HI 0
#define SM_W1LO 32768
#define SM_W2HI 65536
#define SM_W2LO 98304
#define SM_AHI  131072
#define SM_ALO  163840
#define SM_WGEO 196608   // 11*128 f32 = 5632
#define SM_GEO  202240   // 128*13 f32 = 6656
#define SM_DST  208896   // 128 int
#define SM_SRC  209408
#define SM_BE2  209920   // 128 f32
#define SM_BX1  210432
#define SM_WX2  210944
#define SM_PPART 211456  // 2*128 f32
#define SM_BX2  212480
#define SM_TOTAL 212544

// Split-bf16 GEMM: D[128,128] = A[128,128] @ B^T, warp block 32x64.
__device__ __forceinline__ void gemm_tile(
    uint32_t aHi, uint32_t aLo, uint32_t bHi, uint32_t bLo,
    int lane, int m0, int nb, float acc[2][8][4])
{
    #pragma unroll
    for (int ma = 0; ma < 2; ma++)
        #pragma unroll
        for (int na = 0; na < 8; na++)
            #pragma unroll
            for (int q = 0; q < 4; q++) acc[ma][na][q] = 0.f;

    const int arow_l = lane & 15;
    const int akh    = lane >> 4;
    const int brow_l = ((lane >> 4) & 1) * 8 + (lane & 7);
    const int bkh    = (lane >> 3) & 1;

    #pragma unroll 1
    for (int kb = 0; kb < 8; kb++) {
        uint32_t ah[2][4], al[2][4], bh[4][4], bl[4][4];
        #pragma unroll
        for (int ma = 0; ma < 2; ma++) {
            int row = m0 + ma * 16 + arow_l;
            int ch  = kb * 2 + akh;
            uint32_t off = row * 256 + ((ch ^ (row & 15)) << 4);
            LDSM_X4(ah[ma], aHi + off);
            LDSM_X4(al[ma], aLo + off);
        }
        #pragma unroll
        for (int p = 0; p < 4; p++) {
            int row = nb + p * 16 + brow_l;
            int ch  = kb * 2 + bkh;
            uint32_t off = row * 256 + ((ch ^ (row & 15)) << 4);
            LDSM_X4(bh[p], bHi + off);
            LDSM_X4(bl[p], bLo + off);
        }
        #pragma unroll
        for (int ma = 0; ma < 2; ma++)
            #pragma unroll
            for (int na = 0; na < 8; na++) {
                uint32_t b0 = bh[na >> 1][(na & 1) * 2];
                uint32_t b1 = bh[na >> 1][(na & 1) * 2 + 1];
                uint32_t c0 = bl[na >> 1][(na & 1) * 2];
                uint32_t c1 = bl[na >> 1][(na & 1) * 2 + 1];
                MMA_BF16(acc[ma][na], ah[ma], b0, b1);
                MMA_BF16(acc[ma][na], al[ma], b0, b1);
                MMA_BF16(acc[ma][na], ah[ma], c0, c1);
            }
    }
}

__global__ __launch_bounds__(256, 1) void edge_mma_kernel(
    const float* __restrict__ x, const float* __restrict__ vel,
    const void* __restrict__ eidx_raw, const float* __restrict__ We1,
    const float* __restrict__ be2, const float* __restrict__ bx1,
    const float* __restrict__ Wx2, const float* __restrict__ bx2,
    float* __restrict__ out_m, int E)
{
    extern __shared__ char smem[];
    float* smf = (float*)smem;
    const uint32_t sb = smem_u32(smem);
    const int tid  = threadIdx.x;
    const int warp = tid >> 5;
    const int lane = tid & 31;
    const int m0   = (warp & 3) * 32;   // GEMM row block
    const int nb   = (warp >> 2) * 64;  // GEMM col block
    const int r    = tid & 127;         // scalar-phase row (edge in tile)
    const int cb   = (tid >> 7) << 6;   // scalar-phase col half
    const int is64 = g_is64;

    // ---- one-time init: weights + biases to smem ----
    {
        const uint4* shi = (const uint4*)g_Bhi;
        const uint4* slo = (const uint4*)g_Blo;
        for (int i = tid; i < 2048; i += 256) {
            ((uint4*)(smem + SM_W1HI))[i] = shi[i];
            ((uint4*)(smem + SM_W1LO))[i] = slo[i];
            ((uint4*)(smem + SM_W2HI))[i] = shi[2048 + i];
            ((uint4*)(smem + SM_W2LO))[i] = slo[2048 + i];
        }
    }
    if (tid < 128) {
        smf[(SM_BE2 >> 2) + tid] = be2[tid];
        smf[(SM_BX1 >> 2) + tid] = bx1[tid];
        smf[(SM_WX2 >> 2) + tid] = Wx2[tid];
    }
    if (tid == 0) smf[SM_BX2 >> 2] = bx2[0];
    for (int i = tid; i < 11 * 128; i += 256)
        smf[(SM_WGEO >> 2) + i] = We1[256 * D + i];
    __syncthreads();

    float* geo_sf = smf + (SM_GEO >> 2);
    int*   dst_s  = (int*)(smem + SM_DST);
    int*   src_s  = (int*)(smem + SM_SRC);
    float* ppart  = smf + (SM_PPART >> 2);

    const int ntiles = (E + TILE_M - 1) / TILE_M;

    for (int tile = blockIdx.x; tile < ntiles; tile += gridDim.x) {
        const int ebase = tile * TILE_M;

        // ===== stage: indices + geometry (tid<128, edge = tid) =====
        float relx = 0.f, rely = 0.f, relz = 0.f;
        int dreg = 0; bool vreg = false;
        if (tid < 128) {
            int eg = ebase + tid;
            vreg = (eg < E);
            int ec = vreg ? eg : 0;
            int s = load_idx(eidx_raw, ec, is64);
            int d = load_idx(eidx_raw, (long long)E + ec, is64);
            src_s[tid] = s; dst_s[tid] = d; dreg = d;
            float rx = x[s*3+0] - x[d*3+0];
            float ry = x[s*3+1] - x[d*3+1];
            float rz = x[s*3+2] - x[d*3+2];
            relx = rx; rely = ry; relz = rz;
            float d2 = rx*rx + ry*ry + rz*rz;
            float dist = fmaxf(sqrtf(d2), 1e-8f);
            float inv = 1.0f / dist;
            float ux = rx*inv, uy = ry*inv, uz = rz*inv;
            geo_sf[tid * 13 + 0] = d2;
            #pragma unroll
            for (int j = 0; j < 5; j++) {
                const float* vs = vel + (size_t)s * 15 + j * 3;
                const float* vd = vel + (size_t)d * 15 + j * 3;
                geo_sf[tid * 13 + 1 + j] = vs[0]*ux + vs[1]*uy + vs[2]*uz;
                geo_sf[tid * 13 + 6 + j] = vd[0]*ux + vd[1]*uy + vd[2]*uz;
            }
        }
        __syncthreads();

        // ===== scalar: z = U[src]+V[dst]+geo@Wgeo; y1 = silu(z) -> A bufs =====
        {
            float z[64];
            int s2 = src_s[r], d2i = dst_s[r];
            const float4* Ub = (const float4*)(g_U + (size_t)s2 * D + cb);
            const float4* Vb = (const float4*)(g_V + (size_t)d2i * D + cb);
            #pragma unroll
            for (int j = 0; j < 16; j++) {
                float4 u = Ub[j], v = Vb[j];
                z[4*j+0] = u.x + v.x; z[4*j+1] = u.y + v.y;
                z[4*j+2] = u.z + v.z; z[4*j+3] = u.w + v.w;
            }
            #pragma unroll 1
            for (int k = 0; k < 11; k++) {
                float f = geo_sf[r * 13 + k];
                const float4* wr = (const float4*)(smf + (SM_WGEO >> 2) + k * D + cb);
                #pragma unroll
                for (int j = 0; j < 16; j++) {
                    float4 w = wr[j];
                    z[4*j+0] = fmaf(f, w.x, z[4*j+0]);
                    z[4*j+1] = fmaf(f, w.y, z[4*j+1]);
                    z[4*j+2] = fmaf(f, w.z, z[4*j+2]);
                    z[4*j+3] = fmaf(f, w.w, z[4*j+3]);
                }
            }
            #pragma unroll
            for (int j = 0; j < 8; j++) {
                float v0 = silu_f(z[8*j+0]), v1 = silu_f(z[8*j+1]);
                float v2 = silu_f(z[8*j+2]), v3 = silu_f(z[8*j+3]);
                float v4 = silu_f(z[8*j+4]), v5 = silu_f(z[8*j+5]);
                float v6 = silu_f(z[8*j+6]), v7 = silu_f(z[8*j+7]);
                uint4 uh, ul;
                split2(v0, v1, uh.x, ul.x);
                split2(v2, v3, uh.y, ul.y);
                split2(v4, v5, uh.z, ul.z);
                split2(v6, v7, uh.w, ul.w);
                int chunk = (cb >> 3) + j;
                uint32_t off = r * 256 + ((chunk ^ (r & 15)) << 4);
                *(uint4*)(smem + SM_AHI + off) = uh;
                *(uint4*)(smem + SM_ALO + off) = ul;
            }
        }
        __syncthreads();

        // ===== GEMM1: y1 @ We2 =====
        float acc[2][8][4];
        gemm_tile(sb + SM_AHI, sb + SM_ALO, sb + SM_W1HI, sb + SM_W1LO,
                  lane, m0, nb, acc);
        __syncthreads();   // A reads done block-wide before overwrite

        // epilogue1: m = silu(acc + be2) -> A buffers (fragment layout)
        #pragma unroll
        for (int ma = 0; ma < 2; ma++)
            #pragma unroll
            for (int na = 0; na < 8; na++) {
                int col = nb + na * 8 + (lane & 3) * 2;
                float b0 = smf[(SM_BE2 >> 2) + col];
                float b1 = smf[(SM_BE2 >> 2) + col + 1];
                int rA = m0 + ma * 16 + (lane >> 2);
                int rB = rA + 8;
                float v0 = silu_f(acc[ma][na][0] + b0);
                float v1 = silu_f(acc[ma][na][1] + b1);
                float v2 = silu_f(acc[ma][na][2] + b0);
                float v3 = silu_f(acc[ma][na][3] + b1);
                uint32_t hA, lA, hB, lB;
                split2(v0, v1, hA, lA);
                split2(v2, v3, hB, lB);
                uint32_t offA = rA * 256 + (((col >> 3) ^ (rA & 15)) << 4) + (col & 7) * 2;
                uint32_t offB = rB * 256 + (((col >> 3) ^ (rB & 15)) << 4) + (col & 7) * 2;
                *(uint32_t*)(smem + SM_AHI + offA) = hA;
                *(uint32_t*)(smem + SM_ALO + offA) = lA;
                *(uint32_t*)(smem + SM_AHI + offB) = hB;
                *(uint32_t*)(smem + SM_ALO + offB) = lB;
            }
        __syncthreads();

        // ===== GEMM2: m @ Wx1 =====
        gemm_tile(sb + SM_AHI, sb + SM_ALO, sb + SM_W2HI, sb + SM_W2LO,
                  lane, m0, nb, acc);

        // out_m + agg atomics from A buffers (m = hi + lo), coalesced
        #pragma unroll 1
        for (int i = 0; i < 16; i++) {
            int row = warp * 16 + i;
            int eg = ebase + row;
            if (eg < E) {
                uint32_t off = row * 256 + ((((lane >> 1) ^ (row & 15))) << 4)
                             + (lane & 1) * 8;
                uint2 uh = *(const uint2*)(smem + SM_AHI + off);
                uint2 ul = *(const uint2*)(smem + SM_ALO + off);
                float4 f;
                f.x = blo16(uh.x) + blo16(ul.x);
                f.y = bhi16(uh.x) + bhi16(ul.x);
                f.z = blo16(uh.y) + blo16(ul.y);
                f.w = bhi16(uh.y) + bhi16(ul.y);
                *(float4*)(out_m + (size_t)eg * D + lane * 4) = f;
                float* ag = g_agg + (size_t)dst_s[row] * D + lane * 4;
                atomicAdd(ag + 0, f.x);
                atomicAdd(ag + 1, f.y);
                atomicAdd(ag + 2, f.z);
                atomicAdd(ag + 3, f.w);
            }
        }

        // phi_x tail: p_row = sum_col silu(acc2 + bx1)*wx2 (fragment reduce)
        {
            float ps[2][2] = {{0.f, 0.f}, {0.f, 0.f}};
            #pragma unroll
            for (int ma = 0; ma < 2; ma++)
                #pragma unroll
                for (int na = 0; na < 8; na++) {
                    int col = nb + na * 8 + (lane & 3) * 2;
                    float b0 = smf[(SM_BX1 >> 2) + col];
                    float b1 = smf[(SM_BX1 >> 2) + col + 1];
                    float w0 = smf[(SM_WX2 >> 2) + col];
                    float w1 = smf[(SM_WX2 >> 2) + col + 1];
                    ps[ma][0] += silu_f(acc[ma][na][0] + b0) * w0
                               + silu_f(acc[ma][na][1] + b1) * w1;
                    ps[ma][1] += silu_f(acc[ma][na][2] + b0) * w0
                               + silu_f(acc[ma][na][3] + b1) * w1;
                }
            #pragma unroll
            for (int ma = 0; ma < 2; ma++)
                #pragma unroll
                for (int q = 0; q < 2; q++) {
                    ps[ma][q] += __shfl_xor_sync(0xffffffffu, ps[ma][q], 1);
                    ps[ma][q] += __shfl_xor_sync(0xffffffffu, ps[ma][q], 2);
                }
            if ((lane & 3) == 0) {
                int base = (warp >> 2) * 128;
                #pragma unroll
                for (int ma = 0; ma < 2; ma++) {
                    int rA = m0 + ma * 16 + (lane >> 2);
                    ppart[base + rA]     = ps[ma][0];
                    ppart[base + rA + 8] = ps[ma][1];
                }
            }
        }
        __syncthreads();

        if (tid < 128 && vreg) {
            float p = ppart[tid] + ppart[128 + tid] + smf[SM_BX2 >> 2];
            atomicAdd(&g_num[dreg*3 + 0], relx * p);
            atomicAdd(&g_num[dreg*3 + 1], rely * p);
            atomicAdd(&g_num[dreg*3 + 2], relz * p);
            atomicAdd(&g_cnt[dreg], 1.0f);
        }
        __syncthreads();
    }
}

// ---------------- scalar GEMM helper for node/precompute ----------------
#define GEMM_4x4(fr, PAD, W, KLEN, acc)                                        \
    _Pragma("unroll 2")                                                        \
    for (int k4 = 0; k4 < (KLEN); k4 += 4) {                                   \
        float4 f0 = *(const float4*)((fr) + 0 * (PAD) + k4);                   \
        float4 f1 = *(const float4*)((fr) + 1 * (PAD) + k4);                   \
        float4 f2 = *(const float4*)((fr) + 2 * (PAD) + k4);                   \
        float4 f3 = *(const float4*)((fr) + 3 * (PAD) + k4);                   \
        _Pragma("unroll")                                                      \
        for (int kk = 0; kk < 4; kk++) {                                       \
            float4 w = *(const float4*)((W) + (k4 + kk) * D + c0);             \
            float e0 = f4get(f0, kk), e1 = f4get(f1, kk);                      \
            float e2 = f4get(f2, kk), e3 = f4get(f3, kk);                      \
            acc[0][0] = fmaf(e0, w.x, acc[0][0]);                              \
            acc[0][1] = fmaf(e0, w.y, acc[0][1]);                              \
            acc[0][2] = fmaf(e0, w.z, acc[0][2]);                              \
            acc[0][3] = fmaf(e0, w.w, acc[0][3]);                              \
            acc[1][0] = fmaf(e1, w.x, acc[1][0]);                              \
            acc[1][1] = fmaf(e1, w.y, acc[1][1]);                              \
            acc[1][2] = fmaf(e1, w.z, acc[1][2]);                              \
            acc[1][3] = fmaf(e1, w.w, acc[1][3]);                              \
            acc[2][0] = fmaf(e2, w.x, acc[2][0]);                              \
            acc[2][1] = fmaf(e2, w.y, acc[2][1]);                              \
            acc[2][2] = fmaf(e2, w.z, acc[2][2]);                              \
            acc[2][3] = fmaf(e2, w.w, acc[2][3]);                              \
            acc[3][0] = fmaf(e3, w.x, acc[3][0]);                              \
            acc[3][1] = fmaf(e3, w.y, acc[3][1]);                              \
            acc[3][2] = fmaf(e3, w.z, acc[3][2]);                              \
            acc[3][3] = fmaf(e3, w.w, acc[3][3]);                              \
        }                                                                      \
    }

__global__ __launch_bounds__(256) void precompute_kernel(
    const float* __restrict__ h, const float* __restrict__ We1,
    const float* __restrict__ be1, int Nn)
{
    __shared__ float fs[NPB * Y_PAD];
    const int warp = threadIdx.x >> 5;
    const int lane = threadIdx.x & 31;
    const int c0   = lane * 4;
    const int nbase = blockIdx.x * NPB;

    int nidx[4]; bool valid[4];
    #pragma unroll
    for (int i = 0; i < 4; i++) {
        int nl = warp * 4 + i;
        int n  = nbase + nl;
        valid[i] = (n < Nn);
        nidx[i] = valid[i] ? n : 0;
        float4 hh = *(const float4*)(h + (size_t)nidx[i] * D + c0);
        *(float4*)(fs + nl * Y_PAD + c0) = hh;
    }
    __syncwarp();

    const float* fr = fs + (warp * 4) * Y_PAD;
    float acc[4][4];
    {
        float4 b = *(const float4*)(be1 + c0);
        #pragma unroll
        for (int i = 0; i < 4; i++) {
            acc[i][0] = b.x; acc[i][1] = b.y; acc[i][2] = b.z; acc[i][3] = b.w;
        }
    }
    GEMM_4x4(fr, Y_PAD, We1, 128, acc)
    #pragma unroll
    for (int i = 0; i < 4; i++)
        if (valid[i])
            *(float4*)(g_U + (size_t)nidx[i] * D + c0) =
                make_float4(acc[i][0], acc[i][1], acc[i][2], acc[i][3]);

    #pragma unroll
    for (int i = 0; i < 4; i++) {
        acc[i][0] = 0.f; acc[i][1] = 0.f; acc[i][2] = 0.f; acc[i][3] = 0.f;
    }
    GEMM_4x4(fr, Y_PAD, We1 + 128 * D, 128, acc)
    #pragma unroll
    for (int i = 0; i < 4; i++)
        if (valid[i])
            *(float4*)(g_V + (size_t)nidx[i] * D + c0) =
                make_float4(acc[i][0], acc[i][1], acc[i][2], acc[i][3]);
}

__global__ __launch_bounds__(256) void node_kernel(
    const float* __restrict__ h, const float* __restrict__ x,
    const float* __restrict__ Wh1, const float* __restrict__ bh1,
    const float* __restrict__ Wh2, const float* __restrict__ bh2,
    const float* __restrict__ gamma, const float* __restrict__ beta,
    float* __restrict__ out_h, float* __restrict__ out_x, int Nn)
{
    __shared__ float fs[NPB * NODE_PAD];
    const int warp = threadIdx.x >> 5;
    const int lane = threadIdx.x & 31;
    const int c0   = lane * 4;
    const int nbase = blockIdx.x * NPB;

    bool valid[4];
    int nidx[4];
    #pragma unroll
    for (int i = 0; i < 4; i++) {
        int nl = warp * 4 + i;
        int n  = nbase + nl;
        valid[i] = (n < Nn);
        int nc = valid[i] ? n : 0;
        nidx[i] = nc;
        float4 hh = *(const float4*)(h + (size_t)nc * D + c0);
        float4 ag = *(const float4*)(g_agg + (size_t)nc * D + c0);
        *(float4*)(fs + nl * NODE_PAD + c0)       = hh;
        *(float4*)(fs + nl * NODE_PAD + 128 + c0) = ag;
    }
    __syncwarp();

    const float* fr = fs + (warp * 4) * NODE_PAD;
    float acc[4][4];
    {
        float4 b = *(const float4*)(bh1 + c0);
        #pragma unroll
        for (int i = 0; i < 4; i++) {
            acc[i][0] = b.x; acc[i][1] = b.y; acc[i][2] = b.z; acc[i][3] = b.w;
        }
    }
    GEMM_4x4(fr, NODE_PAD, Wh1, 256, acc)
    #pragma unroll
    for (int i = 0; i < 4; i++)
        #pragma unroll
        for (int q = 0; q < 4; q++) acc[i][q] = silu_f(acc[i][q]);

    __syncwarp();
    #pragma unroll
    for (int i = 0; i < 4; i++)
        *(float4*)(fs + (warp*4 + i) * NODE_PAD + c0) =
            make_float4(acc[i][0], acc[i][1], acc[i][2], acc[i][3]);
    __syncwarp();

    {
        float4 b = *(const float4*)(bh2 + c0);
        #pragma unroll
        for (int i = 0; i < 4; i++) {
            acc[i][0] = b.x; acc[i][1] = b.y; acc[i][2] = b.z; acc[i][3] = b.w;
        }
    }
    GEMM_4x4(fr, NODE_PAD, Wh2, 128, acc)

    float hn[4][4];
    float mu[4], rstd[4];
    #pragma unroll
    for (int i = 0; i < 4; i++) {
        float4 hh = *(const float4*)(h + (size_t)nidx[i] * D + c0);
        hn[i][0] = hh.x + acc[i][0];
        hn[i][1] = hh.y + acc[i][1];
        hn[i][2] = hh.z + acc[i][2];
        hn[i][3] = hh.w + acc[i][3];
        float s1 = hn[i][0] + hn[i][1] + hn[i][2] + hn[i][3];
        float s2 = hn[i][0]*hn[i][0] + hn[i][1]*hn[i][1]
                 + hn[i][2]*hn[i][2] + hn[i][3]*hn[i][3];
        #pragma unroll
        for (int off = 16; off > 0; off >>= 1) {
            s1 += __shfl_xor_sync(0xffffffffu, s1, off);
            s2 += __shfl_xor_sync(0xffffffffu, s2, off);
        }
        mu[i] = s1 * (1.0f / 128.0f);
        float var = s2 * (1.0f / 128.0f) - mu[i]*mu[i];
        rstd[i] = rsqrtf(var + 1e-5f);
    }
    float4 g = *(const float4*)(gamma + c0);
    float4 b = *(const float4*)(beta + c0);
    #pragma unroll
    for (int i = 0; i < 4; i++) {
        if (valid[i]) {
            float4 o;
            o.x = (hn[i][0] - mu[i]) * rstd[i] * g.x + b.x;
            o.y = (hn[i][1] - mu[i]) * rstd[i] * g.y + b.y;
            o.z = (hn[i][2] - mu[i]) * rstd[i] * g.z + b.z;
            o.w = (hn[i][3] - mu[i]) * rstd[i] * g.w + b.w;
            *(float4*)(out_h + (size_t)nidx[i] * D + c0) = o;
        }
    }
    if (lane == 0) {
        #pragma unroll
        for (int i = 0; i < 4; i++) {
            if (valid[i]) {
                int n = nidx[i];
                float cnt = g_cnt[n];
                float inv = 1.0f / fmaxf(cnt, 1.0f);
                out_x[n*3 + 0] = x[n*3 + 0] + g_num[n*3 + 0] * inv;
                out_x[n*3 + 1] = x[n*3 + 1] + g_num[n*3 + 1] * inv;
                out_x[n*3 + 2] = x[n*3 + 2] + g_num[n*3 + 2] * inv;
            }
        }
    }
}

extern "C" void kernel_launch(void* const* d_in, const int* in_sizes, int n_in,
                              void* d_out, int out_size) {
    const float* h    = (const float*)d_in[0];
    const float* x    = (const float*)d_in[1];
    const float* vel  = (const float*)d_in[2];
    const void*  eidx = d_in[3];
    const float* We1 = (const float*)d_in[4],  *be1 = (const float*)d_in[5];
    const float* We2 = (const float*)d_in[6],  *be2 = (const float*)d_in[7];
    const float* Wx1 = (const float*)d_in[8],  *bx1 = (const float*)d_in[9];
    const float* Wx2 = (const float*)d_in[10], *bx2 = (const float*)d_in[11];
    const float* Wh1 = (const float*)d_in[12], *bh1 = (const float*)d_in[13];
    const float* Wh2 = (const float*)d_in[14], *bh2 = (const float*)d_in[15];
    const float* gamma = (const float*)d_in[16], *beta = (const float*)d_in[17];

    int Nn = in_sizes[0] / D;
    int E  = in_sizes[3] / 2;

    float* out   = (float*)d_out;
    float* out_h = out;
    float* out_x = out + (size_t)Nn * D;
    float* out_m = out_x + (size_t)Nn * 3;

    static int smem_set = 0;
    if (!smem_set) {
        cudaFuncSetAttribute(edge_mma_kernel,
                             cudaFuncAttributeMaxDynamicSharedMemorySize, SM_TOTAL);
        smem_set = 1;
    }

    detect_kernel<<<1, 1>>>(eidx, E, Nn);
    zero_kernel<<<(Nn * D + 255) / 256, 256>>>(Nn);
    prep_weights_kernel<<<(2 * 16384 + 255) / 256, 256>>>(We2, Wx1);
    precompute_kernel<<<(Nn + NPB - 1) / NPB, 256>>>(h, We1, be1, Nn);
    edge_mma_kernel<<<148, 256, SM_TOTAL>>>(x, vel, eidx, We1,
                                            be2, bx1, Wx2, bx2, out_m, E);
    node_kernel<<<(Nn + NPB - 1) / NPB, 256>>>(h, x, Wh1, bh1, Wh2, bh2,
                                               gamma, beta, out_h, out_x, Nn);
}

// round 9
// speedup vs baseline: 1.2114x; 1.2114x over previous
#include <cuda_runtime.h>
#include <cuda_bf16.h>
#include <cstdint>

#define D 128
#define NPB 32
#define Y_PAD 136
#define NODE_PAD 264
#define MAXN 50000
#define TILE_M 128

// ---------------- device scratch (allocation-free rule) ----------------
__device__ float g_agg[MAXN * D];
__device__ float g_num[MAXN * 3];
__device__ float g_cnt[MAXN];
__device__ float g_U[MAXN * D];   // h @ We1[0:128,:] + be1
__device__ float g_V[MAXN * D];   // h @ We1[128:256,:]
__device__ int   g_is64;
// bf16 weight smem-images, XOR-swizzled [n][k] (256B rows): 0 = We2, 1 = Wx1
__device__ unsigned short g_Bhi[2 * 16384];
__device__ unsigned short g_Blo[2 * 16384];

__device__ __forceinline__ float silu_f(float v) {
    return v * (1.0f / (1.0f + __expf(-v)));
}
__device__ __forceinline__ float f4get(const float4& v, int k) {
    return k == 0 ? v.x : (k == 1 ? v.y : (k == 2 ? v.z : v.w));
}
__device__ __forceinline__ uint32_t smem_u32(const void* p) {
    uint32_t a;
    asm("{ .reg .u64 t; cvta.to.shared.u64 t, %1; cvt.u32.u64 %0, t; }"
        : "=r"(a) : "l"(p));
    return a;
}

#define LDSM_X4(r, addr)                                                        \
    asm volatile("ldmatrix.sync.aligned.m8n8.x4.shared.b16 {%0,%1,%2,%3}, [%4];"\
        : "=r"((r)[0]), "=r"((r)[1]), "=r"((r)[2]), "=r"((r)[3]) : "r"(addr))

#define MMA_BF16(d, a, b0, b1)                                                  \
    asm volatile("mma.sync.aligned.m16n8k16.row.col.f32.bf16.bf16.f32 "         \
        "{%0,%1,%2,%3}, {%4,%5,%6,%7}, {%8,%9}, {%0,%1,%2,%3};"                 \
        : "+f"((d)[0]), "+f"((d)[1]), "+f"((d)[2]), "+f"((d)[3])                \
        : "r"((a)[0]), "r"((a)[1]), "r"((a)[2]), "r"((a)[3]), "r"(b0), "r"(b1))

__device__ __forceinline__ void split2(float v0, float v1, uint32_t& hi, uint32_t& lo) {
    __nv_bfloat16 h0 = __float2bfloat16(v0), h1 = __float2bfloat16(v1);
    float r0 = v0 - __bfloat162float(h0), r1 = v1 - __bfloat162float(h1);
    hi = (uint32_t)__bfloat16_as_ushort(h0) | ((uint32_t)__bfloat16_as_ushort(h1) << 16);
    lo = (uint32_t)__bfloat16_as_ushort(__float2bfloat16(r0))
       | ((uint32_t)__bfloat16_as_ushort(__float2bfloat16(r1)) << 16);
}
__device__ __forceinline__ float blo16(uint32_t u) {
    return __bfloat162float(__ushort_as_bfloat16((unsigned short)(u & 0xffff)));
}
__device__ __forceinline__ float bhi16(uint32_t u) {
    return __bfloat162float(__ushort_as_bfloat16((unsigned short)(u >> 16)));
}

// ---------------- misc small kernels ----------------
__global__ void detect_kernel(const void* eidx_raw, int E, int Nn) {
    const long long* p = (const long long*)eidx_raw;
    int ok = 1;
    for (int i = 0; i < 64 && i < E; i++) {
        long long v = p[i];
        if (v < 0 || v >= (long long)Nn) { ok = 0; break; }
    }
    g_is64 = ok;
}
__device__ __forceinline__ int load_idx(const void* eidx_raw, long long pos, int is64) {
    if (is64) return (int)((const long long*)eidx_raw)[pos];
    return ((const int*)eidx_raw)[pos];
}
__global__ void zero_kernel(int n_nodes) {
    int idx = blockIdx.x * blockDim.x + threadIdx.x;
    if (idx < n_nodes * D) g_agg[idx] = 0.f;
    if (idx < n_nodes * 3) g_num[idx] = 0.f;
    if (idx < n_nodes)     g_cnt[idx] = 0.f;
}

// Build bf16 hi/lo images of We2^T, Wx1^T in swizzled [n][k] layout:
// byte off = n*256 + ((k/8 ^ (n&15))*16) + (k%8)*2
__global__ void prep_weights_kernel(const float* __restrict__ We2,
                                    const float* __restrict__ Wx1) {
    int idx = blockIdx.x * blockDim.x + threadIdx.x;
    if (idx >= 2 * 16384) return;
    int m = idx >> 14;
    int e = idx & 16383;
    int n = e >> 7;
    int k = e & 127;
    const float* W = m ? Wx1 : We2;
    float v = W[k * D + n];
    __nv_bfloat16 hb = __float2bfloat16(v);
    float lo = v - __bfloat162float(hb);
    int off = n * 256 + (((k >> 3) ^ (n & 15)) << 4) + (k & 7) * 2;
    g_Bhi[m * 16384 + (off >> 1)] = __bfloat16_as_ushort(hb);
    g_Blo[m * 16384 + (off >> 1)] = __bfloat16_as_ushort(__float2bfloat16(lo));
}

// ---------------- SMEM layout (bytes) ----------------
#define SM_W1HI 0
#define SM_W1LO 32768
#define SM_W2HI 65536
#define SM_W2LO 98304
#define SM_AHI  131072
#define SM_ALO  163840
#define SM_WGEO 196608   // 11*128 f32 = 5632
#define SM_GEO  202240   // 128*13 f32 = 6656
#define SM_DST  208896   // 128 int
#define SM_SRC  209408
#define SM_BE2  209920   // 128 f32
#define SM_BX1  210432
#define SM_WX2  210944
#define SM_PPART 211456  // 2*128 f32
#define SM_BX2  212480
#define SM_TOTAL 212544

// Split-bf16 GEMM: D[128,128] = A[128,128] @ B^T, warp block 32x64.
__device__ __forceinline__ void gemm_tile(
    uint32_t aHi, uint32_t aLo, uint32_t bHi, uint32_t bLo,
    int lane, int m0, int nb, float acc[2][8][4])
{
    #pragma unroll
    for (int ma = 0; ma < 2; ma++)
        #pragma unroll
        for (int na = 0; na < 8; na++)
            #pragma unroll
            for (int q = 0; q < 4; q++) acc[ma][na][q] = 0.f;

    const int arow_l = lane & 15;
    const int akh    = lane >> 4;
    const int brow_l = ((lane >> 4) & 1) * 8 + (lane & 7);
    const int bkh    = (lane >> 3) & 1;

    #pragma unroll 1
    for (int kb = 0; kb < 8; kb++) {
        uint32_t ah[2][4], al[2][4], bh[4][4], bl[4][4];
        #pragma unroll
        for (int ma = 0; ma < 2; ma++) {
            int row = m0 + ma * 16 + arow_l;
            int ch  = kb * 2 + akh;
            uint32_t off = row * 256 + ((ch ^ (row & 15)) << 4);
            LDSM_X4(ah[ma], aHi + off);
            LDSM_X4(al[ma], aLo + off);
        }
        #pragma unroll
        for (int p = 0; p < 4; p++) {
            int row = nb + p * 16 + brow_l;
            int ch  = kb * 2 + bkh;
            uint32_t off = row * 256 + ((ch ^ (row & 15)) << 4);
            LDSM_X4(bh[p], bHi + off);
            LDSM_X4(bl[p], bLo + off);
        }
        #pragma unroll
        for (int ma = 0; ma < 2; ma++)
            #pragma unroll
            for (int na = 0; na < 8; na++) {
                uint32_t b0 = bh[na >> 1][(na & 1) * 2];
                uint32_t b1 = bh[na >> 1][(na & 1) * 2 + 1];
                uint32_t c0 = bl[na >> 1][(na & 1) * 2];
                uint32_t c1 = bl[na >> 1][(na & 1) * 2 + 1];
                MMA_BF16(acc[ma][na], ah[ma], b0, b1);
                MMA_BF16(acc[ma][na], al[ma], b0, b1);
                MMA_BF16(acc[ma][na], ah[ma], c0, c1);
            }
    }
}

__global__ __launch_bounds__(256, 1) void edge_mma_kernel(
    const float* __restrict__ x, const float* __restrict__ vel,
    const void* __restrict__ eidx_raw, const float* __restrict__ We1,
    const float* __restrict__ be2, const float* __restrict__ bx1,
    const float* __restrict__ Wx2, const float* __restrict__ bx2,
    float* __restrict__ out_m, int E)
{
    extern __shared__ char smem[];
    float* smf = (float*)smem;
    const uint32_t sb = smem_u32(smem);
    const int tid  = threadIdx.x;
    const int warp = tid >> 5;
    const int lane = tid & 31;
    const int m0   = (warp & 3) * 32;   // GEMM row block
    const int nb   = (warp >> 2) * 64;  // GEMM col block
    const int rw0  = warp * 16;         // scalar phase: warp owns 16 edge rows
    const int c0   = lane * 4;          // scalar phase: lane owns 4 cols
    const int is64 = g_is64;

    // ---- one-time init: weights + biases to smem ----
    {
        const uint4* shi = (const uint4*)g_Bhi;
        const uint4* slo = (const uint4*)g_Blo;
        for (int i = tid; i < 2048; i += 256) {
            ((uint4*)(smem + SM_W1HI))[i] = shi[i];
            ((uint4*)(smem + SM_W1LO))[i] = slo[i];
            ((uint4*)(smem + SM_W2HI))[i] = shi[2048 + i];
            ((uint4*)(smem + SM_W2LO))[i] = slo[2048 + i];
        }
    }
    if (tid < 128) {
        smf[(SM_BE2 >> 2) + tid] = be2[tid];
        smf[(SM_BX1 >> 2) + tid] = bx1[tid];
        smf[(SM_WX2 >> 2) + tid] = Wx2[tid];
    }
    if (tid == 0) smf[SM_BX2 >> 2] = bx2[0];
    for (int i = tid; i < 11 * 128; i += 256)
        smf[(SM_WGEO >> 2) + i] = We1[256 * D + i];
    __syncthreads();

    float* geo_sf = smf + (SM_GEO >> 2);
    int*   dst_s  = (int*)(smem + SM_DST);
    int*   src_s  = (int*)(smem + SM_SRC);
    float* ppart  = smf + (SM_PPART >> 2);

    const int ntiles = (E + TILE_M - 1) / TILE_M;

    for (int tile = blockIdx.x; tile < ntiles; tile += gridDim.x) {
        const int ebase = tile * TILE_M;

        // ===== stage: indices + geometry (tid<128, edge = tid) =====
        float relx = 0.f, rely = 0.f, relz = 0.f;
        int dreg = 0; bool vreg = false;
        if (tid < 128) {
            int eg = ebase + tid;
            vreg = (eg < E);
            int ec = vreg ? eg : 0;
            int s = load_idx(eidx_raw, ec, is64);
            int d = load_idx(eidx_raw, (long long)E + ec, is64);
            src_s[tid] = s; dst_s[tid] = d; dreg = d;
            float rx = x[s*3+0] - x[d*3+0];
            float ry = x[s*3+1] - x[d*3+1];
            float rz = x[s*3+2] - x[d*3+2];
            relx = rx; rely = ry; relz = rz;
            float d2 = rx*rx + ry*ry + rz*rz;
            float dist = fmaxf(sqrtf(d2), 1e-8f);
            float inv = 1.0f / dist;
            float ux = rx*inv, uy = ry*inv, uz = rz*inv;
            geo_sf[tid * 13 + 0] = d2;
            #pragma unroll
            for (int j = 0; j < 5; j++) {
                const float* vs = vel + (size_t)s * 15 + j * 3;
                const float* vd = vel + (size_t)d * 15 + j * 3;
                geo_sf[tid * 13 + 1 + j] = vs[0]*ux + vs[1]*uy + vs[2]*uz;
                geo_sf[tid * 13 + 6 + j] = vd[0]*ux + vd[1]*uy + vd[2]*uz;
            }
        }
        __syncthreads();

        // ===== scalar phase (COLUMN-MAPPED, coalesced gathers) =====
        // warp owns 16 edge rows; lane owns cols [c0, c0+4).
        {
            float z[16][4];
            #pragma unroll
            for (int i = 0; i < 16; i++) {
                int s2  = src_s[rw0 + i];
                int d2i = dst_s[rw0 + i];
                float4 u = *(const float4*)(g_U + (size_t)s2 * D + c0);
                float4 v = *(const float4*)(g_V + (size_t)d2i * D + c0);
                z[i][0] = u.x + v.x; z[i][1] = u.y + v.y;
                z[i][2] = u.z + v.z; z[i][3] = u.w + v.w;
            }
            #pragma unroll 1
            for (int k = 0; k < 11; k++) {
                float4 w = *(const float4*)(smf + (SM_WGEO >> 2) + k * D + c0);
                #pragma unroll
                for (int i = 0; i < 16; i++) {
                    float f = geo_sf[(rw0 + i) * 13 + k];   // LDS broadcast
                    z[i][0] = fmaf(f, w.x, z[i][0]);
                    z[i][1] = fmaf(f, w.y, z[i][1]);
                    z[i][2] = fmaf(f, w.z, z[i][2]);
                    z[i][3] = fmaf(f, w.w, z[i][3]);
                }
            }
            // silu + split + store A tiles (swizzled, conflict-free STS.64)
            const int chunk = c0 >> 3;          // lane>>1
            const int sub   = (c0 & 7) * 2;     // 0 or 8
            #pragma unroll
            for (int i = 0; i < 16; i++) {
                int r = rw0 + i;
                float v0 = silu_f(z[i][0]), v1 = silu_f(z[i][1]);
                float v2 = silu_f(z[i][2]), v3 = silu_f(z[i][3]);
                uint32_t h0, l0, h1, l1;
                split2(v0, v1, h0, l0);
                split2(v2, v3, h1, l1);
                uint32_t off = r * 256 + ((chunk ^ (r & 15)) << 4) + sub;
                *(uint2*)(smem + SM_AHI + off) = make_uint2(h0, h1);
                *(uint2*)(smem + SM_ALO + off) = make_uint2(l0, l1);
            }
        }
        __syncthreads();

        // ===== GEMM1: y1 @ We2 =====
        float acc[2][8][4];
        gemm_tile(sb + SM_AHI, sb + SM_ALO, sb + SM_W1HI, sb + SM_W1LO,
                  lane, m0, nb, acc);
        __syncthreads();   // A reads done block-wide before overwrite

        // epilogue1: m = silu(acc + be2) -> A buffers (fragment layout)
        #pragma unroll
        for (int ma = 0; ma < 2; ma++)
            #pragma unroll
            for (int na = 0; na < 8; na++) {
                int col = nb + na * 8 + (lane & 3) * 2;
                float b0 = smf[(SM_BE2 >> 2) + col];
                float b1 = smf[(SM_BE2 >> 2) + col + 1];
                int rA = m0 + ma * 16 + (lane >> 2);
                int rB = rA + 8;
                float v0 = silu_f(acc[ma][na][0] + b0);
                float v1 = silu_f(acc[ma][na][1] + b1);
                float v2 = silu_f(acc[ma][na][2] + b0);
                float v3 = silu_f(acc[ma][na][3] + b1);
                uint32_t hA, lA, hB, lB;
                split2(v0, v1, hA, lA);
                split2(v2, v3, hB, lB);
                uint32_t offA = rA * 256 + (((col >> 3) ^ (rA & 15)) << 4) + (col & 7) * 2;
                uint32_t offB = rB * 256 + (((col >> 3) ^ (rB & 15)) << 4) + (col & 7) * 2;
                *(uint32_t*)(smem + SM_AHI + offA) = hA;
                *(uint32_t*)(smem + SM_ALO + offA) = lA;
                *(uint32_t*)(smem + SM_AHI + offB) = hB;
                *(uint32_t*)(smem + SM_ALO + offB) = lB;
            }
        __syncthreads();

        // ===== GEMM2: m @ Wx1 =====
        gemm_tile(sb + SM_AHI, sb + SM_ALO, sb + SM_W2HI, sb + SM_W2LO,
                  lane, m0, nb, acc);

        // out_m + agg atomics from A buffers (m = hi + lo), coalesced
        #pragma unroll 1
        for (int i = 0; i < 16; i++) {
            int row = warp * 16 + i;
            int eg = ebase + row;
            if (eg < E) {
                uint32_t off = row * 256 + ((((lane >> 1) ^ (row & 15))) << 4)
                             + (lane & 1) * 8;
                uint2 uh = *(const uint2*)(smem + SM_AHI + off);
                uint2 ul = *(const uint2*)(smem + SM_ALO + off);
                float4 f;
                f.x = blo16(uh.x) + blo16(ul.x);
                f.y = bhi16(uh.x) + bhi16(ul.x);
                f.z = blo16(uh.y) + blo16(ul.y);
                f.w = bhi16(uh.y) + bhi16(ul.y);
                *(float4*)(out_m + (size_t)eg * D + lane * 4) = f;
                float* ag = g_agg + (size_t)dst_s[row] * D + lane * 4;
                atomicAdd(ag + 0, f.x);
                atomicAdd(ag + 1, f.y);
                atomicAdd(ag + 2, f.z);
                atomicAdd(ag + 3, f.w);
            }
        }

        // phi_x tail: p_row = sum_col silu(acc2 + bx1)*wx2 (fragment reduce)
        {
            float ps[2][2] = {{0.f, 0.f}, {0.f, 0.f}};
            #pragma unroll
            for (int ma = 0; ma < 2; ma++)
                #pragma unroll
                for (int na = 0; na < 8; na++) {
                    int col = nb + na * 8 + (lane & 3) * 2;
                    float b0 = smf[(SM_BX1 >> 2) + col];
                    float b1 = smf[(SM_BX1 >> 2) + col + 1];
                    float w0 = smf[(SM_WX2 >> 2) + col];
                    float w1 = smf[(SM_WX2 >> 2) + col + 1];
                    ps[ma][0] += silu_f(acc[ma][na][0] + b0) * w0
                               + silu_f(acc[ma][na][1] + b1) * w1;
                    ps[ma][1] += silu_f(acc[ma][na][2] + b0) * w0
                               + silu_f(acc[ma][na][3] + b1) * w1;
                }
            #pragma unroll
            for (int ma = 0; ma < 2; ma++)
                #pragma unroll
                for (int q = 0; q < 2; q++) {
                    ps[ma][q] += __shfl_xor_sync(0xffffffffu, ps[ma][q], 1);
                    ps[ma][q] += __shfl_xor_sync(0xffffffffu, ps[ma][q], 2);
                }
            if ((lane & 3) == 0) {
                int base = (warp >> 2) * 128;
                #pragma unroll
                for (int ma = 0; ma < 2; ma++) {
                    int rA = m0 + ma * 16 + (lane >> 2);
                    ppart[base + rA]     = ps[ma][0];
                    ppart[base + rA + 8] = ps[ma][1];
                }
            }
        }
        __syncthreads();

        if (tid < 128 && vreg) {
            float p = ppart[tid] + ppart[128 + tid] + smf[SM_BX2 >> 2];
            atomicAdd(&g_num[dreg*3 + 0], relx * p);
            atomicAdd(&g_num[dreg*3 + 1], rely * p);
            atomicAdd(&g_num[dreg*3 + 2], relz * p);
            atomicAdd(&g_cnt[dreg], 1.0f);
        }
        __syncthreads();
    }
}

// ---------------- scalar GEMM helper for node/precompute ----------------
#define GEMM_4x4(fr, PAD, W, KLEN, acc)                                        \
    _Pragma("unroll 2")                                                        \
    for (int k4 = 0; k4 < (KLEN); k4 += 4) {                                   \
        float4 f0 = *(const float4*)((fr) + 0 * (PAD) + k4);                   \
        float4 f1 = *(const float4*)((fr) + 1 * (PAD) + k4);                   \
        float4 f2 = *(const float4*)((fr) + 2 * (PAD) + k4);                   \
        float4 f3 = *(const float4*)((fr) + 3 * (PAD) + k4);                   \
        _Pragma("unroll")                                                      \
        for (int kk = 0; kk < 4; kk++) {                                       \
            float4 w = *(const float4*)((W) + (k4 + kk) * D + c0);             \
            float e0 = f4get(f0, kk), e1 = f4get(f1, kk);                      \
            float e2 = f4get(f2, kk), e3 = f4get(f3, kk);                      \
            acc[0][0] = fmaf(e0, w.x, acc[0][0]);                              \
            acc[0][1] = fmaf(e0, w.y, acc[0][1]);                              \
            acc[0][2] = fmaf(e0, w.z, acc[0][2]);                              \
            acc[0][3] = fmaf(e0, w.w, acc[0][3]);                              \
            acc[1][0] = fmaf(e1, w.x, acc[1][0]);                              \
            acc[1][1] = fmaf(e1, w.y, acc[1][1]);                              \
            acc[1][2] = fmaf(e1, w.z, acc[1][2]);                              \
            acc[1][3] = fmaf(e1, w.w, acc[1][3]);                              \
            acc[2][0] = fmaf(e2, w.x, acc[2][0]);                              \
            acc[2][1] = fmaf(e2, w.y, acc[2][1]);                              \
            acc[2][2] = fmaf(e2, w.z, acc[2][2]);                              \
            acc[2][3] = fmaf(e2, w.w, acc[2][3]);                              \
            acc[3][0] = fmaf(e3, w.x, acc[3][0]);                              \
            acc[3][1] = fmaf(e3, w.y, acc[3][1]);                              \
            acc[3][2] = fmaf(e3, w.z, acc[3][2]);                              \
            acc[3][3] = fmaf(e3, w.w, acc[3][3]);                              \
        }                                                                      \
    }

__global__ __launch_bounds__(256) void precompute_kernel(
    const float* __restrict__ h, const float* __restrict__ We1,
    const float* __restrict__ be1, int Nn)
{
    __shared__ float fs[NPB * Y_PAD];
    const int warp = threadIdx.x >> 5;
    const int lane = threadIdx.x & 31;
    const int c0   = lane * 4;
    const int nbase = blockIdx.x * NPB;

    int nidx[4]; bool valid[4];
    #pragma unroll
    for (int i = 0; i < 4; i++) {
        int nl = warp * 4 + i;
        int n  = nbase + nl;
        valid[i] = (n < Nn);
        nidx[i] = valid[i] ? n : 0;
        float4 hh = *(const float4*)(h + (size_t)nidx[i] * D + c0);
        *(float4*)(fs + nl * Y_PAD + c0) = hh;
    }
    __syncwarp();

    const float* fr = fs + (warp * 4) * Y_PAD;
    float acc[4][4];
    {
        float4 b = *(const float4*)(be1 + c0);
        #pragma unroll
        for (int i = 0; i < 4; i++) {
            acc[i][0] = b.x; acc[i][1] = b.y; acc[i][2] = b.z; acc[i][3] = b.w;
        }
    }
    GEMM_4x4(fr, Y_PAD, We1, 128, acc)
    #pragma unroll
    for (int i = 0; i < 4; i++)
        if (valid[i])
            *(float4*)(g_U + (size_t)nidx[i] * D + c0) =
                make_float4(acc[i][0], acc[i][1], acc[i][2], acc[i][3]);

    #pragma unroll
    for (int i = 0; i < 4; i++) {
        acc[i][0] = 0.f; acc[i][1] = 0.f; acc[i][2] = 0.f; acc[i][3] = 0.f;
    }
    GEMM_4x4(fr, Y_PAD, We1 + 128 * D, 128, acc)
    #pragma unroll
    for (int i = 0; i < 4; i++)
        if (valid[i])
            *(float4*)(g_V + (size_t)nidx[i] * D + c0) =
                make_float4(acc[i][0], acc[i][1], acc[i][2], acc[i][3]);
}

__global__ __launch_bounds__(256) void node_kernel(
    const float* __restrict__ h, const float* __restrict__ x,
    const float* __restrict__ Wh1, const float* __restrict__ bh1,
    const float* __restrict__ Wh2, const float* __restrict__ bh2,
    const float* __restrict__ gamma, const float* __restrict__ beta,
    float* __restrict__ out_h, float* __restrict__ out_x, int Nn)
{
    __shared__ float fs[NPB * NODE_PAD];
    const int warp = threadIdx.x >> 5;
    const int lane = threadIdx.x & 31;
    const int c0   = lane * 4;
    const int nbase = blockIdx.x * NPB;

    bool valid[4];
    int nidx[4];
    #pragma unroll
    for (int i = 0; i < 4; i++) {
        int nl = warp * 4 + i;
        int n  = nbase + nl;
        valid[i] = (n < Nn);
        int nc = valid[i] ? n : 0;
        nidx[i] = nc;
        float4 hh = *(const float4*)(h + (size_t)nc * D + c0);
        float4 ag = *(const float4*)(g_agg + (size_t)nc * D + c0);
        *(float4*)(fs + nl * NODE_PAD + c0)       = hh;
        *(float4*)(fs + nl * NODE_PAD + 128 + c0) = ag;
    }
    __syncwarp();

    const float* fr = fs + (warp * 4) * NODE_PAD;
    float acc[4][4];
    {
        float4 b = *(const float4*)(bh1 + c0);
        #pragma unroll
        for (int i = 0; i < 4; i++) {
            acc[i][0] = b.x; acc[i][1] = b.y; acc[i][2] = b.z; acc[i][3] = b.w;
        }
    }
    GEMM_4x4(fr, NODE_PAD, Wh1, 256, acc)
    #pragma unroll
    for (int i = 0; i < 4; i++)
        #pragma unroll
        for (int q = 0; q < 4; q++) acc[i][q] = silu_f(acc[i][q]);

    __syncwarp();
    #pragma unroll
    for (int i = 0; i < 4; i++)
        *(float4*)(fs + (warp*4 + i) * NODE_PAD + c0) =
            make_float4(acc[i][0], acc[i][1], acc[i][2], acc[i][3]);
    __syncwarp();

    {
        float4 b = *(const float4*)(bh2 + c0);
        #pragma unroll
        for (int i = 0; i < 4; i++) {
            acc[i][0] = b.x; acc[i][1] = b.y; acc[i][2] = b.z; acc[i][3] = b.w;
        }
    }
    GEMM_4x4(fr, NODE_PAD, Wh2, 128, acc)

    float hn[4][4];
    float mu[4], rstd[4];
    #pragma unroll
    for (int i = 0; i < 4; i++) {
        float4 hh = *(const float4*)(h + (size_t)nidx[i] * D + c0);
        hn[i][0] = hh.x + acc[i][0];
        hn[i][1] = hh.y + acc[i][1];
        hn[i][2] = hh.z + acc[i][2];
        hn[i][3] = hh.w + acc[i][3];
        float s1 = hn[i][0] + hn[i][1] + hn[i][2] + hn[i][3];
        float s2 = hn[i][0]*hn[i][0] + hn[i][1]*hn[i][1]
                 + hn[i][2]*hn[i][2] + hn[i][3]*hn[i][3];
        #pragma unroll
        for (int off = 16; off > 0; off >>= 1) {
            s1 += __shfl_xor_sync(0xffffffffu, s1, off);
            s2 += __shfl_xor_sync(0xffffffffu, s2, off);
        }
        mu[i] = s1 * (1.0f / 128.0f);
        float var = s2 * (1.0f / 128.0f) - mu[i]*mu[i];
        rstd[i] = rsqrtf(var + 1e-5f);
    }
    float4 g = *(const float4*)(gamma + c0);
    float4 b = *(const float4*)(beta + c0);
    #pragma unroll
    for (int i = 0; i < 4; i++) {
        if (valid[i]) {
            float4 o;
            o.x = (hn[i][0] - mu[i]) * rstd[i] * g.x + b.x;
            o.y = (hn[i][1] - mu[i]) * rstd[i] * g.y + b.y;
            o.z = (hn[i][2] - mu[i]) * rstd[i] * g.z + b.z;
            o.w = (hn[i][3] - mu[i]) * rstd[i] * g.w + b.w;
            *(float4*)(out_h + (size_t)nidx[i] * D + c0) = o;
        }
    }
    if (lane == 0) {
        #pragma unroll
        for (int i = 0; i < 4; i++) {
            if (valid[i]) {
                int n = nidx[i];
                float cnt = g_cnt[n];
                float inv = 1.0f / fmaxf(cnt, 1.0f);
                out_x[n*3 + 0] = x[n*3 + 0] + g_num[n*3 + 0] * inv;
                out_x[n*3 + 1] = x[n*3 + 1] + g_num[n*3 + 1] * inv;
                out_x[n*3 + 2] = x[n*3 + 2] + g_num[n*3 + 2] * inv;
            }
        }
    }
}

extern "C" void kernel_launch(void* const* d_in, const int* in_sizes, int n_in,
                              void* d_out, int out_size) {
    const float* h    = (const float*)d_in[0];
    const float* x    = (const float*)d_in[1];
    const float* vel  = (const float*)d_in[2];
    const void*  eidx = d_in[3];
    const float* We1 = (const float*)d_in[4],  *be1 = (const float*)d_in[5];
    const float* We2 = (const float*)d_in[6],  *be2 = (const float*)d_in[7];
    const float* Wx1 = (const float*)d_in[8],  *bx1 = (const float*)d_in[9];
    const float* Wx2 = (const float*)d_in[10], *bx2 = (const float*)d_in[11];
    const float* Wh1 = (const float*)d_in[12], *bh1 = (const float*)d_in[13];
    const float* Wh2 = (const float*)d_in[14], *bh2 = (const float*)d_in[15];
    const float* gamma = (const float*)d_in[16], *beta = (const float*)d_in[17];

    int Nn = in_sizes[0] / D;
    int E  = in_sizes[3] / 2;

    float* out   = (float*)d_out;
    float* out_h = out;
    float* out_x = out + (size_t)Nn * D;
    float* out_m = out_x + (size_t)Nn * 3;

    static int smem_set = 0;
    if (!smem_set) {
        cudaFuncSetAttribute(edge_mma_kernel,
                             cudaFuncAttributeMaxDynamicSharedMemorySize, SM_TOTAL);
        smem_set = 1;
    }

    detect_kernel<<<1, 1>>>(eidx, E, Nn);
    zero_kernel<<<(Nn * D + 255) / 256, 256>>>(Nn);
    prep_weights_kernel<<<(2 * 16384 + 255) / 256, 256>>>(We2, Wx1);
    precompute_kernel<<<(Nn + NPB - 1) / NPB, 256>>>(h, We1, be1, Nn);
    edge_mma_kernel<<<148, 256, SM_TOTAL>>>(x, vel, eidx, We1,
                                            be2, bx1, Wx2, bx2, out_m, E);
    node_kernel<<<(Nn + NPB - 1) / NPB, 256>>>(h, x, Wh1, bh1, Wh2, bh2,
                                               gamma, beta, out_h, out_x, Nn);
}

// round 10
// speedup vs baseline: 1.3208x; 1.0903x over previous
#include <cuda_runtime.h>
#include <cuda_fp16.h>
#include <cstdint>

#define D 128
#define NPB 32
#define Y_PAD 136
#define NODE_PAD 264
#define MAXN 50000
#define TILE_M 128

// ---------------- device scratch (allocation-free rule) ----------------
__device__ float g_agg[MAXN * D];
__device__ float g_num[MAXN * 3];
__device__ float g_cnt[MAXN];
__device__ float g_U[MAXN * D];   // h @ We1[0:128,:] + be1
__device__ float g_V[MAXN * D];   // h @ We1[128:256,:]
__device__ int   g_is64;
// fp16 weight smem-images, XOR-swizzled [n][k] (256B rows): 0 = We2, 1 = Wx1
__device__ unsigned short g_B[2 * 16384];

__device__ __forceinline__ float silu_f(float v) {
    return v * (1.0f / (1.0f + __expf(-v)));
}
__device__ __forceinline__ float f4get(const float4& v, int k) {
    return k == 0 ? v.x : (k == 1 ? v.y : (k == 2 ? v.z : v.w));
}
__device__ __forceinline__ uint32_t smem_u32(const void* p) {
    uint32_t a;
    asm("{ .reg .u64 t; cvta.to.shared.u64 t, %1; cvt.u32.u64 %0, t; }"
        : "=r"(a) : "l"(p));
    return a;
}

#define LDSM_X4(r, addr)                                                        \
    asm volatile("ldmatrix.sync.aligned.m8n8.x4.shared.b16 {%0,%1,%2,%3}, [%4];"\
        : "=r"((r)[0]), "=r"((r)[1]), "=r"((r)[2]), "=r"((r)[3]) : "r"(addr))

#define MMA_F16(d, a, b0, b1)                                                   \
    asm volatile("mma.sync.aligned.m16n8k16.row.col.f32.f16.f16.f32 "           \
        "{%0,%1,%2,%3}, {%4,%5,%6,%7}, {%8,%9}, {%0,%1,%2,%3};"                 \
        : "+f"((d)[0]), "+f"((d)[1]), "+f"((d)[2]), "+f"((d)[3])                \
        : "r"((a)[0]), "r"((a)[1]), "r"((a)[2]), "r"((a)[3]), "r"(b0), "r"(b1))

// exact 2-term fp16 split of a float pair
__device__ __forceinline__ void split2h(float v0, float v1, uint32_t& hi, uint32_t& lo) {
    __half h0 = __float2half_rn(v0), h1 = __float2half_rn(v1);
    float r0 = v0 - __half2float(h0), r1 = v1 - __half2float(h1);
    hi = (uint32_t)__half_as_ushort(h0) | ((uint32_t)__half_as_ushort(h1) << 16);
    lo = (uint32_t)__half_as_ushort(__float2half_rn(r0))
       | ((uint32_t)__half_as_ushort(__float2half_rn(r1)) << 16);
}
__device__ __forceinline__ float hlo16(uint32_t u) {
    return __half2float(__ushort_as_half((unsigned short)(u & 0xffff)));
}
__device__ __forceinline__ float hhi16(uint32_t u) {
    return __half2float(__ushort_as_half((unsigned short)(u >> 16)));
}

// ---------------- misc small kernels ----------------
__global__ void detect_kernel(const void* eidx_raw, int E, int Nn) {
    const long long* p = (const long long*)eidx_raw;
    int ok = 1;
    for (int i = 0; i < 64 && i < E; i++) {
        long long v = p[i];
        if (v < 0 || v >= (long long)Nn) { ok = 0; break; }
    }
    g_is64 = ok;
}
__device__ __forceinline__ int load_idx(const void* eidx_raw, long long pos, int is64) {
    if (is64) return (int)((const long long*)eidx_raw)[pos];
    return ((const int*)eidx_raw)[pos];
}
__global__ void zero_kernel(int n_nodes) {
    int idx = blockIdx.x * blockDim.x + threadIdx.x;
    if (idx < n_nodes * D) g_agg[idx] = 0.f;
    if (idx < n_nodes * 3) g_num[idx] = 0.f;
    if (idx < n_nodes)     g_cnt[idx] = 0.f;
}

// Build fp16 images of We2^T, Wx1^T in swizzled [n][k] layout:
// byte off = n*256 + ((k/8 ^ (n&15))*16) + (k%8)*2
__global__ void prep_weights_kernel(const float* __restrict__ We2,
                                    const float* __restrict__ Wx1) {
    int idx = blockIdx.x * blockDim.x + threadIdx.x;
    if (idx >= 2 * 16384) return;
    int m = idx >> 14;
    int e = idx & 16383;
    int n = e >> 7;
    int k = e & 127;
    const float* W = m ? Wx1 : We2;
    float v = W[k * D + n];
    int off = n * 256 + (((k >> 3) ^ (n & 15)) << 4) + (k & 7) * 2;
    g_B[m * 16384 + (off >> 1)] = __half_as_ushort(__float2half_rn(v));
}

// ---------------- SMEM layout (bytes) ----------------
#define SM_W1   0        // 32768 (fp16 We2 image)
#define SM_W2   32768    // 32768 (fp16 Wx1 image)
#define SM_AHI  65536    // 32768
#define SM_ALO  98304    // 32768
#define SM_WGEO 131072   // 11*128 f32 = 5632
#define SM_GEO  136704   // 128*13 f32 = 6656
#define SM_DST  143360   // 128 int
#define SM_SRC  143872
#define SM_BE2  144384   // 128 f32
#define SM_BX1  144896
#define SM_WX2  145408
#define SM_PPART 145920  // 2*128 f32
#define SM_BX2  146944
#define SM_TOTAL 147456

// 2-chain fp16 GEMM: D[128,128] = (A_hi + A_lo) @ B^T, warp block 32x64.
// A split exactly into fp16 hi/lo; B rounded once to fp16.
__device__ __forceinline__ void gemm_tile(
    uint32_t aHi, uint32_t aLo, uint32_t bB,
    int lane, int m0, int nb, float acc[2][8][4])
{
    #pragma unroll
    for (int ma = 0; ma < 2; ma++)
        #pragma unroll
        for (int na = 0; na < 8; na++)
            #pragma unroll
            for (int q = 0; q < 4; q++) acc[ma][na][q] = 0.f;

    const int arow_l = lane & 15;
    const int akh    = lane >> 4;
    const int brow_l = ((lane >> 4) & 1) * 8 + (lane & 7);
    const int bkh    = (lane >> 3) & 1;

    #pragma unroll 1
    for (int kb = 0; kb < 8; kb++) {
        uint32_t ah[2][4], al[2][4], bh[4][4];
        #pragma unroll
        for (int ma = 0; ma < 2; ma++) {
            int row = m0 + ma * 16 + arow_l;
            int ch  = kb * 2 + akh;
            uint32_t off = row * 256 + ((ch ^ (row & 15)) << 4);
            LDSM_X4(ah[ma], aHi + off);
            LDSM_X4(al[ma], aLo + off);
        }
        #pragma unroll
        for (int p = 0; p < 4; p++) {
            int row = nb + p * 16 + brow_l;
            int ch  = kb * 2 + bkh;
            uint32_t off = row * 256 + ((ch ^ (row & 15)) << 4);
            LDSM_X4(bh[p], bB + off);
        }
        #pragma unroll
        for (int ma = 0; ma < 2; ma++)
            #pragma unroll
            for (int na = 0; na < 8; na++) {
                uint32_t b0 = bh[na >> 1][(na & 1) * 2];
                uint32_t b1 = bh[na >> 1][(na & 1) * 2 + 1];
                MMA_F16(acc[ma][na], ah[ma], b0, b1);
                MMA_F16(acc[ma][na], al[ma], b0, b1);
            }
    }
}

__global__ __launch_bounds__(256, 1) void edge_mma_kernel(
    const float* __restrict__ x, const float* __restrict__ vel,
    const void* __restrict__ eidx_raw, const float* __restrict__ We1,
    const float* __restrict__ be2, const float* __restrict__ bx1,
    const float* __restrict__ Wx2, const float* __restrict__ bx2,
    float* __restrict__ out_m, int E)
{
    extern __shared__ char smem[];
    float* smf = (float*)smem;
    const uint32_t sb = smem_u32(smem);
    const int tid  = threadIdx.x;
    const int warp = tid >> 5;
    const int lane = tid & 31;
    const int m0   = (warp & 3) * 32;   // GEMM row block
    const int nb   = (warp >> 2) * 64;  // GEMM col block
    const int rw0  = warp * 16;         // scalar phase: warp owns 16 edge rows
    const int c0   = lane * 4;          // scalar phase: lane owns 4 cols
    const int is64 = g_is64;

    // ---- one-time init: weights + biases to smem ----
    {
        const uint4* sw = (const uint4*)g_B;
        for (int i = tid; i < 2048; i += 256) {
            ((uint4*)(smem + SM_W1))[i] = sw[i];
            ((uint4*)(smem + SM_W2))[i] = sw[2048 + i];
        }
    }
    if (tid < 128) {
        smf[(SM_BE2 >> 2) + tid] = be2[tid];
        smf[(SM_BX1 >> 2) + tid] = bx1[tid];
        smf[(SM_WX2 >> 2) + tid] = Wx2[tid];
    }
    if (tid == 0) smf[SM_BX2 >> 2] = bx2[0];
    for (int i = tid; i < 11 * 128; i += 256)
        smf[(SM_WGEO >> 2) + i] = We1[256 * D + i];
    __syncthreads();

    float* geo_sf = smf + (SM_GEO >> 2);
    int*   dst_s  = (int*)(smem + SM_DST);
    int*   src_s  = (int*)(smem + SM_SRC);
    float* ppart  = smf + (SM_PPART >> 2);

    const int ntiles = (E + TILE_M - 1) / TILE_M;

    for (int tile = blockIdx.x; tile < ntiles; tile += gridDim.x) {
        const int ebase = tile * TILE_M;

        // ===== stage: indices + geometry (tid<128, edge = tid) =====
        float relx = 0.f, rely = 0.f, relz = 0.f;
        int dreg = 0; bool vreg = false;
        if (tid < 128) {
            int eg = ebase + tid;
            vreg = (eg < E);
            int ec = vreg ? eg : 0;
            int s = load_idx(eidx_raw, ec, is64);
            int d = load_idx(eidx_raw, (long long)E + ec, is64);
            src_s[tid] = s; dst_s[tid] = d; dreg = d;
            float rx = x[s*3+0] - x[d*3+0];
            float ry = x[s*3+1] - x[d*3+1];
            float rz = x[s*3+2] - x[d*3+2];
            relx = rx; rely = ry; relz = rz;
            float d2 = rx*rx + ry*ry + rz*rz;
            float dist = fmaxf(sqrtf(d2), 1e-8f);
            float inv = 1.0f / dist;
            float ux = rx*inv, uy = ry*inv, uz = rz*inv;
            geo_sf[tid * 13 + 0] = d2;
            #pragma unroll
            for (int j = 0; j < 5; j++) {
                const float* vs = vel + (size_t)s * 15 + j * 3;
                const float* vd = vel + (size_t)d * 15 + j * 3;
                geo_sf[tid * 13 + 1 + j] = vs[0]*ux + vs[1]*uy + vs[2]*uz;
                geo_sf[tid * 13 + 6 + j] = vd[0]*ux + vd[1]*uy + vd[2]*uz;
            }
        }
        __syncthreads();

        // ===== scalar phase (column-mapped, coalesced gathers) =====
        {
            float z[16][4];
            #pragma unroll
            for (int i = 0; i < 16; i++) {
                int s2  = src_s[rw0 + i];
                int d2i = dst_s[rw0 + i];
                float4 u = *(const float4*)(g_U + (size_t)s2 * D + c0);
                float4 v = *(const float4*)(g_V + (size_t)d2i * D + c0);
                z[i][0] = u.x + v.x; z[i][1] = u.y + v.y;
                z[i][2] = u.z + v.z; z[i][3] = u.w + v.w;
            }
            #pragma unroll 1
            for (int k = 0; k < 11; k++) {
                float4 w = *(const float4*)(smf + (SM_WGEO >> 2) + k * D + c0);
                #pragma unroll
                for (int i = 0; i < 16; i++) {
                    float f = geo_sf[(rw0 + i) * 13 + k];   // LDS broadcast
                    z[i][0] = fmaf(f, w.x, z[i][0]);
                    z[i][1] = fmaf(f, w.y, z[i][1]);
                    z[i][2] = fmaf(f, w.z, z[i][2]);
                    z[i][3] = fmaf(f, w.w, z[i][3]);
                }
            }
            const int chunk = c0 >> 3;
            const int sub   = (c0 & 7) * 2;
            #pragma unroll
            for (int i = 0; i < 16; i++) {
                int r = rw0 + i;
                float v0 = silu_f(z[i][0]), v1 = silu_f(z[i][1]);
                float v2 = silu_f(z[i][2]), v3 = silu_f(z[i][3]);
                uint32_t h0, l0, h1, l1;
                split2h(v0, v1, h0, l0);
                split2h(v2, v3, h1, l1);
                uint32_t off = r * 256 + ((chunk ^ (r & 15)) << 4) + sub;
                *(uint2*)(smem + SM_AHI + off) = make_uint2(h0, h1);
                *(uint2*)(smem + SM_ALO + off) = make_uint2(l0, l1);
            }
        }
        __syncthreads();

        // ===== GEMM1: y1 @ We2 =====
        float acc[2][8][4];
        gemm_tile(sb + SM_AHI, sb + SM_ALO, sb + SM_W1, lane, m0, nb, acc);
        __syncthreads();   // A reads done block-wide before overwrite

        // epilogue1: m = silu(acc + be2) -> A buffers (fragment layout)
        #pragma unroll
        for (int ma = 0; ma < 2; ma++)
            #pragma unroll
            for (int na = 0; na < 8; na++) {
                int col = nb + na * 8 + (lane & 3) * 2;
                float b0 = smf[(SM_BE2 >> 2) + col];
                float b1 = smf[(SM_BE2 >> 2) + col + 1];
                int rA = m0 + ma * 16 + (lane >> 2);
                int rB = rA + 8;
                float v0 = silu_f(acc[ma][na][0] + b0);
                float v1 = silu_f(acc[ma][na][1] + b1);
                float v2 = silu_f(acc[ma][na][2] + b0);
                float v3 = silu_f(acc[ma][na][3] + b1);
                uint32_t hA, lA, hB, lB;
                split2h(v0, v1, hA, lA);
                split2h(v2, v3, hB, lB);
                uint32_t offA = rA * 256 + (((col >> 3) ^ (rA & 15)) << 4) + (col & 7) * 2;
                uint32_t offB = rB * 256 + (((col >> 3) ^ (rB & 15)) << 4) + (col & 7) * 2;
                *(uint32_t*)(smem + SM_AHI + offA) = hA;
                *(uint32_t*)(smem + SM_ALO + offA) = lA;
                *(uint32_t*)(smem + SM_AHI + offB) = hB;
                *(uint32_t*)(smem + SM_ALO + offB) = lB;
            }
        __syncthreads();

        // ===== GEMM2: m @ Wx1 =====
        gemm_tile(sb + SM_AHI, sb + SM_ALO, sb + SM_W2, lane, m0, nb, acc);

        // out_m + agg atomics from A buffers (m = hi + lo), coalesced
        #pragma unroll 1
        for (int i = 0; i < 16; i++) {
            int row = warp * 16 + i;
            int eg = ebase + row;
            if (eg < E) {
                uint32_t off = row * 256 + ((((lane >> 1) ^ (row & 15))) << 4)
                             + (lane & 1) * 8;
                uint2 uh = *(const uint2*)(smem + SM_AHI + off);
                uint2 ul = *(const uint2*)(smem + SM_ALO + off);
                float4 f;
                f.x = hlo16(uh.x) + hlo16(ul.x);
                f.y = hhi16(uh.x) + hhi16(ul.x);
                f.z = hlo16(uh.y) + hlo16(ul.y);
                f.w = hhi16(uh.y) + hhi16(ul.y);
                *(float4*)(out_m + (size_t)eg * D + lane * 4) = f;
                float* ag = g_agg + (size_t)dst_s[row] * D + lane * 4;
                atomicAdd(ag + 0, f.x);
                atomicAdd(ag + 1, f.y);
                atomicAdd(ag + 2, f.z);
                atomicAdd(ag + 3, f.w);
            }
        }

        // phi_x tail: p_row = sum_col silu(acc2 + bx1)*wx2 (fragment reduce)
        {
            float ps[2][2] = {{0.f, 0.f}, {0.f, 0.f}};
            #pragma unroll
            for (int ma = 0; ma < 2; ma++)
                #pragma unroll
                for (int na = 0; na < 8; na++) {
                    int col = nb + na * 8 + (lane & 3) * 2;
                    float b0 = smf[(SM_BX1 >> 2) + col];
                    float b1 = smf[(SM_BX1 >> 2) + col + 1];
                    float w0 = smf[(SM_WX2 >> 2) + col];
                    float w1 = smf[(SM_WX2 >> 2) + col + 1];
                    ps[ma][0] += silu_f(acc[ma][na][0] + b0) * w0
                               + silu_f(acc[ma][na][1] + b1) * w1;
                    ps[ma][1] += silu_f(acc[ma][na][2] + b0) * w0
                               + silu_f(acc[ma][na][3] + b1) * w1;
                }
            #pragma unroll
            for (int ma = 0; ma < 2; ma++)
                #pragma unroll
                for (int q = 0; q < 2; q++) {
                    ps[ma][q] += __shfl_xor_sync(0xffffffffu, ps[ma][q], 1);
                    ps[ma][q] += __shfl_xor_sync(0xffffffffu, ps[ma][q], 2);
                }
            if ((lane & 3) == 0) {
                int base = (warp >> 2) * 128;
                #pragma unroll
                for (int ma = 0; ma < 2; ma++) {
                    int rA = m0 + ma * 16 + (lane >> 2);
                    ppart[base + rA]     = ps[ma][0];
                    ppart[base + rA + 8] = ps[ma][1];
                }
            }
        }
        __syncthreads();

        if (tid < 128 && vreg) {
            float p = ppart[tid] + ppart[128 + tid] + smf[SM_BX2 >> 2];
            atomicAdd(&g_num[dreg*3 + 0], relx * p);
            atomicAdd(&g_num[dreg*3 + 1], rely * p);
            atomicAdd(&g_num[dreg*3 + 2], relz * p);
            atomicAdd(&g_cnt[dreg], 1.0f);
        }
        __syncthreads();
    }
}

// ---------------- scalar GEMM helper for node/precompute ----------------
#define GEMM_4x4(fr, PAD, W, KLEN, acc)                                        \
    _Pragma("unroll 2")                                                        \
    for (int k4 = 0; k4 < (KLEN); k4 += 4) {                                   \
        float4 f0 = *(const float4*)((fr) + 0 * (PAD) + k4);                   \
        float4 f1 = *(const float4*)((fr) + 1 * (PAD) + k4);                   \
        float4 f2 = *(const float4*)((fr) + 2 * (PAD) + k4);                   \
        float4 f3 = *(const float4*)((fr) + 3 * (PAD) + k4);                   \
        _Pragma("unroll")                                                      \
        for (int kk = 0; kk < 4; kk++) {                                       \
            float4 w = *(const float4*)((W) + (k4 + kk) * D + c0);             \
            float e0 = f4get(f0, kk), e1 = f4get(f1, kk);                      \
            float e2 = f4get(f2, kk), e3 = f4get(f3, kk);                      \
            acc[0][0] = fmaf(e0, w.x, acc[0][0]);                              \
            acc[0][1] = fmaf(e0, w.y, acc[0][1]);                              \
            acc[0][2] = fmaf(e0, w.z, acc[0][2]);                              \
            acc[0][3] = fmaf(e0, w.w, acc[0][3]);                              \
            acc[1][0] = fmaf(e1, w.x, acc[1][0]);                              \
            acc[1][1] = fmaf(e1, w.y, acc[1][1]);                              \
            acc[1][2] = fmaf(e1, w.z, acc[1][2]);                              \
            acc[1][3] = fmaf(e1, w.w, acc[1][3]);                              \
            acc[2][0] = fmaf(e2, w.x, acc[2][0]);                              \
            acc[2][1] = fmaf(e2, w.y, acc[2][1]);                              \
            acc[2][2] = fmaf(e2, w.z, acc[2][2]);                              \
            acc[2][3] = fmaf(e2, w.w, acc[2][3]);                              \
            acc[3][0] = fmaf(e3, w.x, acc[3][0]);                              \
            acc[3][1] = fmaf(e3, w.y, acc[3][1]);                              \
            acc[3][2] = fmaf(e3, w.z, acc[3][2]);                              \
            acc[3][3] = fmaf(e3, w.w, acc[3][3]);                              \
        }                                                                      \
    }

__global__ __launch_bounds__(256) void precompute_kernel(
    const float* __restrict__ h, const float* __restrict__ We1,
    const float* __restrict__ be1, int Nn)
{
    __shared__ float fs[NPB * Y_PAD];
    const int warp = threadIdx.x >> 5;
    const int lane = threadIdx.x & 31;
    const int c0   = lane * 4;
    const int nbase = blockIdx.x * NPB;

    int nidx[4]; bool valid[4];
    #pragma unroll
    for (int i = 0; i < 4; i++) {
        int nl = warp * 4 + i;
        int n  = nbase + nl;
        valid[i] = (n < Nn);
        nidx[i] = valid[i] ? n : 0;
        float4 hh = *(const float4*)(h + (size_t)nidx[i] * D + c0);
        *(float4*)(fs + nl * Y_PAD + c0) = hh;
    }
    __syncwarp();

    const float* fr = fs + (warp * 4) * Y_PAD;
    float acc[4][4];
    {
        float4 b = *(const float4*)(be1 + c0);
        #pragma unroll
        for (int i = 0; i < 4; i++) {
            acc[i][0] = b.x; acc[i][1] = b.y; acc[i][2] = b.z; acc[i][3] = b.w;
        }
    }
    GEMM_4x4(fr, Y_PAD, We1, 128, acc)
    #pragma unroll
    for (int i = 0; i < 4; i++)
        if (valid[i])
            *(float4*)(g_U + (size_t)nidx[i] * D + c0) =
                make_float4(acc[i][0], acc[i][1], acc[i][2], acc[i][3]);

    #pragma unroll
    for (int i = 0; i < 4; i++) {
        acc[i][0] = 0.f; acc[i][1] = 0.f; acc[i][2] = 0.f; acc[i][3] = 0.f;
    }
    GEMM_4x4(fr, Y_PAD, We1 + 128 * D, 128, acc)
    #pragma unroll
    for (int i = 0; i < 4; i++)
        if (valid[i])
            *(float4*)(g_V + (size_t)nidx[i] * D + c0) =
                make_float4(acc[i][0], acc[i][1], acc[i][2], acc[i][3]);
}

__global__ __launch_bounds__(256) void node_kernel(
    const float* __restrict__ h, const float* __restrict__ x,
    const float* __restrict__ Wh1, const float* __restrict__ bh1,
    const float* __restrict__ Wh2, const float* __restrict__ bh2,
    const float* __restrict__ gamma, const float* __restrict__ beta,
    float* __restrict__ out_h, float* __restrict__ out_x, int Nn)
{
    __shared__ float fs[NPB * NODE_PAD];
    const int warp = threadIdx.x >> 5;
    const int lane = threadIdx.x & 31;
    const int c0   = lane * 4;
    const int nbase = blockIdx.x * NPB;

    bool valid[4];
    int nidx[4];
    #pragma unroll
    for (int i = 0; i < 4; i++) {
        int nl = warp * 4 + i;
        int n  = nbase + nl;
        valid[i] = (n < Nn);
        int nc = valid[i] ? n : 0;
        nidx[i] = nc;
        float4 hh = *(const float4*)(h + (size_t)nc * D + c0);
        float4 ag = *(const float4*)(g_agg + (size_t)nc * D + c0);
        *(float4*)(fs + nl * NODE_PAD + c0)       = hh;
        *(float4*)(fs + nl * NODE_PAD + 128 + c0) = ag;
    }
    __syncwarp();

    const float* fr = fs + (warp * 4) * NODE_PAD;
    float acc[4][4];
    {
        float4 b = *(const float4*)(bh1 + c0);
        #pragma unroll
        for (int i = 0; i < 4; i++) {
            acc[i][0] = b.x; acc[i][1] = b.y; acc[i][2] = b.z; acc[i][3] = b.w;
        }
    }
    GEMM_4x4(fr, NODE_PAD, Wh1, 256, acc)
    #pragma unroll
    for (int i = 0; i < 4; i++)
        #pragma unroll
        for (int q = 0; q < 4; q++) acc[i][q] = silu_f(acc[i][q]);

    __syncwarp();
    #pragma unroll
    for (int i = 0; i < 4; i++)
        *(float4*)(fs + (warp*4 + i) * NODE_PAD + c0) =
            make_float4(acc[i][0], acc[i][1], acc[i][2], acc[i][3]);
    __syncwarp();

    {
        float4 b = *(const float4*)(bh2 + c0);
        #pragma unroll
        for (int i = 0; i < 4; i++) {
            acc[i][0] = b.x; acc[i][1] = b.y; acc[i][2] = b.z; acc[i][3] = b.w;
        }
    }
    GEMM_4x4(fr, NODE_PAD, Wh2, 128, acc)

    float hn[4][4];
    float mu[4], rstd[4];
    #pragma unroll
    for (int i = 0; i < 4; i++) {
        float4 hh = *(const float4*)(h + (size_t)nidx[i] * D + c0);
        hn[i][0] = hh.x + acc[i][0];
        hn[i][1] = hh.y + acc[i][1];
        hn[i][2] = hh.z + acc[i][2];
        hn[i][3] = hh.w + acc[i][3];
        float s1 = hn[i][0] + hn[i][1] + hn[i][2] + hn[i][3];
        float s2 = hn[i][0]*hn[i][0] + hn[i][1]*hn[i][1]
                 + hn[i][2]*hn[i][2] + hn[i][3]*hn[i][3];
        #pragma unroll
        for (int off = 16; off > 0; off >>= 1) {
            s1 += __shfl_xor_sync(0xffffffffu, s1, off);
            s2 += __shfl_xor_sync(0xffffffffu, s2, off);
        }
        mu[i] = s1 * (1.0f / 128.0f);
        float var = s2 * (1.0f / 128.0f) - mu[i]*mu[i];
        rstd[i] = rsqrtf(var + 1e-5f);
    }
    float4 g = *(const float4*)(gamma + c0);
    float4 b = *(const float4*)(beta + c0);
    #pragma unroll
    for (int i = 0; i < 4; i++) {
        if (valid[i]) {
            float4 o;
            o.x = (hn[i][0] - mu[i]) * rstd[i] * g.x + b.x;
            o.y = (hn[i][1] - mu[i]) * rstd[i] * g.y + b.y;
            o.z = (hn[i][2] - mu[i]) * rstd[i] * g.z + b.z;
            o.w = (hn[i][3] - mu[i]) * rstd[i] * g.w + b.w;
            *(float4*)(out_h + (size_t)nidx[i] * D + c0) = o;
        }
    }
    if (lane == 0) {
        #pragma unroll
        for (int i = 0; i < 4; i++) {
            if (valid[i]) {
                int n = nidx[i];
                float cnt = g_cnt[n];
                float inv = 1.0f / fmaxf(cnt, 1.0f);
                out_x[n*3 + 0] = x[n*3 + 0] + g_num[n*3 + 0] * inv;
                out_x[n*3 + 1] = x[n*3 + 1] + g_num[n*3 + 1] * inv;
                out_x[n*3 + 2] = x[n*3 + 2] + g_num[n*3 + 2] * inv;
            }
        }
    }
}

extern "C" void kernel_launch(void* const* d_in, const int* in_sizes, int n_in,
                              void* d_out, int out_size) {
    const float* h    = (const float*)d_in[0];
    const float* x    = (const float*)d_in[1];
    const float* vel  = (const float*)d_in[2];
    const void*  eidx = d_in[3];
    const float* We1 = (const float*)d_in[4],  *be1 = (const float*)d_in[5];
    const float* We2 = (const float*)d_in[6],  *be2 = (const float*)d_in[7];
    const float* Wx1 = (const float*)d_in[8],  *bx1 = (const float*)d_in[9];
    const float* Wx2 = (const float*)d_in[10], *bx2 = (const float*)d_in[11];
    const float* Wh1 = (const float*)d_in[12], *bh1 = (const float*)d_in[13];
    const float* Wh2 = (const float*)d_in[14], *bh2 = (const float*)d_in[15];
    const float* gamma = (const float*)d_in[16], *beta = (const float*)d_in[17];

    int Nn = in_sizes[0] / D;
    int E  = in_sizes[3] / 2;

    float* out   = (float*)d_out;
    float* out_h = out;
    float* out_x = out + (size_t)Nn * D;
    float* out_m = out_x + (size_t)Nn * 3;

    static int smem_set = 0;
    if (!smem_set) {
        cudaFuncSetAttribute(edge_mma_kernel,
                             cudaFuncAttributeMaxDynamicSharedMemorySize, SM_TOTAL);
        smem_set = 1;
    }

    detect_kernel<<<1, 1>>>(eidx, E, Nn);
    zero_kernel<<<(Nn * D + 255) / 256, 256>>>(Nn);
    prep_weights_kernel<<<(2 * 16384 + 255) / 256, 256>>>(We2, Wx1);
    precompute_kernel<<<(Nn + NPB - 1) / NPB, 256>>>(h, We1, be1, Nn);
    edge_mma_kernel<<<148, 256, SM_TOTAL>>>(x, vel, eidx, We1,
                                            be2, bx1, Wx2, bx2, out_m, E);
    node_kernel<<<(Nn + NPB - 1) / NPB, 256>>>(h, x, Wh1, bh1, Wh2, bh2,
                                               gamma, beta, out_h, out_x, Nn);
}

// round 11
// speedup vs baseline: 1.7589x; 1.3316x over previous
#include <cuda_runtime.h>
#include <cuda_fp16.h>
#include <cstdint>

#define D 128
#define NPB 32
#define Y_PAD 136
#define NODE_PAD 264
#define MAXN 50000
#define TILE_M 64

// ---------------- device scratch (allocation-free rule) ----------------
__device__ float g_agg[MAXN * D];
__device__ float g_num[MAXN * 3];
__device__ float g_cnt[MAXN];
__device__ float g_U[MAXN * D];   // h @ We1[0:128,:] + be1
__device__ float g_V[MAXN * D];   // h @ We1[128:256,:]
__device__ int   g_is64;
// fp16 weight smem-images, XOR-swizzled [n][k] (256B rows): 0 = We2, 1 = Wx1
__device__ unsigned short g_B[2 * 16384];

__device__ __forceinline__ float silu_f(float v) {
    return v * (1.0f / (1.0f + __expf(-v)));
}
__device__ __forceinline__ float f4get(const float4& v, int k) {
    return k == 0 ? v.x : (k == 1 ? v.y : (k == 2 ? v.z : v.w));
}
__device__ __forceinline__ uint32_t smem_u32(const void* p) {
    uint32_t a;
    asm("{ .reg .u64 t; cvta.to.shared.u64 t, %1; cvt.u32.u64 %0, t; }"
        : "=r"(a) : "l"(p));
    return a;
}

#define LDSM_X4(r, addr)                                                        \
    asm volatile("ldmatrix.sync.aligned.m8n8.x4.shared.b16 {%0,%1,%2,%3}, [%4];"\
        : "=r"((r)[0]), "=r"((r)[1]), "=r"((r)[2]), "=r"((r)[3]) : "r"(addr))

#define MMA_F16(d, a, b0, b1)                                                   \
    asm volatile("mma.sync.aligned.m16n8k16.row.col.f32.f16.f16.f32 "           \
        "{%0,%1,%2,%3}, {%4,%5,%6,%7}, {%8,%9}, {%0,%1,%2,%3};"                 \
        : "+f"((d)[0]), "+f"((d)[1]), "+f"((d)[2]), "+f"((d)[3])                \
        : "r"((a)[0]), "r"((a)[1]), "r"((a)[2]), "r"((a)[3]), "r"(b0), "r"(b1))

// exact 2-term fp16 split of a float pair
__device__ __forceinline__ void split2h(float v0, float v1, uint32_t& hi, uint32_t& lo) {
    __half h0 = __float2half_rn(v0), h1 = __float2half_rn(v1);
    float r0 = v0 - __half2float(h0), r1 = v1 - __half2float(h1);
    hi = (uint32_t)__half_as_ushort(h0) | ((uint32_t)__half_as_ushort(h1) << 16);
    lo = (uint32_t)__half_as_ushort(__float2half_rn(r0))
       | ((uint32_t)__half_as_ushort(__float2half_rn(r1)) << 16);
}
__device__ __forceinline__ float hlo16(uint32_t u) {
    return __half2float(__ushort_as_half((unsigned short)(u & 0xffff)));
}
__device__ __forceinline__ float hhi16(uint32_t u) {
    return __half2float(__ushort_as_half((unsigned short)(u >> 16)));
}

// ---------------- misc small kernels ----------------
__global__ void detect_kernel(const void* eidx_raw, int E, int Nn) {
    const long long* p = (const long long*)eidx_raw;
    int ok = 1;
    for (int i = 0; i < 64 && i < E; i++) {
        long long v = p[i];
        if (v < 0 || v >= (long long)Nn) { ok = 0; break; }
    }
    g_is64 = ok;
}
__device__ __forceinline__ int load_idx(const void* eidx_raw, long long pos, int is64) {
    if (is64) return (int)((const long long*)eidx_raw)[pos];
    return ((const int*)eidx_raw)[pos];
}
__global__ void zero_kernel(int n_nodes) {
    int idx = blockIdx.x * blockDim.x + threadIdx.x;
    if (idx < n_nodes * D) g_agg[idx] = 0.f;
    if (idx < n_nodes * 3) g_num[idx] = 0.f;
    if (idx < n_nodes)     g_cnt[idx] = 0.f;
}

// Build fp16 images of We2^T, Wx1^T in swizzled [n][k] layout:
// byte off = n*256 + ((k/8 ^ (n&15))*16) + (k%8)*2
__global__ void prep_weights_kernel(const float* __restrict__ We2,
                                    const float* __restrict__ Wx1) {
    int idx = blockIdx.x * blockDim.x + threadIdx.x;
    if (idx >= 2 * 16384) return;
    int m = idx >> 14;
    int e = idx & 16383;
    int n = e >> 7;
    int k = e & 127;
    const float* W = m ? Wx1 : We2;
    float v = W[k * D + n];
    int off = n * 256 + (((k >> 3) ^ (n & 15)) << 4) + (k & 7) * 2;
    g_B[m * 16384 + (off >> 1)] = __half_as_ushort(__float2half_rn(v));
}

// ---------------- SMEM layout (bytes), TILE_M = 64 ----------------
#define SM_W1   0        // 32768 (fp16 We2 image)
#define SM_W2   32768    // 32768 (fp16 Wx1 image)
#define SM_AHI  65536    // 16384 (64 rows x 256B)
#define SM_ALO  81920    // 16384
#define SM_WGEO 98304    // 11*128 f32 = 5632
#define SM_GEO  103936   // 64*13 f32 = 3328
#define SM_DST  107264   // 64 int
#define SM_SRC  107520
#define SM_BE2  107776   // 128 f32
#define SM_BX1  108288
#define SM_WX2  108800
#define SM_PPART 109312  // 2*64 f32
#define SM_BX2  109824
#define SM_TOTAL 109840

// 2-chain fp16 GEMM: D[64,128] = (A_hi + A_lo) @ B^T, warp block 16x64.
__device__ __forceinline__ void gemm_tile16(
    uint32_t aHi, uint32_t aLo, uint32_t bB,
    int lane, int m0, int nb, float acc[8][4])
{
    #pragma unroll
    for (int na = 0; na < 8; na++)
        #pragma unroll
        for (int q = 0; q < 4; q++) acc[na][q] = 0.f;

    const int arow_l = lane & 15;
    const int akh    = lane >> 4;
    const int brow_l = ((lane >> 4) & 1) * 8 + (lane & 7);
    const int bkh    = (lane >> 3) & 1;

    #pragma unroll 1
    for (int kb = 0; kb < 8; kb++) {
        uint32_t ah[4], al[4], bh[4][4];
        {
            int row = m0 + arow_l;
            int ch  = kb * 2 + akh;
            uint32_t off = row * 256 + ((ch ^ (row & 15)) << 4);
            LDSM_X4(ah, aHi + off);
            LDSM_X4(al, aLo + off);
        }
        #pragma unroll
        for (int p = 0; p < 4; p++) {
            int row = nb + p * 16 + brow_l;
            int ch  = kb * 2 + bkh;
            uint32_t off = row * 256 + ((ch ^ (row & 15)) << 4);
            LDSM_X4(bh[p], bB + off);
        }
        #pragma unroll
        for (int na = 0; na < 8; na++) {
            uint32_t b0 = bh[na >> 1][(na & 1) * 2];
            uint32_t b1 = bh[na >> 1][(na & 1) * 2 + 1];
            MMA_F16(acc[na], ah, b0, b1);
            MMA_F16(acc[na], al, b0, b1);
        }
    }
}

__global__ __launch_bounds__(256, 2) void edge_mma_kernel(
    const float* __restrict__ x, const float* __restrict__ vel,
    const void* __restrict__ eidx_raw, const float* __restrict__ We1,
    const float* __restrict__ be2, const float* __restrict__ bx1,
    const float* __restrict__ Wx2, const float* __restrict__ bx2,
    float* __restrict__ out_m, int E)
{
    extern __shared__ char smem[];
    float* smf = (float*)smem;
    const uint32_t sb = smem_u32(smem);
    const int tid  = threadIdx.x;
    const int warp = tid >> 5;
    const int lane = tid & 31;
    const int m0   = (warp & 3) * 16;   // GEMM row block (16 rows)
    const int nb   = (warp >> 2) * 64;  // GEMM col block
    const int rw0  = warp * 8;          // scalar phase: warp owns 8 edge rows
    const int c0   = lane * 4;          // scalar phase: lane owns 4 cols
    const int is64 = g_is64;

    // ---- one-time init: weights + biases to smem ----
    {
        const uint4* sw = (const uint4*)g_B;
        for (int i = tid; i < 2048; i += 256) {
            ((uint4*)(smem + SM_W1))[i] = sw[i];
            ((uint4*)(smem + SM_W2))[i] = sw[2048 + i];
        }
    }
    if (tid < 128) {
        smf[(SM_BE2 >> 2) + tid] = be2[tid];
        smf[(SM_BX1 >> 2) + tid] = bx1[tid];
        smf[(SM_WX2 >> 2) + tid] = Wx2[tid];
    }
    if (tid == 0) smf[SM_BX2 >> 2] = bx2[0];
    for (int i = tid; i < 11 * 128; i += 256)
        smf[(SM_WGEO >> 2) + i] = We1[256 * D + i];
    __syncthreads();

    float* geo_sf = smf + (SM_GEO >> 2);
    int*   dst_s  = (int*)(smem + SM_DST);
    int*   src_s  = (int*)(smem + SM_SRC);
    float* ppart  = smf + (SM_PPART >> 2);

    const int ntiles = (E + TILE_M - 1) / TILE_M;

    for (int tile = blockIdx.x; tile < ntiles; tile += gridDim.x) {
        const int ebase = tile * TILE_M;

        // ===== stage: indices + geometry (tid<64, edge = tid) =====
        float relx = 0.f, rely = 0.f, relz = 0.f;
        int dreg = 0; bool vreg = false;
        if (tid < TILE_M) {
            int eg = ebase + tid;
            vreg = (eg < E);
            int ec = vreg ? eg : 0;
            int s = load_idx(eidx_raw, ec, is64);
            int d = load_idx(eidx_raw, (long long)E + ec, is64);
            src_s[tid] = s; dst_s[tid] = d; dreg = d;
            float rx = x[s*3+0] - x[d*3+0];
            float ry = x[s*3+1] - x[d*3+1];
            float rz = x[s*3+2] - x[d*3+2];
            relx = rx; rely = ry; relz = rz;
            float d2 = rx*rx + ry*ry + rz*rz;
            float dist = fmaxf(sqrtf(d2), 1e-8f);
            float inv = 1.0f / dist;
            float ux = rx*inv, uy = ry*inv, uz = rz*inv;
            geo_sf[tid * 13 + 0] = d2;
            #pragma unroll
            for (int j = 0; j < 5; j++) {
                const float* vs = vel + (size_t)s * 15 + j * 3;
                const float* vd = vel + (size_t)d * 15 + j * 3;
                geo_sf[tid * 13 + 1 + j] = vs[0]*ux + vs[1]*uy + vs[2]*uz;
                geo_sf[tid * 13 + 6 + j] = vd[0]*ux + vd[1]*uy + vd[2]*uz;
            }
        }
        __syncthreads();

        // ===== scalar phase (column-mapped, coalesced gathers) =====
        {
            float z[8][4];
            #pragma unroll
            for (int i = 0; i < 8; i++) {
                int s2  = src_s[rw0 + i];
                int d2i = dst_s[rw0 + i];
                float4 u = *(const float4*)(g_U + (size_t)s2 * D + c0);
                float4 v = *(const float4*)(g_V + (size_t)d2i * D + c0);
                z[i][0] = u.x + v.x; z[i][1] = u.y + v.y;
                z[i][2] = u.z + v.z; z[i][3] = u.w + v.w;
            }
            #pragma unroll 1
            for (int k = 0; k < 11; k++) {
                float4 w = *(const float4*)(smf + (SM_WGEO >> 2) + k * D + c0);
                #pragma unroll
                for (int i = 0; i < 8; i++) {
                    float f = geo_sf[(rw0 + i) * 13 + k];   // LDS broadcast
                    z[i][0] = fmaf(f, w.x, z[i][0]);
                    z[i][1] = fmaf(f, w.y, z[i][1]);
                    z[i][2] = fmaf(f, w.z, z[i][2]);
                    z[i][3] = fmaf(f, w.w, z[i][3]);
                }
            }
            const int chunk = c0 >> 3;
            const int sub   = (c0 & 7) * 2;
            #pragma unroll
            for (int i = 0; i < 8; i++) {
                int r = rw0 + i;
                float v0 = silu_f(z[i][0]), v1 = silu_f(z[i][1]);
                float v2 = silu_f(z[i][2]), v3 = silu_f(z[i][3]);
                uint32_t h0, l0, h1, l1;
                split2h(v0, v1, h0, l0);
                split2h(v2, v3, h1, l1);
                uint32_t off = r * 256 + ((chunk ^ (r & 15)) << 4) + sub;
                *(uint2*)(smem + SM_AHI + off) = make_uint2(h0, h1);
                *(uint2*)(smem + SM_ALO + off) = make_uint2(l0, l1);
            }
        }
        __syncthreads();

        // ===== GEMM1: y1 @ We2 =====
        float acc[8][4];
        gemm_tile16(sb + SM_AHI, sb + SM_ALO, sb + SM_W1, lane, m0, nb, acc);
        __syncthreads();   // A reads done block-wide before overwrite

        // epilogue1: m = silu(acc + be2) -> A buffers (fragment layout)
        #pragma unroll
        for (int na = 0; na < 8; na++) {
            int col = nb + na * 8 + (lane & 3) * 2;
            float b0 = smf[(SM_BE2 >> 2) + col];
            float b1 = smf[(SM_BE2 >> 2) + col + 1];
            int rA = m0 + (lane >> 2);
            int rB = rA + 8;
            float v0 = silu_f(acc[na][0] + b0);
            float v1 = silu_f(acc[na][1] + b1);
            float v2 = silu_f(acc[na][2] + b0);
            float v3 = silu_f(acc[na][3] + b1);
            uint32_t hA, lA, hB, lB;
            split2h(v0, v1, hA, lA);
            split2h(v2, v3, hB, lB);
            uint32_t offA = rA * 256 + (((col >> 3) ^ (rA & 15)) << 4) + (col & 7) * 2;
            uint32_t offB = rB * 256 + (((col >> 3) ^ (rB & 15)) << 4) + (col & 7) * 2;
            *(uint32_t*)(smem + SM_AHI + offA) = hA;
            *(uint32_t*)(smem + SM_ALO + offA) = lA;
            *(uint32_t*)(smem + SM_AHI + offB) = hB;
            *(uint32_t*)(smem + SM_ALO + offB) = lB;
        }
        __syncthreads();

        // ===== GEMM2: m @ Wx1 =====
        gemm_tile16(sb + SM_AHI, sb + SM_ALO, sb + SM_W2, lane, m0, nb, acc);

        // out_m + agg atomics from A buffers (m = hi + lo), coalesced
        #pragma unroll 1
        for (int i = 0; i < 8; i++) {
            int row = warp * 8 + i;
            int eg = ebase + row;
            if (eg < E) {
                uint32_t off = row * 256 + ((((lane >> 1) ^ (row & 15))) << 4)
                             + (lane & 1) * 8;
                uint2 uh = *(const uint2*)(smem + SM_AHI + off);
                uint2 ul = *(const uint2*)(smem + SM_ALO + off);
                float4 f;
                f.x = hlo16(uh.x) + hlo16(ul.x);
                f.y = hhi16(uh.x) + hhi16(ul.x);
                f.z = hlo16(uh.y) + hlo16(ul.y);
                f.w = hhi16(uh.y) + hhi16(ul.y);
                *(float4*)(out_m + (size_t)eg * D + lane * 4) = f;
                float* ag = g_agg + (size_t)dst_s[row] * D + lane * 4;
                atomicAdd(ag + 0, f.x);
                atomicAdd(ag + 1, f.y);
                atomicAdd(ag + 2, f.z);
                atomicAdd(ag + 3, f.w);
            }
        }

        // phi_x tail: p_row = sum_col silu(acc2 + bx1)*wx2 (fragment reduce)
        {
            float ps[2] = {0.f, 0.f};
            #pragma unroll
            for (int na = 0; na < 8; na++) {
                int col = nb + na * 8 + (lane & 3) * 2;
                float b0 = smf[(SM_BX1 >> 2) + col];
                float b1 = smf[(SM_BX1 >> 2) + col + 1];
                float w0 = smf[(SM_WX2 >> 2) + col];
                float w1 = smf[(SM_WX2 >> 2) + col + 1];
                ps[0] += silu_f(acc[na][0] + b0) * w0
                       + silu_f(acc[na][1] + b1) * w1;
                ps[1] += silu_f(acc[na][2] + b0) * w0
                       + silu_f(acc[na][3] + b1) * w1;
            }
            #pragma unroll
            for (int q = 0; q < 2; q++) {
                ps[q] += __shfl_xor_sync(0xffffffffu, ps[q], 1);
                ps[q] += __shfl_xor_sync(0xffffffffu, ps[q], 2);
            }
            if ((lane & 3) == 0) {
                int base = (warp >> 2) * 64;
                int rA = m0 + (lane >> 2);
                ppart[base + rA]     = ps[0];
                ppart[base + rA + 8] = ps[1];
            }
        }
        __syncthreads();

        if (tid < TILE_M && vreg) {
            float p = ppart[tid] + ppart[64 + tid] + smf[SM_BX2 >> 2];
            atomicAdd(&g_num[dreg*3 + 0], relx * p);
            atomicAdd(&g_num[dreg*3 + 1], rely * p);
            atomicAdd(&g_num[dreg*3 + 2], relz * p);
            atomicAdd(&g_cnt[dreg], 1.0f);
        }
        __syncthreads();
    }
}

// ---------------- scalar GEMM helper for node/precompute ----------------
#define GEMM_4x4(fr, PAD, W, KLEN, acc)                                        \
    _Pragma("unroll 2")                                                        \
    for (int k4 = 0; k4 < (KLEN); k4 += 4) {                                   \
        float4 f0 = *(const float4*)((fr) + 0 * (PAD) + k4);                   \
        float4 f1 = *(const float4*)((fr) + 1 * (PAD) + k4);                   \
        float4 f2 = *(const float4*)((fr) + 2 * (PAD) + k4);                   \
        float4 f3 = *(const float4*)((fr) + 3 * (PAD) + k4);                   \
        _Pragma("unroll")                                                      \
        for (int kk = 0; kk < 4; kk++) {                                       \
            float4 w = *(const float4*)((W) + (k4 + kk) * D + c0);             \
            float e0 = f4get(f0, kk), e1 = f4get(f1, kk);                      \
            float e2 = f4get(f2, kk), e3 = f4get(f3, kk);                      \
            acc[0][0] = fmaf(e0, w.x, acc[0][0]);                              \
            acc[0][1] = fmaf(e0, w.y, acc[0][1]);                              \
            acc[0][2] = fmaf(e0, w.z, acc[0][2]);                              \
            acc[0][3] = fmaf(e0, w.w, acc[0][3]);                              \
            acc[1][0] = fmaf(e1, w.x, acc[1][0]);                              \
            acc[1][1] = fmaf(e1, w.y, acc[1][1]);                              \
            acc[1][2] = fmaf(e1, w.z, acc[1][2]);                              \
            acc[1][3] = fmaf(e1, w.w, acc[1][3]);                              \
            acc[2][0] = fmaf(e2, w.x, acc[2][0]);                              \
            acc[2][1] = fmaf(e2, w.y, acc[2][1]);                              \
            acc[2][2] = fmaf(e2, w.z, acc[2][2]);                              \
            acc[2][3] = fmaf(e2, w.w, acc[2][3]);                              \
            acc[3][0] = fmaf(e3, w.x, acc[3][0]);                              \
            acc[3][1] = fmaf(e3, w.y, acc[3][1]);                              \
            acc[3][2] = fmaf(e3, w.z, acc[3][2]);                              \
            acc[3][3] = fmaf(e3, w.w, acc[3][3]);                              \
        }                                                                      \
    }

__global__ __launch_bounds__(256) void precompute_kernel(
    const float* __restrict__ h, const float* __restrict__ We1,
    const float* __restrict__ be1, int Nn)
{
    __shared__ float fs[NPB * Y_PAD];
    const int warp = threadIdx.x >> 5;
    const int lane = threadIdx.x & 31;
    const int c0   = lane * 4;
    const int nbase = blockIdx.x * NPB;

    int nidx[4]; bool valid[4];
    #pragma unroll
    for (int i = 0; i < 4; i++) {
        int nl = warp * 4 + i;
        int n  = nbase + nl;
        valid[i] = (n < Nn);
        nidx[i] = valid[i] ? n : 0;
        float4 hh = *(const float4*)(h + (size_t)nidx[i] * D + c0);
        *(float4*)(fs + nl * Y_PAD + c0) = hh;
    }
    __syncwarp();

    const float* fr = fs + (warp * 4) * Y_PAD;
    float acc[4][4];
    {
        float4 b = *(const float4*)(be1 + c0);
        #pragma unroll
        for (int i = 0; i < 4; i++) {
            acc[i][0] = b.x; acc[i][1] = b.y; acc[i][2] = b.z; acc[i][3] = b.w;
        }
    }
    GEMM_4x4(fr, Y_PAD, We1, 128, acc)
    #pragma unroll
    for (int i = 0; i < 4; i++)
        if (valid[i])
            *(float4*)(g_U + (size_t)nidx[i] * D + c0) =
                make_float4(acc[i][0], acc[i][1], acc[i][2], acc[i][3]);

    #pragma unroll
    for (int i = 0; i < 4; i++) {
        acc[i][0] = 0.f; acc[i][1] = 0.f; acc[i][2] = 0.f; acc[i][3] = 0.f;
    }
    GEMM_4x4(fr, Y_PAD, We1 + 128 * D, 128, acc)
    #pragma unroll
    for (int i = 0; i < 4; i++)
        if (valid[i])
            *(float4*)(g_V + (size_t)nidx[i] * D + c0) =
                make_float4(acc[i][0], acc[i][1], acc[i][2], acc[i][3]);
}

__global__ __launch_bounds__(256) void node_kernel(
    const float* __restrict__ h, const float* __restrict__ x,
    const float* __restrict__ Wh1, const float* __restrict__ bh1,
    const float* __restrict__ Wh2, const float* __restrict__ bh2,
    const float* __restrict__ gamma, const float* __restrict__ beta,
    float* __restrict__ out_h, float* __restrict__ out_x, int Nn)
{
    __shared__ float fs[NPB * NODE_PAD];
    const int warp = threadIdx.x >> 5;
    const int lane = threadIdx.x & 31;
    const int c0   = lane * 4;
    const int nbase = blockIdx.x * NPB;

    bool valid[4];
    int nidx[4];
    #pragma unroll
    for (int i = 0; i < 4; i++) {
        int nl = warp * 4 + i;
        int n  = nbase + nl;
        valid[i] = (n < Nn);
        int nc = valid[i] ? n : 0;
        nidx[i] = nc;
        float4 hh = *(const float4*)(h + (size_t)nc * D + c0);
        float4 ag = *(const float4*)(g_agg + (size_t)nc * D + c0);
        *(float4*)(fs + nl * NODE_PAD + c0)       = hh;
        *(float4*)(fs + nl * NODE_PAD + 128 + c0) = ag;
    }
    __syncwarp();

    const float* fr = fs + (warp * 4) * NODE_PAD;
    float acc[4][4];
    {
        float4 b = *(const float4*)(bh1 + c0);
        #pragma unroll
        for (int i = 0; i < 4; i++) {
            acc[i][0] = b.x; acc[i][1] = b.y; acc[i][2] = b.z; acc[i][3] = b.w;
        }
    }
    GEMM_4x4(fr, NODE_PAD, Wh1, 256, acc)
    #pragma unroll
    for (int i = 0; i < 4; i++)
        #pragma unroll
        for (int q = 0; q < 4; q++) acc[i][q] = silu_f(acc[i][q]);

    __syncwarp();
    #pragma unroll
    for (int i = 0; i < 4; i++)
        *(float4*)(fs + (warp*4 + i) * NODE_PAD + c0) =
            make_float4(acc[i][0], acc[i][1], acc[i][2], acc[i][3]);
    __syncwarp();

    {
        float4 b = *(const float4*)(bh2 + c0);
        #pragma unroll
        for (int i = 0; i < 4; i++) {
            acc[i][0] = b.x; acc[i][1] = b.y; acc[i][2] = b.z; acc[i][3] = b.w;
        }
    }
    GEMM_4x4(fr, NODE_PAD, Wh2, 128, acc)

    float hn[4][4];
    float mu[4], rstd[4];
    #pragma unroll
    for (int i = 0; i < 4; i++) {
        float4 hh = *(const float4*)(h + (size_t)nidx[i] * D + c0);
        hn[i][0] = hh.x + acc[i][0];
        hn[i][1] = hh.y + acc[i][1];
        hn[i][2] = hh.z + acc[i][2];
        hn[i][3] = hh.w + acc[i][3];
        float s1 = hn[i][0] + hn[i][1] + hn[i][2] + hn[i][3];
        float s2 = hn[i][0]*hn[i][0] + hn[i][1]*hn[i][1]
                 + hn[i][2]*hn[i][2] + hn[i][3]*hn[i][3];
        #pragma unroll
        for (int off = 16; off > 0; off >>= 1) {
            s1 += __shfl_xor_sync(0xffffffffu, s1, off);
            s2 += __shfl_xor_sync(0xffffffffu, s2, off);
        }
        mu[i] = s1 * (1.0f / 128.0f);
        float var = s2 * (1.0f / 128.0f) - mu[i]*mu[i];
        rstd[i] = rsqrtf(var + 1e-5f);
    }
    float4 g = *(const float4*)(gamma + c0);
    float4 b = *(const float4*)(beta + c0);
    #pragma unroll
    for (int i = 0; i < 4; i++) {
        if (valid[i]) {
            float4 o;
            o.x = (hn[i][0] - mu[i]) * rstd[i] * g.x + b.x;
            o.y = (hn[i][1] - mu[i]) * rstd[i] * g.y + b.y;
            o.z = (hn[i][2] - mu[i]) * rstd[i] * g.z + b.z;
            o.w = (hn[i][3] - mu[i]) * rstd[i] * g.w + b.w;
            *(float4*)(out_h + (size_t)nidx[i] * D + c0) = o;
        }
    }
    if (lane == 0) {
        #pragma unroll
        for (int i = 0; i < 4; i++) {
            if (valid[i]) {
                int n = nidx[i];
                float cnt = g_cnt[n];
                float inv = 1.0f / fmaxf(cnt, 1.0f);
                out_x[n*3 + 0] = x[n*3 + 0] + g_num[n*3 + 0] * inv;
                out_x[n*3 + 1] = x[n*3 + 1] + g_num[n*3 + 1] * inv;
                out_x[n*3 + 2] = x[n*3 + 2] + g_num[n*3 + 2] * inv;
            }
        }
    }
}

extern "C" void kernel_launch(void* const* d_in, const int* in_sizes, int n_in,
                              void* d_out, int out_size) {
    const float* h    = (const float*)d_in[0];
    const float* x    = (const float*)d_in[1];
    const float* vel  = (const float*)d_in[2];
    const void*  eidx = d_in[3];
    const float* We1 = (const float*)d_in[4],  *be1 = (const float*)d_in[5];
    const float* We2 = (const float*)d_in[6],  *be2 = (const float*)d_in[7];
    const float* Wx1 = (const float*)d_in[8],  *bx1 = (const float*)d_in[9];
    const float* Wx2 = (const float*)d_in[10], *bx2 = (const float*)d_in[11];
    const float* Wh1 = (const float*)d_in[12], *bh1 = (const float*)d_in[13];
    const float* Wh2 = (const float*)d_in[14], *bh2 = (const float*)d_in[15];
    const float* gamma = (const float*)d_in[16], *beta = (const float*)d_in[17];

    int Nn = in_sizes[0] / D;
    int E  = in_sizes[3] / 2;

    float* out   = (float*)d_out;
    float* out_h = out;
    float* out_x = out + (size_t)Nn * D;
    float* out_m = out_x + (size_t)Nn * 3;

    static int smem_set = 0;
    if (!smem_set) {
        cudaFuncSetAttribute(edge_mma_kernel,
                             cudaFuncAttributeMaxDynamicSharedMemorySize, SM_TOTAL);
        smem_set = 1;
    }

    detect_kernel<<<1, 1>>>(eidx, E, Nn);
    zero_kernel<<<(Nn * D + 255) / 256, 256>>>(Nn);
    prep_weights_kernel<<<(2 * 16384 + 255) / 256, 256>>>(We2, Wx1);
    precompute_kernel<<<(Nn + NPB - 1) / NPB, 256>>>(h, We1, be1, Nn);
    edge_mma_kernel<<<296, 256, SM_TOTAL>>>(x, vel, eidx, We1,
                                            be2, bx1, Wx2, bx2, out_m, E);
    node_kernel<<<(Nn + NPB - 1) / NPB, 256>>>(h, x, Wh1, bh1, Wh2, bh2,
                                               gamma, beta, out_h, out_x, Nn);
}

// round 12
// speedup vs baseline: 1.8499x; 1.0518x over previous
#include <cuda_runtime.h>
#include <cuda_fp16.h>
#include <cstdint>

#define D 128
#define NPB 32
#define Y_PAD 136
#define NODE_PAD 264
#define MAXN 50000
#define TILE_M 64

// ---------------- device scratch (allocation-free rule) ----------------
__device__ float g_agg[MAXN * D];
__device__ float g_num[MAXN * 3];
__device__ float g_cnt[MAXN];
__device__ float g_U[MAXN * D];   // h @ We1[0:128,:] + be1
__device__ float g_V[MAXN * D];   // h @ We1[128:256,:]
__device__ int   g_is64;
// fp16 weight smem-images, XOR-swizzled [n][k] (256B rows): 0 = We2, 1 = Wx1
__device__ unsigned short g_B[2 * 16384];

__device__ __forceinline__ float silu_f(float v) {
    return v * (1.0f / (1.0f + __expf(-v)));
}
__device__ __forceinline__ float f4get(const float4& v, int k) {
    return k == 0 ? v.x : (k == 1 ? v.y : (k == 2 ? v.z : v.w));
}
__device__ __forceinline__ uint32_t smem_u32(const void* p) {
    uint32_t a;
    asm("{ .reg .u64 t; cvta.to.shared.u64 t, %1; cvt.u32.u64 %0, t; }"
        : "=r"(a) : "l"(p));
    return a;
}

#define LDSM_X4(r, addr)                                                        \
    asm volatile("ldmatrix.sync.aligned.m8n8.x4.shared.b16 {%0,%1,%2,%3}, [%4];"\
        : "=r"((r)[0]), "=r"((r)[1]), "=r"((r)[2]), "=r"((r)[3]) : "r"(addr))

#define MMA_F16(d, a, b0, b1)                                                   \
    asm volatile("mma.sync.aligned.m16n8k16.row.col.f32.f16.f16.f32 "           \
        "{%0,%1,%2,%3}, {%4,%5,%6,%7}, {%8,%9}, {%0,%1,%2,%3};"                 \
        : "+f"((d)[0]), "+f"((d)[1]), "+f"((d)[2]), "+f"((d)[3])                \
        : "r"((a)[0]), "r"((a)[1]), "r"((a)[2]), "r"((a)[3]), "r"(b0), "r"(b1))

// exact 2-term fp16 split of a float pair
__device__ __forceinline__ void split2h(float v0, float v1, uint32_t& hi, uint32_t& lo) {
    __half h0 = __float2half_rn(v0), h1 = __float2half_rn(v1);
    float r0 = v0 - __half2float(h0), r1 = v1 - __half2float(h1);
    hi = (uint32_t)__half_as_ushort(h0) | ((uint32_t)__half_as_ushort(h1) << 16);
    lo = (uint32_t)__half_as_ushort(__float2half_rn(r0))
       | ((uint32_t)__half_as_ushort(__float2half_rn(r1)) << 16);
}
__device__ __forceinline__ float hlo16(uint32_t u) {
    return __half2float(__ushort_as_half((unsigned short)(u & 0xffff)));
}
__device__ __forceinline__ float hhi16(uint32_t u) {
    return __half2float(__ushort_as_half((unsigned short)(u >> 16)));
}

// ---------------- misc small kernels ----------------
__global__ void detect_kernel(const void* eidx_raw, int E, int Nn) {
    const long long* p = (const long long*)eidx_raw;
    int ok = 1;
    for (int i = 0; i < 64 && i < E; i++) {
        long long v = p[i];
        if (v < 0 || v >= (long long)Nn) { ok = 0; break; }
    }
    g_is64 = ok;
}
__device__ __forceinline__ int load_idx(const void* eidx_raw, long long pos, int is64) {
    if (is64) return (int)((const long long*)eidx_raw)[pos];
    return ((const int*)eidx_raw)[pos];
}
__global__ void zero_kernel(int n_nodes) {
    int idx = blockIdx.x * blockDim.x + threadIdx.x;
    if (idx < n_nodes * D) g_agg[idx] = 0.f;
    if (idx < n_nodes * 3) g_num[idx] = 0.f;
    if (idx < n_nodes)     g_cnt[idx] = 0.f;
}

// Build fp16 images of We2^T, Wx1^T in swizzled [n][k] layout:
// byte off = n*256 + ((k/8 ^ (n&15))*16) + (k%8)*2
__global__ void prep_weights_kernel(const float* __restrict__ We2,
                                    const float* __restrict__ Wx1) {
    int idx = blockIdx.x * blockDim.x + threadIdx.x;
    if (idx >= 2 * 16384) return;
    int m = idx >> 14;
    int e = idx & 16383;
    int n = e >> 7;
    int k = e & 127;
    const float* W = m ? Wx1 : We2;
    float v = W[k * D + n];
    int off = n * 256 + (((k >> 3) ^ (n & 15)) << 4) + (k & 7) * 2;
    g_B[m * 16384 + (off >> 1)] = __half_as_ushort(__float2half_rn(v));
}

// ---------------- SMEM layout (bytes), TILE_M = 64, 3 CTAs/SM ----------------
// Single rotating weight buffer; WGEO lives in the head of SM_AHI (dead once
// A is stored) and is re-copied each tile.
#define SM_W    0        // 32768 (rotating fp16 weight image)
#define SM_AHI  32768    // 16384 (64 rows x 256B); first 5632B double as WGEO
#define SM_ALO  49152    // 16384
#define SM_GEO  65536    // 64*13 f32 = 3328
#define SM_DST  68864    // 64 int
#define SM_SRC  69120    // 64 int
#define SM_BE2  69376    // 128 f32
#define SM_BX1  69888
#define SM_WX2  70400
#define SM_PPART 70912   // 2*64 f32
#define SM_BX2  71424
#define SM_TOTAL 71440

// 2-chain fp16 GEMM: D[64,128] = (A_hi + A_lo) @ B^T, warp block 16x64.
__device__ __forceinline__ void gemm_tile16(
    uint32_t aHi, uint32_t aLo, uint32_t bB,
    int lane, int m0, int nb, float acc[8][4])
{
    #pragma unroll
    for (int na = 0; na < 8; na++)
        #pragma unroll
        for (int q = 0; q < 4; q++) acc[na][q] = 0.f;

    const int arow_l = lane & 15;
    const int akh    = lane >> 4;
    const int brow_l = ((lane >> 4) & 1) * 8 + (lane & 7);
    const int bkh    = (lane >> 3) & 1;

    #pragma unroll 1
    for (int kb = 0; kb < 8; kb++) {
        uint32_t ah[4], al[4], bh[4][4];
        {
            int row = m0 + arow_l;
            int ch  = kb * 2 + akh;
            uint32_t off = row * 256 + ((ch ^ (row & 15)) << 4);
            LDSM_X4(ah, aHi + off);
            LDSM_X4(al, aLo + off);
        }
        #pragma unroll
        for (int p = 0; p < 4; p++) {
            int row = nb + p * 16 + brow_l;
            int ch  = kb * 2 + bkh;
            uint32_t off = row * 256 + ((ch ^ (row & 15)) << 4);
            LDSM_X4(bh[p], bB + off);
        }
        #pragma unroll
        for (int na = 0; na < 8; na++) {
            uint32_t b0 = bh[na >> 1][(na & 1) * 2];
            uint32_t b1 = bh[na >> 1][(na & 1) * 2 + 1];
            MMA_F16(acc[na], ah, b0, b1);
            MMA_F16(acc[na], al, b0, b1);
        }
    }
}

__global__ __launch_bounds__(256, 3) void edge_mma_kernel(
    const float* __restrict__ x, const float* __restrict__ vel,
    const void* __restrict__ eidx_raw, const float* __restrict__ We1,
    const float* __restrict__ be2, const float* __restrict__ bx1,
    const float* __restrict__ Wx2, const float* __restrict__ bx2,
    float* __restrict__ out_m, int E)
{
    extern __shared__ char smem[];
    float* smf = (float*)smem;
    const uint32_t sb = smem_u32(smem);
    const int tid  = threadIdx.x;
    const int warp = tid >> 5;
    const int lane = tid & 31;
    const int m0   = (warp & 3) * 16;   // GEMM row block (16 rows)
    const int nb   = (warp >> 2) * 64;  // GEMM col block
    const int rw0  = warp * 8;          // scalar phase: warp owns 8 edge rows
    const int c0   = lane * 4;          // scalar phase: lane owns 4 cols
    const int is64 = g_is64;

    // ---- one-time init: biases ----
    if (tid < 128) {
        smf[(SM_BE2 >> 2) + tid] = be2[tid];
        smf[(SM_BX1 >> 2) + tid] = bx1[tid];
        smf[(SM_WX2 >> 2) + tid] = Wx2[tid];
    }
    if (tid == 0) smf[SM_BX2 >> 2] = bx2[0];
    __syncthreads();

    float* geo_sf = smf + (SM_GEO >> 2);
    float* wgeo   = smf + (SM_AHI >> 2);     // WGEO aliases A-buffer head
    int*   dst_s  = (int*)(smem + SM_DST);
    int*   src_s  = (int*)(smem + SM_SRC);
    float* ppart  = smf + (SM_PPART >> 2);
    const uint4* gB = (const uint4*)g_B;

    const int ntiles = (E + TILE_M - 1) / TILE_M;

    for (int tile = blockIdx.x; tile < ntiles; tile += gridDim.x) {
        const int ebase = tile * TILE_M;

        // ===== stage: indices + geometry (tid<64); all: copy WGEO into A head =====
        float relx = 0.f, rely = 0.f, relz = 0.f;
        int dreg = 0; bool vreg = false;
        if (tid < TILE_M) {
            int eg = ebase + tid;
            vreg = (eg < E);
            int ec = vreg ? eg : 0;
            int s = load_idx(eidx_raw, ec, is64);
            int d = load_idx(eidx_raw, (long long)E + ec, is64);
            src_s[tid] = s; dst_s[tid] = d; dreg = d;
            float rx = x[s*3+0] - x[d*3+0];
            float ry = x[s*3+1] - x[d*3+1];
            float rz = x[s*3+2] - x[d*3+2];
            relx = rx; rely = ry; relz = rz;
            float d2 = rx*rx + ry*ry + rz*rz;
            float dist = fmaxf(sqrtf(d2), 1e-8f);
            float inv = 1.0f / dist;
            float ux = rx*inv, uy = ry*inv, uz = rz*inv;
            geo_sf[tid * 13 + 0] = d2;
            #pragma unroll
            for (int j = 0; j < 5; j++) {
                const float* vs = vel + (size_t)s * 15 + j * 3;
                const float* vd = vel + (size_t)d * 15 + j * 3;
                geo_sf[tid * 13 + 1 + j] = vs[0]*ux + vs[1]*uy + vs[2]*uz;
                geo_sf[tid * 13 + 6 + j] = vd[0]*ux + vd[1]*uy + vd[2]*uz;
            }
        }
        // WGEO: 11*128 f32 = 352 float4 from We1 rows 256..266 (L2-hot)
        {
            const float4* src = (const float4*)(We1 + 256 * D);
            float4* dst = (float4*)wgeo;
            for (int i = tid; i < 352; i += 256) dst[i] = src[i];
        }
        __syncthreads();

        // ===== scalar phase (column-mapped, coalesced gathers) =====
        float z[8][4];
        {
            #pragma unroll
            for (int i = 0; i < 8; i++) {
                int s2  = src_s[rw0 + i];
                int d2i = dst_s[rw0 + i];
                float4 u = *(const float4*)(g_U + (size_t)s2 * D + c0);
                float4 v = *(const float4*)(g_V + (size_t)d2i * D + c0);
                z[i][0] = u.x + v.x; z[i][1] = u.y + v.y;
                z[i][2] = u.z + v.z; z[i][3] = u.w + v.w;
            }
            #pragma unroll 1
            for (int k = 0; k < 11; k++) {
                float4 w = *(const float4*)(wgeo + k * D + c0);
                #pragma unroll
                for (int i = 0; i < 8; i++) {
                    float f = geo_sf[(rw0 + i) * 13 + k];   // LDS broadcast
                    z[i][0] = fmaf(f, w.x, z[i][0]);
                    z[i][1] = fmaf(f, w.y, z[i][1]);
                    z[i][2] = fmaf(f, w.z, z[i][2]);
                    z[i][3] = fmaf(f, w.w, z[i][3]);
                }
            }
        }
        __syncthreads();   // all WGEO reads complete before A stores clobber it

        // ===== store A hi/lo; concurrently fill W buffer with We2 image =====
        {
            const int chunk = c0 >> 3;
            const int sub   = (c0 & 7) * 2;
            #pragma unroll
            for (int i = 0; i < 8; i++) {
                int r = rw0 + i;
                float v0 = silu_f(z[i][0]), v1 = silu_f(z[i][1]);
                float v2 = silu_f(z[i][2]), v3 = silu_f(z[i][3]);
                uint32_t h0, l0, h1, l1;
                split2h(v0, v1, h0, l0);
                split2h(v2, v3, h1, l1);
                uint32_t off = r * 256 + ((chunk ^ (r & 15)) << 4) + sub;
                *(uint2*)(smem + SM_AHI + off) = make_uint2(h0, h1);
                *(uint2*)(smem + SM_ALO + off) = make_uint2(l0, l1);
            }
            for (int i = tid; i < 2048; i += 256)
                ((uint4*)(smem + SM_W))[i] = gB[i];          // We2 image
        }
        __syncthreads();

        // ===== GEMM1: y1 @ We2 =====
        float acc[8][4];
        gemm_tile16(sb + SM_AHI, sb + SM_ALO, sb + SM_W, lane, m0, nb, acc);
        __syncthreads();   // A + W reads done block-wide before overwrite

        // epilogue1: m = silu(acc + be2) -> A buffers; fill W with Wx1 image
        #pragma unroll
        for (int na = 0; na < 8; na++) {
            int col = nb + na * 8 + (lane & 3) * 2;
            float b0 = smf[(SM_BE2 >> 2) + col];
            float b1 = smf[(SM_BE2 >> 2) + col + 1];
            int rA = m0 + (lane >> 2);
            int rB = rA + 8;
            float v0 = silu_f(acc[na][0] + b0);
            float v1 = silu_f(acc[na][1] + b1);
            float v2 = silu_f(acc[na][2] + b0);
            float v3 = silu_f(acc[na][3] + b1);
            uint32_t hA, lA, hB, lB;
            split2h(v0, v1, hA, lA);
            split2h(v2, v3, hB, lB);
            uint32_t offA = rA * 256 + (((col >> 3) ^ (rA & 15)) << 4) + (col & 7) * 2;
            uint32_t offB = rB * 256 + (((col >> 3) ^ (rB & 15)) << 4) + (col & 7) * 2;
            *(uint32_t*)(smem + SM_AHI + offA) = hA;
            *(uint32_t*)(smem + SM_ALO + offA) = lA;
            *(uint32_t*)(smem + SM_AHI + offB) = hB;
            *(uint32_t*)(smem + SM_ALO + offB) = lB;
        }
        for (int i = tid; i < 2048; i += 256)
            ((uint4*)(smem + SM_W))[i] = gB[2048 + i];       // Wx1 image
        __syncthreads();

        // ===== GEMM2: m @ Wx1 =====
        gemm_tile16(sb + SM_AHI, sb + SM_ALO, sb + SM_W, lane, m0, nb, acc);

        // out_m + agg atomics from A buffers (m = hi + lo), coalesced
        #pragma unroll 1
        for (int i = 0; i < 8; i++) {
            int row = warp * 8 + i;
            int eg = ebase + row;
            if (eg < E) {
                uint32_t off = row * 256 + ((((lane >> 1) ^ (row & 15))) << 4)
                             + (lane & 1) * 8;
                uint2 uh = *(const uint2*)(smem + SM_AHI + off);
                uint2 ul = *(const uint2*)(smem + SM_ALO + off);
                float4 f;
                f.x = hlo16(uh.x) + hlo16(ul.x);
                f.y = hhi16(uh.x) + hhi16(ul.x);
                f.z = hlo16(uh.y) + hlo16(ul.y);
                f.w = hhi16(uh.y) + hhi16(ul.y);
                *(float4*)(out_m + (size_t)eg * D + lane * 4) = f;
                float* ag = g_agg + (size_t)dst_s[row] * D + lane * 4;
                atomicAdd(ag + 0, f.x);
                atomicAdd(ag + 1, f.y);
                atomicAdd(ag + 2, f.z);
                atomicAdd(ag + 3, f.w);
            }
        }

        // phi_x tail: p_row = sum_col silu(acc2 + bx1)*wx2 (fragment reduce)
        {
            float ps[2] = {0.f, 0.f};
            #pragma unroll
            for (int na = 0; na < 8; na++) {
                int col = nb + na * 8 + (lane & 3) * 2;
                float b0 = smf[(SM_BX1 >> 2) + col];
                float b1 = smf[(SM_BX1 >> 2) + col + 1];
                float w0 = smf[(SM_WX2 >> 2) + col];
                float w1 = smf[(SM_WX2 >> 2) + col + 1];
                ps[0] += silu_f(acc[na][0] + b0) * w0
                       + silu_f(acc[na][1] + b1) * w1;
                ps[1] += silu_f(acc[na][2] + b0) * w0
                       + silu_f(acc[na][3] + b1) * w1;
            }
            #pragma unroll
            for (int q = 0; q < 2; q++) {
                ps[q] += __shfl_xor_sync(0xffffffffu, ps[q], 1);
                ps[q] += __shfl_xor_sync(0xffffffffu, ps[q], 2);
            }
            if ((lane & 3) == 0) {
                int base = (warp >> 2) * 64;
                int rA = m0 + (lane >> 2);
                ppart[base + rA]     = ps[0];
                ppart[base + rA + 8] = ps[1];
            }
        }
        __syncthreads();

        if (tid < TILE_M && vreg) {
            float p = ppart[tid] + ppart[64 + tid] + smf[SM_BX2 >> 2];
            atomicAdd(&g_num[dreg*3 + 0], relx * p);
            atomicAdd(&g_num[dreg*3 + 1], rely * p);
            atomicAdd(&g_num[dreg*3 + 2], relz * p);
            atomicAdd(&g_cnt[dreg], 1.0f);
        }
        __syncthreads();   // before next tile's WGEO copy / geo stage
    }
}

// ---------------- scalar GEMM helper for node/precompute ----------------
#define GEMM_4x4(fr, PAD, W, KLEN, acc)                                        \
    _Pragma("unroll 2")                                                        \
    for (int k4 = 0; k4 < (KLEN); k4 += 4) {                                   \
        float4 f0 = *(const float4*)((fr) + 0 * (PAD) + k4);                   \
        float4 f1 = *(const float4*)((fr) + 1 * (PAD) + k4);                   \
        float4 f2 = *(const float4*)((fr) + 2 * (PAD) + k4);                   \
        float4 f3 = *(const float4*)((fr) + 3 * (PAD) + k4);                   \
        _Pragma("unroll")                                                      \
        for (int kk = 0; kk < 4; kk++) {                                       \
            float4 w = *(const float4*)((W) + (k4 + kk) * D + c0);             \
            float e0 = f4get(f0, kk), e1 = f4get(f1, kk);                      \
            float e2 = f4get(f2, kk), e3 = f4get(f3, kk);                      \
            acc[0][0] = fmaf(e0, w.x, acc[0][0]);                              \
            acc[0][1] = fmaf(e0, w.y, acc[0][1]);                              \
            acc[0][2] = fmaf(e0, w.z, acc[0][2]);                              \
            acc[0][3] = fmaf(e0, w.w, acc[0][3]);                              \
            acc[1][0] = fmaf(e1, w.x, acc[1][0]);                              \
            acc[1][1] = fmaf(e1, w.y, acc[1][1]);                              \
            acc[1][2] = fmaf(e1, w.z, acc[1][2]);                              \
            acc[1][3] = fmaf(e1, w.w, acc[1][3]);                              \
            acc[2][0] = fmaf(e2, w.x, acc[2][0]);                              \
            acc[2][1] = fmaf(e2, w.y, acc[2][1]);                              \
            acc[2][2] = fmaf(e2, w.z, acc[2][2]);                              \
            acc[2][3] = fmaf(e2, w.w, acc[2][3]);                              \
            acc[3][0] = fmaf(e3, w.x, acc[3][0]);                              \
            acc[3][1] = fmaf(e3, w.y, acc[3][1]);                              \
            acc[3][2] = fmaf(e3, w.z, acc[3][2]);                              \
            acc[3][3] = fmaf(e3, w.w, acc[3][3]);                              \
        }                                                                      \
    }

__global__ __launch_bounds__(256) void precompute_kernel(
    const float* __restrict__ h, const float* __restrict__ We1,
    const float* __restrict__ be1, int Nn)
{
    __shared__ float fs[NPB * Y_PAD];
    const int warp = threadIdx.x >> 5;
    const int lane = threadIdx.x & 31;
    const int c0   = lane * 4;
    const int nbase = blockIdx.x * NPB;

    int nidx[4]; bool valid[4];
    #pragma unroll
    for (int i = 0; i < 4; i++) {
        int nl = warp * 4 + i;
        int n  = nbase + nl;
        valid[i] = (n < Nn);
        nidx[i] = valid[i] ? n : 0;
        float4 hh = *(const float4*)(h + (size_t)nidx[i] * D + c0);
        *(float4*)(fs + nl * Y_PAD + c0) = hh;
    }
    __syncwarp();

    const float* fr = fs + (warp * 4) * Y_PAD;
    float acc[4][4];
    {
        float4 b = *(const float4*)(be1 + c0);
        #pragma unroll
        for (int i = 0; i < 4; i++) {
            acc[i][0] = b.x; acc[i][1] = b.y; acc[i][2] = b.z; acc[i][3] = b.w;
        }
    }
    GEMM_4x4(fr, Y_PAD, We1, 128, acc)
    #pragma unroll
    for (int i = 0; i < 4; i++)
        if (valid[i])
            *(float4*)(g_U + (size_t)nidx[i] * D + c0) =
                make_float4(acc[i][0], acc[i][1], acc[i][2], acc[i][3]);

    #pragma unroll
    for (int i = 0; i < 4; i++) {
        acc[i][0] = 0.f; acc[i][1] = 0.f; acc[i][2] = 0.f; acc[i][3] = 0.f;
    }
    GEMM_4x4(fr, Y_PAD, We1 + 128 * D, 128, acc)
    #pragma unroll
    for (int i = 0; i < 4; i++)
        if (valid[i])
            *(float4*)(g_V + (size_t)nidx[i] * D + c0) =
                make_float4(acc[i][0], acc[i][1], acc[i][2], acc[i][3]);
}

__global__ __launch_bounds__(256) void node_kernel(
    const float* __restrict__ h, const float* __restrict__ x,
    const float* __restrict__ Wh1, const float* __restrict__ bh1,
    const float* __restrict__ Wh2, const float* __restrict__ bh2,
    const float* __restrict__ gamma, const float* __restrict__ beta,
    float* __restrict__ out_h, float* __restrict__ out_x, int Nn)
{
    __shared__ float fs[NPB * NODE_PAD];
    const int warp = threadIdx.x >> 5;
    const int lane = threadIdx.x & 31;
    const int c0   = lane * 4;
    const int nbase = blockIdx.x * NPB;

    bool valid[4];
    int nidx[4];
    #pragma unroll
    for (int i = 0; i < 4; i++) {
        int nl = warp * 4 + i;
        int n  = nbase + nl;
        valid[i] = (n < Nn);
        int nc = valid[i] ? n : 0;
        nidx[i] = nc;
        float4 hh = *(const float4*)(h + (size_t)nc * D + c0);
        float4 ag = *(const float4*)(g_agg + (size_t)nc * D + c0);
        *(float4*)(fs + nl * NODE_PAD + c0)       = hh;
        *(float4*)(fs + nl * NODE_PAD + 128 + c0) = ag;
    }
    __syncwarp();

    const float* fr = fs + (warp * 4) * NODE_PAD;
    float acc[4][4];
    {
        float4 b = *(const float4*)(bh1 + c0);
        #pragma unroll
        for (int i = 0; i < 4; i++) {
            acc[i][0] = b.x; acc[i][1] = b.y; acc[i][2] = b.z; acc[i][3] = b.w;
        }
    }
    GEMM_4x4(fr, NODE_PAD, Wh1, 256, acc)
    #pragma unroll
    for (int i = 0; i < 4; i++)
        #pragma unroll
        for (int q = 0; q < 4; q++) acc[i][q] = silu_f(acc[i][q]);

    __syncwarp();
    #pragma unroll
    for (int i = 0; i < 4; i++)
        *(float4*)(fs + (warp*4 + i) * NODE_PAD + c0) =
            make_float4(acc[i][0], acc[i][1], acc[i][2], acc[i][3]);
    __syncwarp();

    {
        float4 b = *(const float4*)(bh2 + c0);
        #pragma unroll
        for (int i = 0; i < 4; i++) {
            acc[i][0] = b.x; acc[i][1] = b.y; acc[i][2] = b.z; acc[i][3] = b.w;
        }
    }
    GEMM_4x4(fr, NODE_PAD, Wh2, 128, acc)

    float hn[4][4];
    float mu[4], rstd[4];
    #pragma unroll
    for (int i = 0; i < 4; i++) {
        float4 hh = *(const float4*)(h + (size_t)nidx[i] * D + c0);
        hn[i][0] = hh.x + acc[i][0];
        hn[i][1] = hh.y + acc[i][1];
        hn[i][2] = hh.z + acc[i][2];
        hn[i][3] = hh.w + acc[i][3];
        float s1 = hn[i][0] + hn[i][1] + hn[i][2] + hn[i][3];
        float s2 = hn[i][0]*hn[i][0] + hn[i][1]*hn[i][1]
                 + hn[i][2]*hn[i][2] + hn[i][3]*hn[i][3];
        #pragma unroll
        for (int off = 16; off > 0; off >>= 1) {
            s1 += __shfl_xor_sync(0xffffffffu, s1, off);
            s2 += __shfl_xor_sync(0xffffffffu, s2, off);
        }
        mu[i] = s1 * (1.0f / 128.0f);
        float var = s2 * (1.0f / 128.0f) - mu[i]*mu[i];
        rstd[i] = rsqrtf(var + 1e-5f);
    }
    float4 g = *(const float4*)(gamma + c0);
    float4 b = *(const float4*)(beta + c0);
    #pragma unroll
    for (int i = 0; i < 4; i++) {
        if (valid[i]) {
            float4 o;
            o.x = (hn[i][0] - mu[i]) * rstd[i] * g.x + b.x;
            o.y = (hn[i][1] - mu[i]) * rstd[i] * g.y + b.y;
            o.z = (hn[i][2] - mu[i]) * rstd[i] * g.z + b.z;
            o.w = (hn[i][3] - mu[i]) * rstd[i] * g.w + b.w;
            *(float4*)(out_h + (size_t)nidx[i] * D + c0) = o;
        }
    }
    if (lane == 0) {
        #pragma unroll
        for (int i = 0; i < 4; i++) {
            if (valid[i]) {
                int n = nidx[i];
                float cnt = g_cnt[n];
                float inv = 1.0f / fmaxf(cnt, 1.0f);
                out_x[n*3 + 0] = x[n*3 + 0] + g_num[n*3 + 0] * inv;
                out_x[n*3 + 1] = x[n*3 + 1] + g_num[n*3 + 1] * inv;
                out_x[n*3 + 2] = x[n*3 + 2] + g_num[n*3 + 2] * inv;
            }
        }
    }
}

extern "C" void kernel_launch(void* const* d_in, const int* in_sizes, int n_in,
                              void* d_out, int out_size) {
    const float* h    = (const float*)d_in[0];
    const float* x    = (const float*)d_in[1];
    const float* vel  = (const float*)d_in[2];
    const void*  eidx = d_in[3];
    const float* We1 = (const float*)d_in[4],  *be1 = (const float*)d_in[5];
    const float* We2 = (const float*)d_in[6],  *be2 = (const float*)d_in[7];
    const float* Wx1 = (const float*)d_in[8],  *bx1 = (const float*)d_in[9];
    const float* Wx2 = (const float*)d_in[10], *bx2 = (const float*)d_in[11];
    const float* Wh1 = (const float*)d_in[12], *bh1 = (const float*)d_in[13];
    const float* Wh2 = (const float*)d_in[14], *bh2 = (const float*)d_in[15];
    const float* gamma = (const float*)d_in[16], *beta = (const float*)d_in[17];

    int Nn = in_sizes[0] / D;
    int E  = in_sizes[3] / 2;

    float* out   = (float*)d_out;
    float* out_h = out;
    float* out_x = out + (size_t)Nn * D;
    float* out_m = out_x + (size_t)Nn * 3;

    static int smem_set = 0;
    if (!smem_set) {
        cudaFuncSetAttribute(edge_mma_kernel,
                             cudaFuncAttributeMaxDynamicSharedMemorySize, SM_TOTAL);
        smem_set = 1;
    }

    detect_kernel<<<1, 1>>>(eidx, E, Nn);
    zero_kernel<<<(Nn * D + 255) / 256, 256>>>(Nn);
    prep_weights_kernel<<<(2 * 16384 + 255) / 256, 256>>>(We2, Wx1);
    precompute_kernel<<<(Nn + NPB - 1) / NPB, 256>>>(h, We1, be1, Nn);
    edge_mma_kernel<<<444, 256, SM_TOTAL>>>(x, vel, eidx, We1,
                                            be2, bx1, Wx2, bx2, out_m, E);
    node_kernel<<<(Nn + NPB - 1) / NPB, 256>>>(h, x, Wh1, bh1, Wh2, bh2,
                                               gamma, beta, out_h, out_x, Nn);
}

// round 13
// speedup vs baseline: 1.9887x; 1.0750x over previous
#include <cuda_runtime.h>
#include <cuda_fp16.h>
#include <cstdint>

#define D 128
#define Y_PAD 136
#define NODE_PAD 264
#define MAXN 50000
#define TILE_M 64

// ---------------- device scratch (allocation-free rule) ----------------
__device__ float g_agg[MAXN * D];
__device__ float g_num[MAXN * 3];
__device__ float g_cnt[MAXN];
__device__ float g_U[MAXN * D];   // h @ We1[0:128,:] + be1
__device__ float g_V[MAXN * D];   // h @ We1[128:256,:]
__device__ int   g_is64;
// fp16 weight smem-images, XOR-swizzled [n][k] (256B rows): 0 = We2, 1 = Wx1
__device__ unsigned short g_B[2 * 16384];

__device__ __forceinline__ float silu_f(float v) {
    return v * (1.0f / (1.0f + __expf(-v)));
}
__device__ __forceinline__ float f4get(const float4& v, int k) {
    return k == 0 ? v.x : (k == 1 ? v.y : (k == 2 ? v.z : v.w));
}
__device__ __forceinline__ uint32_t smem_u32(const void* p) {
    uint32_t a;
    asm("{ .reg .u64 t; cvta.to.shared.u64 t, %1; cvt.u32.u64 %0, t; }"
        : "=r"(a) : "l"(p));
    return a;
}

#define LDSM_X4(r, addr)                                                        \
    asm volatile("ldmatrix.sync.aligned.m8n8.x4.shared.b16 {%0,%1,%2,%3}, [%4];"\
        : "=r"((r)[0]), "=r"((r)[1]), "=r"((r)[2]), "=r"((r)[3]) : "r"(addr))

#define MMA_F16(d, a, b0, b1)                                                   \
    asm volatile("mma.sync.aligned.m16n8k16.row.col.f32.f16.f16.f32 "           \
        "{%0,%1,%2,%3}, {%4,%5,%6,%7}, {%8,%9}, {%0,%1,%2,%3};"                 \
        : "+f"((d)[0]), "+f"((d)[1]), "+f"((d)[2]), "+f"((d)[3])                \
        : "r"((a)[0]), "r"((a)[1]), "r"((a)[2]), "r"((a)[3]), "r"(b0), "r"(b1))

// exact 2-term fp16 split via packed cvt.rn.f16x2.f32 (4 CVT, was 6)
__device__ __forceinline__ void split2h(float v0, float v1, uint32_t& hi, uint32_t& lo) {
    __half2 h = __floats2half2_rn(v0, v1);
    float2 hf = __half22float2(h);
    __half2 l = __floats2half2_rn(v0 - hf.x, v1 - hf.y);
    hi = *reinterpret_cast<uint32_t*>(&h);
    lo = *reinterpret_cast<uint32_t*>(&l);
}
__device__ __forceinline__ float hlo16(uint32_t u) {
    return __half2float(__ushort_as_half((unsigned short)(u & 0xffff)));
}
__device__ __forceinline__ float hhi16(uint32_t u) {
    return __half2float(__ushort_as_half((unsigned short)(u >> 16)));
}

// ---------------- misc small kernels ----------------
__global__ void detect_kernel(const void* eidx_raw, int E, int Nn) {
    const long long* p = (const long long*)eidx_raw;
    int ok = 1;
    for (int i = 0; i < 64 && i < E; i++) {
        long long v = p[i];
        if (v < 0 || v >= (long long)Nn) { ok = 0; break; }
    }
    g_is64 = ok;
}
__device__ __forceinline__ int load_idx(const void* eidx_raw, long long pos, int is64) {
    if (is64) return (int)((const long long*)eidx_raw)[pos];
    return ((const int*)eidx_raw)[pos];
}
__global__ void zero_kernel(int n_nodes) {
    int idx = blockIdx.x * blockDim.x + threadIdx.x;
    if (idx < n_nodes * D) g_agg[idx] = 0.f;
    if (idx < n_nodes * 3) g_num[idx] = 0.f;
    if (idx < n_nodes)     g_cnt[idx] = 0.f;
}

// Build fp16 images of We2^T, Wx1^T in swizzled [n][k] layout:
// byte off = n*256 + ((k/8 ^ (n&15))*16) + (k%8)*2
__global__ void prep_weights_kernel(const float* __restrict__ We2,
                                    const float* __restrict__ Wx1) {
    int idx = blockIdx.x * blockDim.x + threadIdx.x;
    if (idx >= 2 * 16384) return;
    int m = idx >> 14;
    int e = idx & 16383;
    int n = e >> 7;
    int k = e & 127;
    const float* W = m ? Wx1 : We2;
    float v = W[k * D + n];
    int off = n * 256 + (((k >> 3) ^ (n & 15)) << 4) + (k & 7) * 2;
    g_B[m * 16384 + (off >> 1)] = __half_as_ushort(__float2half_rn(v));
}

// ---------------- SMEM layout (bytes), TILE_M = 64, 3 CTAs/SM ----------------
#define SM_W    0        // 32768 (rotating fp16 weight image)
#define SM_AHI  32768    // 16384 (64 rows x 256B); first 5632B double as WGEO
#define SM_ALO  49152    // 16384
#define SM_GEO  65536    // 64*13 f32 = 3328
#define SM_DST  68864    // 64 int
#define SM_SRC  69120    // 64 int
#define SM_BE2  69376    // 128 f32
#define SM_BX1  69888
#define SM_WX2  70400
#define SM_PPART 70912   // 2*64 f32
#define SM_BX2  71424
#define SM_TOTAL 71440

// 2-chain fp16 GEMM: D[64,128] = (A_hi + A_lo) @ B^T, warp block 16x64.
__device__ __forceinline__ void gemm_tile16(
    uint32_t aHi, uint32_t aLo, uint32_t bB,
    int lane, int m0, int nb, float acc[8][4])
{
    #pragma unroll
    for (int na = 0; na < 8; na++)
        #pragma unroll
        for (int q = 0; q < 4; q++) acc[na][q] = 0.f;

    const int arow_l = lane & 15;
    const int akh    = lane >> 4;
    const int brow_l = ((lane >> 4) & 1) * 8 + (lane & 7);
    const int bkh    = (lane >> 3) & 1;

    #pragma unroll 1
    for (int kb = 0; kb < 8; kb++) {
        uint32_t ah[4], al[4], bh[4][4];
        {
            int row = m0 + arow_l;
            int ch  = kb * 2 + akh;
            uint32_t off = row * 256 + ((ch ^ (row & 15)) << 4);
            LDSM_X4(ah, aHi + off);
            LDSM_X4(al, aLo + off);
        }
        #pragma unroll
        for (int p = 0; p < 4; p++) {
            int row = nb + p * 16 + brow_l;
            int ch  = kb * 2 + bkh;
            uint32_t off = row * 256 + ((ch ^ (row & 15)) << 4);
            LDSM_X4(bh[p], bB + off);
        }
        #pragma unroll
        for (int na = 0; na < 8; na++) {
            uint32_t b0 = bh[na >> 1][(na & 1) * 2];
            uint32_t b1 = bh[na >> 1][(na & 1) * 2 + 1];
            MMA_F16(acc[na], ah, b0, b1);
            MMA_F16(acc[na], al, b0, b1);
        }
    }
}

// 1-chain variant (A_hi only) — used for GEMM2, whose output only feeds the
// phi_x scalar; fp16 rounding there adds ~1e-4 relative error.
__device__ __forceinline__ void gemm_tile16_1c(
    uint32_t aHi, uint32_t bB,
    int lane, int m0, int nb, float acc[8][4])
{
    #pragma unroll
    for (int na = 0; na < 8; na++)
        #pragma unroll
        for (int q = 0; q < 4; q++) acc[na][q] = 0.f;

    const int arow_l = lane & 15;
    const int akh    = lane >> 4;
    const int brow_l = ((lane >> 4) & 1) * 8 + (lane & 7);
    const int bkh    = (lane >> 3) & 1;

    #pragma unroll 1
    for (int kb = 0; kb < 8; kb++) {
        uint32_t ah[4], bh[4][4];
        {
            int row = m0 + arow_l;
            int ch  = kb * 2 + akh;
            uint32_t off = row * 256 + ((ch ^ (row & 15)) << 4);
            LDSM_X4(ah, aHi + off);
        }
        #pragma unroll
        for (int p = 0; p < 4; p++) {
            int row = nb + p * 16 + brow_l;
            int ch  = kb * 2 + bkh;
            uint32_t off = row * 256 + ((ch ^ (row & 15)) << 4);
            LDSM_X4(bh[p], bB + off);
        }
        #pragma unroll
        for (int na = 0; na < 8; na++) {
            uint32_t b0 = bh[na >> 1][(na & 1) * 2];
            uint32_t b1 = bh[na >> 1][(na & 1) * 2 + 1];
            MMA_F16(acc[na], ah, b0, b1);
        }
    }
}

__global__ __launch_bounds__(256, 3) void edge_mma_kernel(
    const float* __restrict__ x, const float* __restrict__ vel,
    const void* __restrict__ eidx_raw, const float* __restrict__ We1,
    const float* __restrict__ be2, const float* __restrict__ bx1,
    const float* __restrict__ Wx2, const float* __restrict__ bx2,
    float* __restrict__ out_m, int E)
{
    extern __shared__ char smem[];
    float* smf = (float*)smem;
    const uint32_t sb = smem_u32(smem);
    const int tid  = threadIdx.x;
    const int warp = tid >> 5;
    const int lane = tid & 31;
    const int m0   = (warp & 3) * 16;   // GEMM row block (16 rows)
    const int nb   = (warp >> 2) * 64;  // GEMM col block
    const int rw0  = warp * 8;          // scalar phase: warp owns 8 edge rows
    const int c0   = lane * 4;          // scalar phase: lane owns 4 cols
    const int is64 = g_is64;

    // ---- one-time init: biases ----
    if (tid < 128) {
        smf[(SM_BE2 >> 2) + tid] = be2[tid];
        smf[(SM_BX1 >> 2) + tid] = bx1[tid];
        smf[(SM_WX2 >> 2) + tid] = Wx2[tid];
    }
    if (tid == 0) smf[SM_BX2 >> 2] = bx2[0];
    __syncthreads();

    float* geo_sf = smf + (SM_GEO >> 2);
    float* wgeo   = smf + (SM_AHI >> 2);     // WGEO aliases A-buffer head
    int*   dst_s  = (int*)(smem + SM_DST);
    int*   src_s  = (int*)(smem + SM_SRC);
    float* ppart  = smf + (SM_PPART >> 2);
    const uint4* gB = (const uint4*)g_B;

    const int ntiles = (E + TILE_M - 1) / TILE_M;

    for (int tile = blockIdx.x; tile < ntiles; tile += gridDim.x) {
        const int ebase = tile * TILE_M;

        // ===== stage: indices + geometry (tid<64); all: copy WGEO into A head =====
        float relx = 0.f, rely = 0.f, relz = 0.f;
        int dreg = 0; bool vreg = false;
        if (tid < TILE_M) {
            int eg = ebase + tid;
            vreg = (eg < E);
            int ec = vreg ? eg : 0;
            int s = load_idx(eidx_raw, ec, is64);
            int d = load_idx(eidx_raw, (long long)E + ec, is64);
            src_s[tid] = s; dst_s[tid] = d; dreg = d;
            float rx = x[s*3+0] - x[d*3+0];
            float ry = x[s*3+1] - x[d*3+1];
            float rz = x[s*3+2] - x[d*3+2];
            relx = rx; rely = ry; relz = rz;
            float d2 = rx*rx + ry*ry + rz*rz;
            float dist = fmaxf(sqrtf(d2), 1e-8f);
            float inv = 1.0f / dist;
            float ux = rx*inv, uy = ry*inv, uz = rz*inv;
            geo_sf[tid * 13 + 0] = d2;
            #pragma unroll
            for (int j = 0; j < 5; j++) {
                const float* vs = vel + (size_t)s * 15 + j * 3;
                const float* vd = vel + (size_t)d * 15 + j * 3;
                geo_sf[tid * 13 + 1 + j] = vs[0]*ux + vs[1]*uy + vs[2]*uz;
                geo_sf[tid * 13 + 6 + j] = vd[0]*ux + vd[1]*uy + vd[2]*uz;
            }
        }
        // WGEO: 11*128 f32 = 352 float4 from We1 rows 256..266 (L2-hot)
        {
            const float4* src = (const float4*)(We1 + 256 * D);
            float4* dst = (float4*)wgeo;
            for (int i = tid; i < 352; i += 256) dst[i] = src[i];
        }
        __syncthreads();

        // ===== scalar phase (column-mapped, coalesced gathers) =====
        float z[8][4];
        {
            #pragma unroll
            for (int i = 0; i < 8; i++) {
                int s2  = src_s[rw0 + i];
                int d2i = dst_s[rw0 + i];
                float4 u = *(const float4*)(g_U + (size_t)s2 * D + c0);
                float4 v = *(const float4*)(g_V + (size_t)d2i * D + c0);
                z[i][0] = u.x + v.x; z[i][1] = u.y + v.y;
                z[i][2] = u.z + v.z; z[i][3] = u.w + v.w;
            }
            #pragma unroll 1
            for (int k = 0; k < 11; k++) {
                float4 w = *(const float4*)(wgeo + k * D + c0);
                #pragma unroll
                for (int i = 0; i < 8; i++) {
                    float f = geo_sf[(rw0 + i) * 13 + k];   // LDS broadcast
                    z[i][0] = fmaf(f, w.x, z[i][0]);
                    z[i][1] = fmaf(f, w.y, z[i][1]);
                    z[i][2] = fmaf(f, w.z, z[i][2]);
                    z[i][3] = fmaf(f, w.w, z[i][3]);
                }
            }
        }
        __syncthreads();   // all WGEO reads complete before A stores clobber it

        // ===== store A hi/lo; concurrently fill W buffer with We2 image =====
        {
            const int chunk = c0 >> 3;
            const int sub   = (c0 & 7) * 2;
            #pragma unroll
            for (int i = 0; i < 8; i++) {
                int r = rw0 + i;
                float v0 = silu_f(z[i][0]), v1 = silu_f(z[i][1]);
                float v2 = silu_f(z[i][2]), v3 = silu_f(z[i][3]);
                uint32_t h0, l0, h1, l1;
                split2h(v0, v1, h0, l0);
                split2h(v2, v3, h1, l1);
                uint32_t off = r * 256 + ((chunk ^ (r & 15)) << 4) + sub;
                *(uint2*)(smem + SM_AHI + off) = make_uint2(h0, h1);
                *(uint2*)(smem + SM_ALO + off) = make_uint2(l0, l1);
            }
            for (int i = tid; i < 2048; i += 256)
                ((uint4*)(smem + SM_W))[i] = gB[i];          // We2 image
        }
        __syncthreads();

        // ===== GEMM1: y1 @ We2 (2-chain, exact split) =====
        float acc[8][4];
        gemm_tile16(sb + SM_AHI, sb + SM_ALO, sb + SM_W, lane, m0, nb, acc);
        __syncthreads();   // A + W reads done block-wide before overwrite

        // epilogue1: m = silu(acc + be2) -> A buffers; fill W with Wx1 image
        #pragma unroll
        for (int na = 0; na < 8; na++) {
            int col = nb + na * 8 + (lane & 3) * 2;
            float b0 = smf[(SM_BE2 >> 2) + col];
            float b1 = smf[(SM_BE2 >> 2) + col + 1];
            int rA = m0 + (lane >> 2);
            int rB = rA + 8;
            float v0 = silu_f(acc[na][0] + b0);
            float v1 = silu_f(acc[na][1] + b1);
            float v2 = silu_f(acc[na][2] + b0);
            float v3 = silu_f(acc[na][3] + b1);
            uint32_t hA, lA, hB, lB;
            split2h(v0, v1, hA, lA);
            split2h(v2, v3, hB, lB);
            uint32_t offA = rA * 256 + (((col >> 3) ^ (rA & 15)) << 4) + (col & 7) * 2;
            uint32_t offB = rB * 256 + (((col >> 3) ^ (rB & 15)) << 4) + (col & 7) * 2;
            *(uint32_t*)(smem + SM_AHI + offA) = hA;
            *(uint32_t*)(smem + SM_ALO + offA) = lA;
            *(uint32_t*)(smem + SM_AHI + offB) = hB;
            *(uint32_t*)(smem + SM_ALO + offB) = lB;
        }
        for (int i = tid; i < 2048; i += 256)
            ((uint4*)(smem + SM_W))[i] = gB[2048 + i];       // Wx1 image
        __syncthreads();

        // ===== GEMM2: m @ Wx1 (1-chain; output feeds phi_x scalar only) =====
        gemm_tile16_1c(sb + SM_AHI, sb + SM_W, lane, m0, nb, acc);

        // out_m + agg atomics from A buffers (m = hi + lo), coalesced
        #pragma unroll 1
        for (int i = 0; i < 8; i++) {
            int row = warp * 8 + i;
            int eg = ebase + row;
            if (eg < E) {
                uint32_t off = row * 256 + ((((lane >> 1) ^ (row & 15))) << 4)
                             + (lane & 1) * 8;
                uint2 uh = *(const uint2*)(smem + SM_AHI + off);
                uint2 ul = *(const uint2*)(smem + SM_ALO + off);
                float4 f;
                f.x = hlo16(uh.x) + hlo16(ul.x);
                f.y = hhi16(uh.x) + hhi16(ul.x);
                f.z = hlo16(uh.y) + hlo16(ul.y);
                f.w = hhi16(uh.y) + hhi16(ul.y);
                *(float4*)(out_m + (size_t)eg * D + lane * 4) = f;
                float* ag = g_agg + (size_t)dst_s[row] * D + lane * 4;
                atomicAdd(ag + 0, f.x);
                atomicAdd(ag + 1, f.y);
                atomicAdd(ag + 2, f.z);
                atomicAdd(ag + 3, f.w);
            }
        }

        // phi_x tail: p_row = sum_col silu(acc2 + bx1)*wx2 (fragment reduce)
        {
            float ps[2] = {0.f, 0.f};
            #pragma unroll
            for (int na = 0; na < 8; na++) {
                int col = nb + na * 8 + (lane & 3) * 2;
                float b0 = smf[(SM_BX1 >> 2) + col];
                float b1 = smf[(SM_BX1 >> 2) + col + 1];
                float w0 = smf[(SM_WX2 >> 2) + col];
                float w1 = smf[(SM_WX2 >> 2) + col + 1];
                ps[0] += silu_f(acc[na][0] + b0) * w0
                       + silu_f(acc[na][1] + b1) * w1;
                ps[1] += silu_f(acc[na][2] + b0) * w0
                       + silu_f(acc[na][3] + b1) * w1;
            }
            #pragma unroll
            for (int q = 0; q < 2; q++) {
                ps[q] += __shfl_xor_sync(0xffffffffu, ps[q], 1);
                ps[q] += __shfl_xor_sync(0xffffffffu, ps[q], 2);
            }
            if ((lane & 3) == 0) {
                int base = (warp >> 2) * 64;
                int rA = m0 + (lane >> 2);
                ppart[base + rA]     = ps[0];
                ppart[base + rA + 8] = ps[1];
            }
        }
        __syncthreads();

        if (tid < TILE_M && vreg) {
            float p = ppart[tid] + ppart[64 + tid] + smf[SM_BX2 >> 2];
            atomicAdd(&g_num[dreg*3 + 0], relx * p);
            atomicAdd(&g_num[dreg*3 + 1], rely * p);
            atomicAdd(&g_num[dreg*3 + 2], relz * p);
            atomicAdd(&g_cnt[dreg], 1.0f);
        }
        __syncthreads();   // before next tile's WGEO copy / geo stage
    }
}

// ---------------- scalar GEMM helper: 8 rows x 4 cols per thread ----------------
// One LDG.128 weight row now feeds 32 FMAs (was 16) -> halves L1 pressure.
#define GEMM_8x4(fr, PAD, W, KLEN, acc)                                        \
    _Pragma("unroll 1")                                                        \
    for (int k4 = 0; k4 < (KLEN); k4 += 4) {                                   \
        float4 f[8];                                                           \
        _Pragma("unroll")                                                      \
        for (int i = 0; i < 8; i++)                                            \
            f[i] = *(const float4*)((fr) + i * (PAD) + k4);                    \
        _Pragma("unroll")                                                      \
        for (int kk = 0; kk < 4; kk++) {                                       \
            float4 w = *(const float4*)((W) + (k4 + kk) * D + c0);             \
            _Pragma("unroll")                                                  \
            for (int i = 0; i < 8; i++) {                                      \
                float e = f4get(f[i], kk);                                     \
                acc[i][0] = fmaf(e, w.x, acc[i][0]);                           \
                acc[i][1] = fmaf(e, w.y, acc[i][1]);                           \
                acc[i][2] = fmaf(e, w.z, acc[i][2]);                           \
                acc[i][3] = fmaf(e, w.w, acc[i][3]);                           \
            }                                                                  \
        }                                                                      \
    }

// Per-node precompute: 128 threads, 4 warps x 8 nodes.
__global__ __launch_bounds__(128) void precompute_kernel(
    const float* __restrict__ h, const float* __restrict__ We1,
    const float* __restrict__ be1, int Nn)
{
    __shared__ float fs[32 * Y_PAD];
    const int warp = threadIdx.x >> 5;
    const int lane = threadIdx.x & 31;
    const int c0   = lane * 4;
    const int nbase = blockIdx.x * 32;

    int nidx[8]; bool valid[8];
    #pragma unroll
    for (int i = 0; i < 8; i++) {
        int nl = warp * 8 + i;
        int n  = nbase + nl;
        valid[i] = (n < Nn);
        nidx[i] = valid[i] ? n : 0;
        float4 hh = *(const float4*)(h + (size_t)nidx[i] * D + c0);
        *(float4*)(fs + nl * Y_PAD + c0) = hh;
    }
    __syncwarp();

    const float* fr = fs + (warp * 8) * Y_PAD;
    float acc[8][4];
    {
        float4 b = *(const float4*)(be1 + c0);
        #pragma unroll
        for (int i = 0; i < 8; i++) {
            acc[i][0] = b.x; acc[i][1] = b.y; acc[i][2] = b.z; acc[i][3] = b.w;
        }
    }
    GEMM_8x4(fr, Y_PAD, We1, 128, acc)
    #pragma unroll
    for (int i = 0; i < 8; i++)
        if (valid[i])
            *(float4*)(g_U + (size_t)nidx[i] * D + c0) =
                make_float4(acc[i][0], acc[i][1], acc[i][2], acc[i][3]);

    #pragma unroll
    for (int i = 0; i < 8; i++) {
        acc[i][0] = 0.f; acc[i][1] = 0.f; acc[i][2] = 0.f; acc[i][3] = 0.f;
    }
    GEMM_8x4(fr, Y_PAD, We1 + 128 * D, 128, acc)
    #pragma unroll
    for (int i = 0; i < 8; i++)
        if (valid[i])
            *(float4*)(g_V + (size_t)nidx[i] * D + c0) =
                make_float4(acc[i][0], acc[i][1], acc[i][2], acc[i][3]);
}

// Node kernel: 128 threads, 4 warps x 8 nodes.
__global__ __launch_bounds__(128) void node_kernel(
    const float* __restrict__ h, const float* __restrict__ x,
    const float* __restrict__ Wh1, const float* __restrict__ bh1,
    const float* __restrict__ Wh2, const float* __restrict__ bh2,
    const float* __restrict__ gamma, const float* __restrict__ beta,
    float* __restrict__ out_h, float* __restrict__ out_x, int Nn)
{
    __shared__ float fs[32 * NODE_PAD];
    const int warp = threadIdx.x >> 5;
    const int lane = threadIdx.x & 31;
    const int c0   = lane * 4;
    const int nbase = blockIdx.x * 32;

    bool valid[8];
    int nidx[8];
    #pragma unroll
    for (int i = 0; i < 8; i++) {
        int nl = warp * 8 + i;
        int n  = nbase + nl;
        valid[i] = (n < Nn);
        int nc = valid[i] ? n : 0;
        nidx[i] = nc;
        float4 hh = *(const float4*)(h + (size_t)nc * D + c0);
        float4 ag = *(const float4*)(g_agg + (size_t)nc * D + c0);
        *(float4*)(fs + nl * NODE_PAD + c0)       = hh;
        *(float4*)(fs + nl * NODE_PAD + 128 + c0) = ag;
    }
    __syncwarp();

    const float* fr = fs + (warp * 8) * NODE_PAD;
    float acc[8][4];
    {
        float4 b = *(const float4*)(bh1 + c0);
        #pragma unroll
        for (int i = 0; i < 8; i++) {
            acc[i][0] = b.x; acc[i][1] = b.y; acc[i][2] = b.z; acc[i][3] = b.w;
        }
    }
    GEMM_8x4(fr, NODE_PAD, Wh1, 256, acc)
    #pragma unroll
    for (int i = 0; i < 8; i++)
        #pragma unroll
        for (int q = 0; q < 4; q++) acc[i][q] = silu_f(acc[i][q]);

    __syncwarp();   // warp owns its 8 rows exclusively
    #pragma unroll
    for (int i = 0; i < 8; i++)
        *(float4*)(fs + (warp*8 + i) * NODE_PAD + c0) =
            make_float4(acc[i][0], acc[i][1], acc[i][2], acc[i][3]);
    __syncwarp();

    {
        float4 b = *(const float4*)(bh2 + c0);
        #pragma unroll
        for (int i = 0; i < 8; i++) {
            acc[i][0] = b.x; acc[i][1] = b.y; acc[i][2] = b.z; acc[i][3] = b.w;
        }
    }
    GEMM_8x4(fr, NODE_PAD, Wh2, 128, acc)

    float4 g = *(const float4*)(gamma + c0);
    float4 b = *(const float4*)(beta + c0);
    #pragma unroll
    for (int i = 0; i < 8; i++) {
        float4 hh = *(const float4*)(h + (size_t)nidx[i] * D + c0);
        float h0 = hh.x + acc[i][0];
        float h1 = hh.y + acc[i][1];
        float h2 = hh.z + acc[i][2];
        float h3 = hh.w + acc[i][3];
        float s1 = h0 + h1 + h2 + h3;
        float s2 = h0*h0 + h1*h1 + h2*h2 + h3*h3;
        #pragma unroll
        for (int off = 16; off > 0; off >>= 1) {
            s1 += __shfl_xor_sync(0xffffffffu, s1, off);
            s2 += __shfl_xor_sync(0xffffffffu, s2, off);
        }
        float mu = s1 * (1.0f / 128.0f);
        float var = s2 * (1.0f / 128.0f) - mu*mu;
        float rstd = rsqrtf(var + 1e-5f);
        if (valid[i]) {
            float4 o;
            o.x = (h0 - mu) * rstd * g.x + b.x;
            o.y = (h1 - mu) * rstd * g.y + b.y;
            o.z = (h2 - mu) * rstd * g.z + b.z;
            o.w = (h3 - mu) * rstd * g.w + b.w;
            *(float4*)(out_h + (size_t)nidx[i] * D + c0) = o;
        }
    }

    if (lane == 0) {
        #pragma unroll
        for (int i = 0; i < 8; i++) {
            if (valid[i]) {
                int n = nidx[i];
                float cnt = g_cnt[n];
                float inv = 1.0f / fmaxf(cnt, 1.0f);
                out_x[n*3 + 0] = x[n*3 + 0] + g_num[n*3 + 0] * inv;
                out_x[n*3 + 1] = x[n*3 + 1] + g_num[n*3 + 1] * inv;
                out_x[n*3 + 2] = x[n*3 + 2] + g_num[n*3 + 2] * inv;
            }
        }
    }
}

extern "C" void kernel_launch(void* const* d_in, const int* in_sizes, int n_in,
                              void* d_out, int out_size) {
    const float* h    = (const float*)d_in[0];
    const float* x    = (const float*)d_in[1];
    const float* vel  = (const float*)d_in[2];
    const void*  eidx = d_in[3];
    const float* We1 = (const float*)d_in[4],  *be1 = (const float*)d_in[5];
    const float* We2 = (const float*)d_in[6],  *be2 = (const float*)d_in[7];
    const float* Wx1 = (const float*)d_in[8],  *bx1 = (const float*)d_in[9];
    const float* Wx2 = (const float*)d_in[10], *bx2 = (const float*)d_in[11];
    const float* Wh1 = (const float*)d_in[12], *bh1 = (const float*)d_in[13];
    const float* Wh2 = (const float*)d_in[14], *bh2 = (const float*)d_in[15];
    const float* gamma = (const float*)d_in[16], *beta = (const float*)d_in[17];

    int Nn = in_sizes[0] / D;
    int E  = in_sizes[3] / 2;

    float* out   = (float*)d_out;
    float* out_h = out;
    float* out_x = out + (size_t)Nn * D;
    float* out_m = out_x + (size_t)Nn * 3;

    static int smem_set = 0;
    if (!smem_set) {
        cudaFuncSetAttribute(edge_mma_kernel,
                             cudaFuncAttributeMaxDynamicSharedMemorySize, SM_TOTAL);
        smem_set = 1;
    }

    detect_kernel<<<1, 1>>>(eidx, E, Nn);
    zero_kernel<<<(Nn * D + 255) / 256, 256>>>(Nn);
    prep_weights_kernel<<<(2 * 16384 + 255) / 256, 256>>>(We2, Wx1);
    precompute_kernel<<<(Nn + 31) / 32, 128>>>(h, We1, be1, Nn);
    edge_mma_kernel<<<444, 256, SM_TOTAL>>>(x, vel, eidx, We1,
                                            be2, bx1, Wx2, bx2, out_m, E);
    node_kernel<<<(Nn + 31) / 32, 128>>>(h, x, Wh1, bh1, Wh2, bh2,
                                         gamma, beta, out_h, out_x, Nn);
}

// round 14
// speedup vs baseline: 2.1789x; 1.0957x over previous
#include <cuda_runtime.h>
#include <cuda_fp16.h>
#include <cstdint>

#define D 128
#define Y_PAD 136
#define NODE_PAD 264
#define MAXN 50000
#define TILE_M 64

// ---------------- device scratch (allocation-free rule) ----------------
__device__ float g_agg[MAXN * D];
__device__ float g_num[MAXN * 3];
__device__ float g_cnt[MAXN];
__device__ float g_U[MAXN * D];   // h @ We1[0:128,:] + be1
__device__ float g_V[MAXN * D];   // h @ We1[128:256,:]
__device__ int   g_is64;
// fp16 weight smem-images, XOR-swizzled [n][k] (256B rows): 0 = We2, 1 = Wx1
__device__ unsigned short g_B[2 * 16384];

__device__ __forceinline__ float silu_f(float v) {
    return v * (1.0f / (1.0f + __expf(-v)));
}
__device__ __forceinline__ float f4get(const float4& v, int k) {
    return k == 0 ? v.x : (k == 1 ? v.y : (k == 2 ? v.z : v.w));
}
__device__ __forceinline__ uint32_t smem_u32(const void* p) {
    uint32_t a;
    asm("{ .reg .u64 t; cvta.to.shared.u64 t, %1; cvt.u32.u64 %0, t; }"
        : "=r"(a) : "l"(p));
    return a;
}

// vectorized reduction: one RED.E.ADD.F32x4 instead of 4 scalar REDs (sm_90+)
__device__ __forceinline__ void red_add_f4(float* ptr, float4 v) {
    asm volatile("red.global.add.v4.f32 [%0], {%1, %2, %3, %4};"
                 :: "l"(ptr), "f"(v.x), "f"(v.y), "f"(v.z), "f"(v.w)
                 : "memory");
}

#define LDSM_X4(r, addr)                                                        \
    asm volatile("ldmatrix.sync.aligned.m8n8.x4.shared.b16 {%0,%1,%2,%3}, [%4];"\
        : "=r"((r)[0]), "=r"((r)[1]), "=r"((r)[2]), "=r"((r)[3]) : "r"(addr))

#define MMA_F16(d, a, b0, b1)                                                   \
    asm volatile("mma.sync.aligned.m16n8k16.row.col.f32.f16.f16.f32 "           \
        "{%0,%1,%2,%3}, {%4,%5,%6,%7}, {%8,%9}, {%0,%1,%2,%3};"                 \
        : "+f"((d)[0]), "+f"((d)[1]), "+f"((d)[2]), "+f"((d)[3])                \
        : "r"((a)[0]), "r"((a)[1]), "r"((a)[2]), "r"((a)[3]), "r"(b0), "r"(b1))

// exact 2-term fp16 split via packed cvt.rn.f16x2.f32
__device__ __forceinline__ void split2h(float v0, float v1, uint32_t& hi, uint32_t& lo) {
    __half2 h = __floats2half2_rn(v0, v1);
    float2 hf = __half22float2(h);
    __half2 l = __floats2half2_rn(v0 - hf.x, v1 - hf.y);
    hi = *reinterpret_cast<uint32_t*>(&h);
    lo = *reinterpret_cast<uint32_t*>(&l);
}
__device__ __forceinline__ float hlo16(uint32_t u) {
    return __half2float(__ushort_as_half((unsigned short)(u & 0xffff)));
}
__device__ __forceinline__ float hhi16(uint32_t u) {
    return __half2float(__ushort_as_half((unsigned short)(u >> 16)));
}

// ---------------- misc small kernels ----------------
__global__ void detect_kernel(const void* eidx_raw, int E, int Nn) {
    const long long* p = (const long long*)eidx_raw;
    int ok = 1;
    for (int i = 0; i < 64 && i < E; i++) {
        long long v = p[i];
        if (v < 0 || v >= (long long)Nn) { ok = 0; break; }
    }
    g_is64 = ok;
}
__device__ __forceinline__ int load_idx(const void* eidx_raw, long long pos, int is64) {
    if (is64) return (int)((const long long*)eidx_raw)[pos];
    return ((const int*)eidx_raw)[pos];
}
__global__ void zero_kernel(int n_nodes) {
    int idx = blockIdx.x * blockDim.x + threadIdx.x;
    if (idx < n_nodes * D) g_agg[idx] = 0.f;
    if (idx < n_nodes * 3) g_num[idx] = 0.f;
    if (idx < n_nodes)     g_cnt[idx] = 0.f;
}

// Build fp16 images of We2^T, Wx1^T in swizzled [n][k] layout:
// byte off = n*256 + ((k/8 ^ (n&15))*16) + (k%8)*2
__global__ void prep_weights_kernel(const float* __restrict__ We2,
                                    const float* __restrict__ Wx1) {
    int idx = blockIdx.x * blockDim.x + threadIdx.x;
    if (idx >= 2 * 16384) return;
    int m = idx >> 14;
    int e = idx & 16383;
    int n = e >> 7;
    int k = e & 127;
    const float* W = m ? Wx1 : We2;
    float v = W[k * D + n];
    int off = n * 256 + (((k >> 3) ^ (n & 15)) << 4) + (k & 7) * 2;
    g_B[m * 16384 + (off >> 1)] = __half_as_ushort(__float2half_rn(v));
}

// ---------------- SMEM layout (bytes), TILE_M = 64, 3 CTAs/SM ----------------
#define SM_W    0        // 32768 (rotating fp16 weight image)
#define SM_AHI  32768    // 16384 (64 rows x 256B); first 5632B double as WGEO
#define SM_ALO  49152    // 16384
#define SM_GEO  65536    // 64*13 f32 = 3328
#define SM_DST  68864    // 64 int
#define SM_SRC  69120    // 64 int
#define SM_BE2  69376    // 128 f32
#define SM_BX1  69888
#define SM_WX2  70400
#define SM_PPART 70912   // 2*64 f32
#define SM_BX2  71424
#define SM_TOTAL 71440

// 2-chain fp16 GEMM: D[64,128] = (A_hi + A_lo) @ B^T, warp block 16x64.
__device__ __forceinline__ void gemm_tile16(
    uint32_t aHi, uint32_t aLo, uint32_t bB,
    int lane, int m0, int nb, float acc[8][4])
{
    #pragma unroll
    for (int na = 0; na < 8; na++)
        #pragma unroll
        for (int q = 0; q < 4; q++) acc[na][q] = 0.f;

    const int arow_l = lane & 15;
    const int akh    = lane >> 4;
    const int brow_l = ((lane >> 4) & 1) * 8 + (lane & 7);
    const int bkh    = (lane >> 3) & 1;

    #pragma unroll 1
    for (int kb = 0; kb < 8; kb++) {
        uint32_t ah[4], al[4], bh[4][4];
        {
            int row = m0 + arow_l;
            int ch  = kb * 2 + akh;
            uint32_t off = row * 256 + ((ch ^ (row & 15)) << 4);
            LDSM_X4(ah, aHi + off);
            LDSM_X4(al, aLo + off);
        }
        #pragma unroll
        for (int p = 0; p < 4; p++) {
            int row = nb + p * 16 + brow_l;
            int ch  = kb * 2 + bkh;
            uint32_t off = row * 256 + ((ch ^ (row & 15)) << 4);
            LDSM_X4(bh[p], bB + off);
        }
        #pragma unroll
        for (int na = 0; na < 8; na++) {
            uint32_t b0 = bh[na >> 1][(na & 1) * 2];
            uint32_t b1 = bh[na >> 1][(na & 1) * 2 + 1];
            MMA_F16(acc[na], ah, b0, b1);
            MMA_F16(acc[na], al, b0, b1);
        }
    }
}

// 1-chain variant (A_hi only) — GEMM2 output only feeds the phi_x scalar.
__device__ __forceinline__ void gemm_tile16_1c(
    uint32_t aHi, uint32_t bB,
    int lane, int m0, int nb, float acc[8][4])
{
    #pragma unroll
    for (int na = 0; na < 8; na++)
        #pragma unroll
        for (int q = 0; q < 4; q++) acc[na][q] = 0.f;

    const int arow_l = lane & 15;
    const int akh    = lane >> 4;
    const int brow_l = ((lane >> 4) & 1) * 8 + (lane & 7);
    const int bkh    = (lane >> 3) & 1;

    #pragma unroll 1
    for (int kb = 0; kb < 8; kb++) {
        uint32_t ah[4], bh[4][4];
        {
            int row = m0 + arow_l;
            int ch  = kb * 2 + akh;
            uint32_t off = row * 256 + ((ch ^ (row & 15)) << 4);
            LDSM_X4(ah, aHi + off);
        }
        #pragma unroll
        for (int p = 0; p < 4; p++) {
            int row = nb + p * 16 + brow_l;
            int ch  = kb * 2 + bkh;
            uint32_t off = row * 256 + ((ch ^ (row & 15)) << 4);
            LDSM_X4(bh[p], bB + off);
        }
        #pragma unroll
        for (int na = 0; na < 8; na++) {
            uint32_t b0 = bh[na >> 1][(na & 1) * 2];
            uint32_t b1 = bh[na >> 1][(na & 1) * 2 + 1];
            MMA_F16(acc[na], ah, b0, b1);
        }
    }
}

__global__ __launch_bounds__(256, 3) void edge_mma_kernel(
    const float* __restrict__ x, const float* __restrict__ vel,
    const void* __restrict__ eidx_raw, const float* __restrict__ We1,
    const float* __restrict__ be2, const float* __restrict__ bx1,
    const float* __restrict__ Wx2, const float* __restrict__ bx2,
    float* __restrict__ out_m, int E)
{
    extern __shared__ char smem[];
    float* smf = (float*)smem;
    const uint32_t sb = smem_u32(smem);
    const int tid  = threadIdx.x;
    const int warp = tid >> 5;
    const int lane = tid & 31;
    const int m0   = (warp & 3) * 16;   // GEMM row block (16 rows)
    const int nb   = (warp >> 2) * 64;  // GEMM col block
    const int rw0  = warp * 8;          // scalar phase: warp owns 8 edge rows
    const int c0   = lane * 4;          // scalar phase: lane owns 4 cols
    const int is64 = g_is64;

    // ---- one-time init: biases ----
    if (tid < 128) {
        smf[(SM_BE2 >> 2) + tid] = be2[tid];
        smf[(SM_BX1 >> 2) + tid] = bx1[tid];
        smf[(SM_WX2 >> 2) + tid] = Wx2[tid];
    }
    if (tid == 0) smf[SM_BX2 >> 2] = bx2[0];
    __syncthreads();

    float* geo_sf = smf + (SM_GEO >> 2);
    float* wgeo   = smf + (SM_AHI >> 2);     // WGEO aliases A-buffer head
    int*   dst_s  = (int*)(smem + SM_DST);
    int*   src_s  = (int*)(smem + SM_SRC);
    float* ppart  = smf + (SM_PPART >> 2);
    const uint4* gB = (const uint4*)g_B;

    const int ntiles = (E + TILE_M - 1) / TILE_M;

    for (int tile = blockIdx.x; tile < ntiles; tile += gridDim.x) {
        const int ebase = tile * TILE_M;

        // ===== stage: indices + geometry (tid<64); all: copy WGEO into A head =====
        float relx = 0.f, rely = 0.f, relz = 0.f;
        int dreg = 0; bool vreg = false;
        if (tid < TILE_M) {
            int eg = ebase + tid;
            vreg = (eg < E);
            int ec = vreg ? eg : 0;
            int s = load_idx(eidx_raw, ec, is64);
            int d = load_idx(eidx_raw, (long long)E + ec, is64);
            src_s[tid] = s; dst_s[tid] = d; dreg = d;
            float rx = x[s*3+0] - x[d*3+0];
            float ry = x[s*3+1] - x[d*3+1];
            float rz = x[s*3+2] - x[d*3+2];
            relx = rx; rely = ry; relz = rz;
            float d2 = rx*rx + ry*ry + rz*rz;
            float dist = fmaxf(sqrtf(d2), 1e-8f);
            float inv = 1.0f / dist;
            float ux = rx*inv, uy = ry*inv, uz = rz*inv;
            geo_sf[tid * 13 + 0] = d2;
            #pragma unroll
            for (int j = 0; j < 5; j++) {
                const float* vs = vel + (size_t)s * 15 + j * 3;
                const float* vd = vel + (size_t)d * 15 + j * 3;
                geo_sf[tid * 13 + 1 + j] = vs[0]*ux + vs[1]*uy + vs[2]*uz;
                geo_sf[tid * 13 + 6 + j] = vd[0]*ux + vd[1]*uy + vd[2]*uz;
            }
        }
        // WGEO: 11*128 f32 = 352 float4 from We1 rows 256..266 (L2-hot)
        {
            const float4* src = (const float4*)(We1 + 256 * D);
            float4* dst = (float4*)wgeo;
            for (int i = tid; i < 352; i += 256) dst[i] = src[i];
        }
        __syncthreads();

        // ===== scalar phase (column-mapped, coalesced gathers) =====
        float z[8][4];
        {
            #pragma unroll
            for (int i = 0; i < 8; i++) {
                int s2  = src_s[rw0 + i];
                int d2i = dst_s[rw0 + i];
                float4 u = *(const float4*)(g_U + (size_t)s2 * D + c0);
                float4 v = *(const float4*)(g_V + (size_t)d2i * D + c0);
                z[i][0] = u.x + v.x; z[i][1] = u.y + v.y;
                z[i][2] = u.z + v.z; z[i][3] = u.w + v.w;
            }
            #pragma unroll 1
            for (int k = 0; k < 11; k++) {
                float4 w = *(const float4*)(wgeo + k * D + c0);
                #pragma unroll
                for (int i = 0; i < 8; i++) {
                    float f = geo_sf[(rw0 + i) * 13 + k];   // LDS broadcast
                    z[i][0] = fmaf(f, w.x, z[i][0]);
                    z[i][1] = fmaf(f, w.y, z[i][1]);
                    z[i][2] = fmaf(f, w.z, z[i][2]);
                    z[i][3] = fmaf(f, w.w, z[i][3]);
                }
            }
        }
        __syncthreads();   // all WGEO reads complete before A stores clobber it

        // ===== store A hi/lo; concurrently fill W buffer with We2 image =====
        {
            const int chunk = c0 >> 3;
            const int sub   = (c0 & 7) * 2;
            #pragma unroll
            for (int i = 0; i < 8; i++) {
                int r = rw0 + i;
                float v0 = silu_f(z[i][0]), v1 = silu_f(z[i][1]);
                float v2 = silu_f(z[i][2]), v3 = silu_f(z[i][3]);
                uint32_t h0, l0, h1, l1;
                split2h(v0, v1, h0, l0);
                split2h(v2, v3, h1, l1);
                uint32_t off = r * 256 + ((chunk ^ (r & 15)) << 4) + sub;
                *(uint2*)(smem + SM_AHI + off) = make_uint2(h0, h1);
                *(uint2*)(smem + SM_ALO + off) = make_uint2(l0, l1);
            }
            for (int i = tid; i < 2048; i += 256)
                ((uint4*)(smem + SM_W))[i] = gB[i];          // We2 image
        }
        __syncthreads();

        // ===== GEMM1: y1 @ We2 (2-chain, exact split) =====
        float acc[8][4];
        gemm_tile16(sb + SM_AHI, sb + SM_ALO, sb + SM_W, lane, m0, nb, acc);
        __syncthreads();   // A + W reads done block-wide before overwrite

        // epilogue1: m = silu(acc + be2) -> A buffers; fill W with Wx1 image
        #pragma unroll
        for (int na = 0; na < 8; na++) {
            int col = nb + na * 8 + (lane & 3) * 2;
            float b0 = smf[(SM_BE2 >> 2) + col];
            float b1 = smf[(SM_BE2 >> 2) + col + 1];
            int rA = m0 + (lane >> 2);
            int rB = rA + 8;
            float v0 = silu_f(acc[na][0] + b0);
            float v1 = silu_f(acc[na][1] + b1);
            float v2 = silu_f(acc[na][2] + b0);
            float v3 = silu_f(acc[na][3] + b1);
            uint32_t hA, lA, hB, lB;
            split2h(v0, v1, hA, lA);
            split2h(v2, v3, hB, lB);
            uint32_t offA = rA * 256 + (((col >> 3) ^ (rA & 15)) << 4) + (col & 7) * 2;
            uint32_t offB = rB * 256 + (((col >> 3) ^ (rB & 15)) << 4) + (col & 7) * 2;
            *(uint32_t*)(smem + SM_AHI + offA) = hA;
            *(uint32_t*)(smem + SM_ALO + offA) = lA;
            *(uint32_t*)(smem + SM_AHI + offB) = hB;
            *(uint32_t*)(smem + SM_ALO + offB) = lB;
        }
        for (int i = tid; i < 2048; i += 256)
            ((uint4*)(smem + SM_W))[i] = gB[2048 + i];       // Wx1 image
        __syncthreads();

        // ===== GEMM2: m @ Wx1 (1-chain; output feeds phi_x scalar only) =====
        gemm_tile16_1c(sb + SM_AHI, sb + SM_W, lane, m0, nb, acc);

        // out_m + agg vector-red from A buffers (m = hi + lo), coalesced
        #pragma unroll 1
        for (int i = 0; i < 8; i++) {
            int row = warp * 8 + i;
            int eg = ebase + row;
            if (eg < E) {
                uint32_t off = row * 256 + ((((lane >> 1) ^ (row & 15))) << 4)
                             + (lane & 1) * 8;
                uint2 uh = *(const uint2*)(smem + SM_AHI + off);
                uint2 ul = *(const uint2*)(smem + SM_ALO + off);
                float4 f;
                f.x = hlo16(uh.x) + hlo16(ul.x);
                f.y = hhi16(uh.x) + hhi16(ul.x);
                f.z = hlo16(uh.y) + hlo16(ul.y);
                f.w = hhi16(uh.y) + hhi16(ul.y);
                *(float4*)(out_m + (size_t)eg * D + lane * 4) = f;
                red_add_f4(g_agg + (size_t)dst_s[row] * D + lane * 4, f);
            }
        }

        // phi_x tail: p_row = sum_col silu(acc2 + bx1)*wx2 (fragment reduce)
        {
            float ps[2] = {0.f, 0.f};
            #pragma unroll
            for (int na = 0; na < 8; na++) {
                int col = nb + na * 8 + (lane & 3) * 2;
                float b0 = smf[(SM_BX1 >> 2) + col];
                float b1 = smf[(SM_BX1 >> 2) + col + 1];
                float w0 = smf[(SM_WX2 >> 2) + col];
                float w1 = smf[(SM_WX2 >> 2) + col + 1];
                ps[0] += silu_f(acc[na][0] + b0) * w0
                       + silu_f(acc[na][1] + b1) * w1;
                ps[1] += silu_f(acc[na][2] + b0) * w0
                       + silu_f(acc[na][3] + b1) * w1;
            }
            #pragma unroll
            for (int q = 0; q < 2; q++) {
                ps[q] += __shfl_xor_sync(0xffffffffu, ps[q], 1);
                ps[q] += __shfl_xor_sync(0xffffffffu, ps[q], 2);
            }
            if ((lane & 3) == 0) {
                int base = (warp >> 2) * 64;
                int rA = m0 + (lane >> 2);
                ppart[base + rA]     = ps[0];
                ppart[base + rA + 8] = ps[1];
            }
        }
        __syncthreads();

        if (tid < TILE_M && vreg) {
            float p = ppart[tid] + ppart[64 + tid] + smf[SM_BX2 >> 2];
            atomicAdd(&g_num[dreg*3 + 0], relx * p);
            atomicAdd(&g_num[dreg*3 + 1], rely * p);
            atomicAdd(&g_num[dreg*3 + 2], relz * p);
            atomicAdd(&g_cnt[dreg], 1.0f);
        }
        __syncthreads();   // before next tile's WGEO copy / geo stage
    }
}

// ---------------- scalar GEMM helper: 8 rows x 4 cols per thread ----------------
#define GEMM_8x4(fr, PAD, W, KLEN, acc)                                        \
    _Pragma("unroll 1")                                                        \
    for (int k4 = 0; k4 < (KLEN); k4 += 4) {                                   \
        float4 f[8];                                                           \
        _Pragma("unroll")                                                      \
        for (int i = 0; i < 8; i++)                                            \
            f[i] = *(const float4*)((fr) + i * (PAD) + k4);                    \
        _Pragma("unroll")                                                      \
        for (int kk = 0; kk < 4; kk++) {                                       \
            float4 w = *(const float4*)((W) + (k4 + kk) * D + c0);             \
            _Pragma("unroll")                                                  \
            for (int i = 0; i < 8; i++) {                                      \
                float e = f4get(f[i], kk);                                     \
                acc[i][0] = fmaf(e, w.x, acc[i][0]);                           \
                acc[i][1] = fmaf(e, w.y, acc[i][1]);                           \
                acc[i][2] = fmaf(e, w.z, acc[i][2]);                           \
                acc[i][3] = fmaf(e, w.w, acc[i][3]);                           \
            }                                                                  \
        }                                                                      \
    }

// Per-node precompute: 128 threads, 4 warps x 8 nodes.
__global__ __launch_bounds__(128) void precompute_kernel(
    const float* __restrict__ h, const float* __restrict__ We1,
    const float* __restrict__ be1, int Nn)
{
    __shared__ float fs[32 * Y_PAD];
    const int warp = threadIdx.x >> 5;
    const int lane = threadIdx.x & 31;
    const int c0   = lane * 4;
    const int nbase = blockIdx.x * 32;

    int nidx[8]; bool valid[8];
    #pragma unroll
    for (int i = 0; i < 8; i++) {
        int nl = warp * 8 + i;
        int n  = nbase + nl;
        valid[i] = (n < Nn);
        nidx[i] = valid[i] ? n : 0;
        float4 hh = *(const float4*)(h + (size_t)nidx[i] * D + c0);
        *(float4*)(fs + nl * Y_PAD + c0) = hh;
    }
    __syncwarp();

    const float* fr = fs + (warp * 8) * Y_PAD;
    float acc[8][4];
    {
        float4 b = *(const float4*)(be1 + c0);
        #pragma unroll
        for (int i = 0; i < 8; i++) {
            acc[i][0] = b.x; acc[i][1] = b.y; acc[i][2] = b.z; acc[i][3] = b.w;
        }
    }
    GEMM_8x4(fr, Y_PAD, We1, 128, acc)
    #pragma unroll
    for (int i = 0; i < 8; i++)
        if (valid[i])
            *(float4*)(g_U + (size_t)nidx[i] * D + c0) =
                make_float4(acc[i][0], acc[i][1], acc[i][2], acc[i][3]);

    #pragma unroll
    for (int i = 0; i < 8; i++) {
        acc[i][0] = 0.f; acc[i][1] = 0.f; acc[i][2] = 0.f; acc[i][3] = 0.f;
    }
    GEMM_8x4(fr, Y_PAD, We1 + 128 * D, 128, acc)
    #pragma unroll
    for (int i = 0; i < 8; i++)
        if (valid[i])
            *(float4*)(g_V + (size_t)nidx[i] * D + c0) =
                make_float4(acc[i][0], acc[i][1], acc[i][2], acc[i][3]);
}

// Node kernel: 128 threads, 4 warps x 8 nodes.
__global__ __launch_bounds__(128) void node_kernel(
    const float* __restrict__ h, const float* __restrict__ x,
    const float* __restrict__ Wh1, const float* __restrict__ bh1,
    const float* __restrict__ Wh2, const float* __restrict__ bh2,
    const float* __restrict__ gamma, const float* __restrict__ beta,
    float* __restrict__ out_h, float* __restrict__ out_x, int Nn)
{
    __shared__ float fs[32 * NODE_PAD];
    const int warp = threadIdx.x >> 5;
    const int lane = threadIdx.x & 31;
    const int c0   = lane * 4;
    const int nbase = blockIdx.x * 32;

    bool valid[8];
    int nidx[8];
    #pragma unroll
    for (int i = 0; i < 8; i++) {
        int nl = warp * 8 + i;
        int n  = nbase + nl;
        valid[i] = (n < Nn);
        int nc = valid[i] ? n : 0;
        nidx[i] = nc;
        float4 hh = *(const float4*)(h + (size_t)nc * D + c0);
        float4 ag = *(const float4*)(g_agg + (size_t)nc * D + c0);
        *(float4*)(fs + nl * NODE_PAD + c0)       = hh;
        *(float4*)(fs + nl * NODE_PAD + 128 + c0) = ag;
    }
    __syncwarp();

    const float* fr = fs + (warp * 8) * NODE_PAD;
    float acc[8][4];
    {
        float4 b = *(const float4*)(bh1 + c0);
        #pragma unroll
        for (int i = 0; i < 8; i++) {
            acc[i][0] = b.x; acc[i][1] = b.y; acc[i][2] = b.z; acc[i][3] = b.w;
        }
    }
    GEMM_8x4(fr, NODE_PAD, Wh1, 256, acc)
    #pragma unroll
    for (int i = 0; i < 8; i++)
        #pragma unroll
        for (int q = 0; q < 4; q++) acc[i][q] = silu_f(acc[i][q]);

    __syncwarp();   // warp owns its 8 rows exclusively
    #pragma unroll
    for (int i = 0; i < 8; i++)
        *(float4*)(fs + (warp*8 + i) * NODE_PAD + c0) =
            make_float4(acc[i][0], acc[i][1], acc[i][2], acc[i][3]);
    __syncwarp();

    {
        float4 b = *(const float4*)(bh2 + c0);
        #pragma unroll
        for (int i = 0; i < 8; i++) {
            acc[i][0] = b.x; acc[i][1] = b.y; acc[i][2] = b.z; acc[i][3] = b.w;
        }
    }
    GEMM_8x4(fr, NODE_PAD, Wh2, 128, acc)

    float4 g = *(const float4*)(gamma + c0);
    float4 b = *(const float4*)(beta + c0);
    #pragma unroll
    for (int i = 0; i < 8; i++) {
        float4 hh = *(const float4*)(h + (size_t)nidx[i] * D + c0);
        float h0 = hh.x + acc[i][0];
        float h1 = hh.y + acc[i][1];
        float h2 = hh.z + acc[i][2];
        float h3 = hh.w + acc[i][3];
        float s1 = h0 + h1 + h2 + h3;
        float s2 = h0*h0 + h1*h1 + h2*h2 + h3*h3;
        #pragma unroll
        for (int off = 16; off > 0; off >>= 1) {
            s1 += __shfl_xor_sync(0xffffffffu, s1, off);
            s2 += __shfl_xor_sync(0xffffffffu, s2, off);
        }
        float mu = s1 * (1.0f / 128.0f);
        float var = s2 * (1.0f / 128.0f) - mu*mu;
        float rstd = rsqrtf(var + 1e-5f);
        if (valid[i]) {
            float4 o;
            o.x = (h0 - mu) * rstd * g.x + b.x;
            o.y = (h1 - mu) * rstd * g.y + b.y;
            o.z = (h2 - mu) * rstd * g.z + b.z;
            o.w = (h3 - mu) * rstd * g.w + b.w;
            *(float4*)(out_h + (size_t)nidx[i] * D + c0) = o;
        }
    }

    if (lane == 0) {
        #pragma unroll
        for (int i = 0; i < 8; i++) {
            if (valid[i]) {
                int n = nidx[i];
                float cnt = g_cnt[n];
                float inv = 1.0f / fmaxf(cnt, 1.0f);
                out_x[n*3 + 0] = x[n*3 + 0] + g_num[n*3 + 0] * inv;
                out_x[n*3 + 1] = x[n*3 + 1] + g_num[n*3 + 1] * inv;
                out_x[n*3 + 2] = x[n*3 + 2] + g_num[n*3 + 2] * inv;
            }
        }
    }
}

extern "C" void kernel_launch(void* const* d_in, const int* in_sizes, int n_in,
                              void* d_out, int out_size) {
    const float* h    = (const float*)d_in[0];
    const float* x    = (const float*)d_in[1];
    const float* vel  = (const float*)d_in[2];
    const void*  eidx = d_in[3];
    const float* We1 = (const float*)d_in[4],  *be1 = (const float*)d_in[5];
    const float* We2 = (const float*)d_in[6],  *be2 = (const float*)d_in[7];
    const float* Wx1 = (const float*)d_in[8],  *bx1 = (const float*)d_in[9];
    const float* Wx2 = (const float*)d_in[10], *bx2 = (const float*)d_in[11];
    const float* Wh1 = (const float*)d_in[12], *bh1 = (const float*)d_in[13];
    const float* Wh2 = (const float*)d_in[14], *bh2 = (const float*)d_in[15];
    const float* gamma = (const float*)d_in[16], *beta = (const float*)d_in[17];

    int Nn = in_sizes[0] / D;
    int E  = in_sizes[3] / 2;

    float* out   = (float*)d_out;
    float* out_h = out;
    float* out_x = out + (size_t)Nn * D;
    float* out_m = out_x + (size_t)Nn * 3;

    static int smem_set = 0;
    if (!smem_set) {
        cudaFuncSetAttribute(edge_mma_kernel,
                             cudaFuncAttributeMaxDynamicSharedMemorySize, SM_TOTAL);
        smem_set = 1;
    }

    detect_kernel<<<1, 1>>>(eidx, E, Nn);
    zero_kernel<<<(Nn * D + 255) / 256, 256>>>(Nn);
    prep_weights_kernel<<<(2 * 16384 + 255) / 256, 256>>>(We2, Wx1);
    precompute_kernel<<<(Nn + 31) / 32, 128>>>(h, We1, be1, Nn);
    edge_mma_kernel<<<444, 256, SM_TOTAL>>>(x, vel, eidx, We1,
                                            be2, bx1, Wx2, bx2, out_m, E);
    node_kernel<<<(Nn + 31) / 32, 128>>>(h, x, Wh1, bh1, Wh2, bh2,
                                         gamma, beta, out_h, out_x, Nn);
}

// round 15
// speedup vs baseline: 2.8245x; 1.2963x over previous
#include <cuda_runtime.h>
#include <cuda_fp16.h>
#include <cstdint>

#define D 128
#define MAXN 50000
#define TILE_M 64

// ---------------- device scratch (allocation-free rule) ----------------
__device__ float g_agg[MAXN * D];
__device__ float g_num[MAXN * 3];
__device__ float g_cnt[MAXN];
__device__ float g_U[MAXN * D];
__device__ float g_V[MAXN * D];
__device__ int   g_is64;
// fp16 weight images, XOR-swizzled [n][k] (256B rows):
// 0=We2, 1=Wx1, 2=We1top, 3=We1bot, 4=Wh1top, 5=Wh1bot, 6=Wh2
__device__ unsigned short g_B[7 * 16384];

__device__ __forceinline__ float silu_f(float v) {
    return v * (1.0f / (1.0f + __expf(-v)));
}
__device__ __forceinline__ uint32_t smem_u32(const void* p) {
    uint32_t a;
    asm("{ .reg .u64 t; cvta.to.shared.u64 t, %1; cvt.u32.u64 %0, t; }"
        : "=r"(a) : "l"(p));
    return a;
}
__device__ __forceinline__ void red_add_f4(float* ptr, float4 v) {
    asm volatile("red.global.add.v4.f32 [%0], {%1, %2, %3, %4};"
                 :: "l"(ptr), "f"(v.x), "f"(v.y), "f"(v.z), "f"(v.w)
                 : "memory");
}

#define LDSM_X4(r, addr)                                                        \
    asm volatile("ldmatrix.sync.aligned.m8n8.x4.shared.b16 {%0,%1,%2,%3}, [%4];"\
        : "=r"((r)[0]), "=r"((r)[1]), "=r"((r)[2]), "=r"((r)[3]) : "r"(addr))

#define MMA_F16(d, a, b0, b1)                                                   \
    asm volatile("mma.sync.aligned.m16n8k16.row.col.f32.f16.f16.f32 "           \
        "{%0,%1,%2,%3}, {%4,%5,%6,%7}, {%8,%9}, {%0,%1,%2,%3};"                 \
        : "+f"((d)[0]), "+f"((d)[1]), "+f"((d)[2]), "+f"((d)[3])                \
        : "r"((a)[0]), "r"((a)[1]), "r"((a)[2]), "r"((a)[3]), "r"(b0), "r"(b1))

__device__ __forceinline__ void split2h(float v0, float v1, uint32_t& hi, uint32_t& lo) {
    __half2 h = __floats2half2_rn(v0, v1);
    float2 hf = __half22float2(h);
    __half2 l = __floats2half2_rn(v0 - hf.x, v1 - hf.y);
    hi = *reinterpret_cast<uint32_t*>(&h);
    lo = *reinterpret_cast<uint32_t*>(&l);
}
__device__ __forceinline__ float hlo16(uint32_t u) {
    return __half2float(__ushort_as_half((unsigned short)(u & 0xffff)));
}
__device__ __forceinline__ float hhi16(uint32_t u) {
    return __half2float(__ushort_as_half((unsigned short)(u >> 16)));
}

// ---------------- misc small kernels ----------------
__global__ void detect_kernel(const void* eidx_raw, int E, int Nn) {
    const long long* p = (const long long*)eidx_raw;
    int ok = 1;
    for (int i = 0; i < 64 && i < E; i++) {
        long long v = p[i];
        if (v < 0 || v >= (long long)Nn) { ok = 0; break; }
    }
    g_is64 = ok;
}
__device__ __forceinline__ int load_idx(const void* eidx_raw, long long pos, int is64) {
    if (is64) return (int)((const long long*)eidx_raw)[pos];
    return ((const int*)eidx_raw)[pos];
}

// Build 7 fp16 images in swizzled [n][k] layout.
__global__ void prep_weights_kernel(const float* __restrict__ We2,
                                    const float* __restrict__ Wx1,
                                    const float* __restrict__ We1,
                                    const float* __restrict__ Wh1,
                                    const float* __restrict__ Wh2) {
    int idx = blockIdx.x * blockDim.x + threadIdx.x;
    if (idx >= 7 * 16384) return;
    int m = idx >> 14;
    int e = idx & 16383;
    int n = e >> 7;
    int k = e & 127;
    float v;
    switch (m) {
        case 0: v = We2[k * D + n]; break;
        case 1: v = Wx1[k * D + n]; break;
        case 2: v = We1[k * D + n]; break;
        case 3: v = We1[(128 + k) * D + n]; break;
        case 4: v = Wh1[k * D + n]; break;
        case 5: v = Wh1[(128 + k) * D + n]; break;
        default: v = Wh2[k * D + n]; break;
    }
    int off = n * 256 + (((k >> 3) ^ (n & 15)) << 4) + (k & 7) * 2;
    g_B[m * 16384 + (off >> 1)] = __half_as_ushort(__float2half_rn(v));
}

// ---------------- GEMM cores ----------------
// Accumulating 2-chain fp16 GEMM step: acc += (A_hi + A_lo) @ B^T, warp 16x64.
__device__ __forceinline__ void gemm_acc16(
    uint32_t aHi, uint32_t aLo, uint32_t bB,
    int lane, int m0, int nb, float acc[8][4])
{
    const int arow_l = lane & 15;
    const int akh    = lane >> 4;
    const int brow_l = ((lane >> 4) & 1) * 8 + (lane & 7);
    const int bkh    = (lane >> 3) & 1;

    #pragma unroll 1
    for (int kb = 0; kb < 8; kb++) {
        uint32_t ah[4], al[4], bh[4][4];
        {
            int row = m0 + arow_l;
            int ch  = kb * 2 + akh;
            uint32_t off = row * 256 + ((ch ^ (row & 15)) << 4);
            LDSM_X4(ah, aHi + off);
            LDSM_X4(al, aLo + off);
        }
        #pragma unroll
        for (int p = 0; p < 4; p++) {
            int row = nb + p * 16 + brow_l;
            int ch  = kb * 2 + bkh;
            uint32_t off = row * 256 + ((ch ^ (row & 15)) << 4);
            LDSM_X4(bh[p], bB + off);
        }
        #pragma unroll
        for (int na = 0; na < 8; na++) {
            uint32_t b0 = bh[na >> 1][(na & 1) * 2];
            uint32_t b1 = bh[na >> 1][(na & 1) * 2 + 1];
            MMA_F16(acc[na], ah, b0, b1);
            MMA_F16(acc[na], al, b0, b1);
        }
    }
}

__device__ __forceinline__ void gemm_tile16(
    uint32_t aHi, uint32_t aLo, uint32_t bB,
    int lane, int m0, int nb, float acc[8][4])
{
    #pragma unroll
    for (int na = 0; na < 8; na++)
        #pragma unroll
        for (int q = 0; q < 4; q++) acc[na][q] = 0.f;
    gemm_acc16(aHi, aLo, bB, lane, m0, nb, acc);
}

// 1-chain variant (A_hi only).
__device__ __forceinline__ void gemm_tile16_1c(
    uint32_t aHi, uint32_t bB,
    int lane, int m0, int nb, float acc[8][4])
{
    #pragma unroll
    for (int na = 0; na < 8; na++)
        #pragma unroll
        for (int q = 0; q < 4; q++) acc[na][q] = 0.f;

    const int arow_l = lane & 15;
    const int akh    = lane >> 4;
    const int brow_l = ((lane >> 4) & 1) * 8 + (lane & 7);
    const int bkh    = (lane >> 3) & 1;

    #pragma unroll 1
    for (int kb = 0; kb < 8; kb++) {
        uint32_t ah[4], bh[4][4];
        {
            int row = m0 + arow_l;
            int ch  = kb * 2 + akh;
            uint32_t off = row * 256 + ((ch ^ (row & 15)) << 4);
            LDSM_X4(ah, aHi + off);
        }
        #pragma unroll
        for (int p = 0; p < 4; p++) {
            int row = nb + p * 16 + brow_l;
            int ch  = kb * 2 + bkh;
            uint32_t off = row * 256 + ((ch ^ (row & 15)) << 4);
            LDSM_X4(bh[p], bB + off);
        }
        #pragma unroll
        for (int na = 0; na < 8; na++) {
            uint32_t b0 = bh[na >> 1][(na & 1) * 2];
            uint32_t b1 = bh[na >> 1][(na & 1) * 2 + 1];
            MMA_F16(acc[na], ah, b0, b1);
        }
    }
}

// ---------------- edge kernel SMEM (bytes), unchanged from R14 ----------------
#define SM_W    0
#define SM_AHI  32768
#define SM_ALO  49152
#define SM_GEO  65536
#define SM_DST  68864
#define SM_SRC  69120
#define SM_BE2  69376
#define SM_BX1  69888
#define SM_WX2  70400
#define SM_PPART 70912
#define SM_BX2  71424
#define SM_TOTAL 71440

__global__ __launch_bounds__(256, 3) void edge_mma_kernel(
    const float* __restrict__ x, const float* __restrict__ vel,
    const void* __restrict__ eidx_raw, const float* __restrict__ We1,
    const float* __restrict__ be2, const float* __restrict__ bx1,
    const float* __restrict__ Wx2, const float* __restrict__ bx2,
    float* __restrict__ out_m, int E)
{
    extern __shared__ char smem[];
    float* smf = (float*)smem;
    const uint32_t sb = smem_u32(smem);
    const int tid  = threadIdx.x;
    const int warp = tid >> 5;
    const int lane = tid & 31;
    const int m0   = (warp & 3) * 16;
    const int nb   = (warp >> 2) * 64;
    const int rw0  = warp * 8;
    const int c0   = lane * 4;
    const int is64 = g_is64;

    if (tid < 128) {
        smf[(SM_BE2 >> 2) + tid] = be2[tid];
        smf[(SM_BX1 >> 2) + tid] = bx1[tid];
        smf[(SM_WX2 >> 2) + tid] = Wx2[tid];
    }
    if (tid == 0) smf[SM_BX2 >> 2] = bx2[0];
    __syncthreads();

    float* geo_sf = smf + (SM_GEO >> 2);
    float* wgeo   = smf + (SM_AHI >> 2);
    int*   dst_s  = (int*)(smem + SM_DST);
    int*   src_s  = (int*)(smem + SM_SRC);
    float* ppart  = smf + (SM_PPART >> 2);
    const uint4* gB = (const uint4*)g_B;

    const int ntiles = (E + TILE_M - 1) / TILE_M;

    for (int tile = blockIdx.x; tile < ntiles; tile += gridDim.x) {
        const int ebase = tile * TILE_M;

        float relx = 0.f, rely = 0.f, relz = 0.f;
        int dreg = 0; bool vreg = false;
        if (tid < TILE_M) {
            int eg = ebase + tid;
            vreg = (eg < E);
            int ec = vreg ? eg : 0;
            int s = load_idx(eidx_raw, ec, is64);
            int d = load_idx(eidx_raw, (long long)E + ec, is64);
            src_s[tid] = s; dst_s[tid] = d; dreg = d;
            float rx = x[s*3+0] - x[d*3+0];
            float ry = x[s*3+1] - x[d*3+1];
            float rz = x[s*3+2] - x[d*3+2];
            relx = rx; rely = ry; relz = rz;
            float d2 = rx*rx + ry*ry + rz*rz;
            float dist = fmaxf(sqrtf(d2), 1e-8f);
            float inv = 1.0f / dist;
            float ux = rx*inv, uy = ry*inv, uz = rz*inv;
            geo_sf[tid * 13 + 0] = d2;
            #pragma unroll
            for (int j = 0; j < 5; j++) {
                const float* vs = vel + (size_t)s * 15 + j * 3;
                const float* vd = vel + (size_t)d * 15 + j * 3;
                geo_sf[tid * 13 + 1 + j] = vs[0]*ux + vs[1]*uy + vs[2]*uz;
                geo_sf[tid * 13 + 6 + j] = vd[0]*ux + vd[1]*uy + vd[2]*uz;
            }
        }
        {
            const float4* src = (const float4*)(We1 + 256 * D);
            float4* dst = (float4*)wgeo;
            for (int i = tid; i < 352; i += 256) dst[i] = src[i];
        }
        __syncthreads();

        float z[8][4];
        {
            #pragma unroll
            for (int i = 0; i < 8; i++) {
                int s2  = src_s[rw0 + i];
                int d2i = dst_s[rw0 + i];
                float4 u = *(const float4*)(g_U + (size_t)s2 * D + c0);
                float4 v = *(const float4*)(g_V + (size_t)d2i * D + c0);
                z[i][0] = u.x + v.x; z[i][1] = u.y + v.y;
                z[i][2] = u.z + v.z; z[i][3] = u.w + v.w;
            }
            #pragma unroll 1
            for (int k = 0; k < 11; k++) {
                float4 w = *(const float4*)(wgeo + k * D + c0);
                #pragma unroll
                for (int i = 0; i < 8; i++) {
                    float f = geo_sf[(rw0 + i) * 13 + k];
                    z[i][0] = fmaf(f, w.x, z[i][0]);
                    z[i][1] = fmaf(f, w.y, z[i][1]);
                    z[i][2] = fmaf(f, w.z, z[i][2]);
                    z[i][3] = fmaf(f, w.w, z[i][3]);
                }
            }
        }
        __syncthreads();

        {
            const int chunk = c0 >> 3;
            const int sub   = (c0 & 7) * 2;
            #pragma unroll
            for (int i = 0; i < 8; i++) {
                int r = rw0 + i;
                float v0 = silu_f(z[i][0]), v1 = silu_f(z[i][1]);
                float v2 = silu_f(z[i][2]), v3 = silu_f(z[i][3]);
                uint32_t h0, l0, h1, l1;
                split2h(v0, v1, h0, l0);
                split2h(v2, v3, h1, l1);
                uint32_t off = r * 256 + ((chunk ^ (r & 15)) << 4) + sub;
                *(uint2*)(smem + SM_AHI + off) = make_uint2(h0, h1);
                *(uint2*)(smem + SM_ALO + off) = make_uint2(l0, l1);
            }
            for (int i = tid; i < 2048; i += 256)
                ((uint4*)(smem + SM_W))[i] = gB[i];
        }
        __syncthreads();

        float acc[8][4];
        gemm_tile16(sb + SM_AHI, sb + SM_ALO, sb + SM_W, lane, m0, nb, acc);
        __syncthreads();

        #pragma unroll
        for (int na = 0; na < 8; na++) {
            int col = nb + na * 8 + (lane & 3) * 2;
            float b0 = smf[(SM_BE2 >> 2) + col];
            float b1 = smf[(SM_BE2 >> 2) + col + 1];
            int rA = m0 + (lane >> 2);
            int rB = rA + 8;
            float v0 = silu_f(acc[na][0] + b0);
            float v1 = silu_f(acc[na][1] + b1);
            float v2 = silu_f(acc[na][2] + b0);
            float v3 = silu_f(acc[na][3] + b1);
            uint32_t hA, lA, hB, lB;
            split2h(v0, v1, hA, lA);
            split2h(v2, v3, hB, lB);
            uint32_t offA = rA * 256 + (((col >> 3) ^ (rA & 15)) << 4) + (col & 7) * 2;
            uint32_t offB = rB * 256 + (((col >> 3) ^ (rB & 15)) << 4) + (col & 7) * 2;
            *(uint32_t*)(smem + SM_AHI + offA) = hA;
            *(uint32_t*)(smem + SM_ALO + offA) = lA;
            *(uint32_t*)(smem + SM_AHI + offB) = hB;
            *(uint32_t*)(smem + SM_ALO + offB) = lB;
        }
        for (int i = tid; i < 2048; i += 256)
            ((uint4*)(smem + SM_W))[i] = gB[2048 + i];
        __syncthreads();

        gemm_tile16_1c(sb + SM_AHI, sb + SM_W, lane, m0, nb, acc);

        #pragma unroll 1
        for (int i = 0; i < 8; i++) {
            int row = warp * 8 + i;
            int eg = ebase + row;
            if (eg < E) {
                uint32_t off = row * 256 + ((((lane >> 1) ^ (row & 15))) << 4)
                             + (lane & 1) * 8;
                uint2 uh = *(const uint2*)(smem + SM_AHI + off);
                uint2 ul = *(const uint2*)(smem + SM_ALO + off);
                float4 f;
                f.x = hlo16(uh.x) + hlo16(ul.x);
                f.y = hhi16(uh.x) + hhi16(ul.x);
                f.z = hlo16(uh.y) + hlo16(ul.y);
                f.w = hhi16(uh.y) + hhi16(ul.y);
                *(float4*)(out_m + (size_t)eg * D + lane * 4) = f;
                red_add_f4(g_agg + (size_t)dst_s[row] * D + lane * 4, f);
            }
        }

        {
            float ps[2] = {0.f, 0.f};
            #pragma unroll
            for (int na = 0; na < 8; na++) {
                int col = nb + na * 8 + (lane & 3) * 2;
                float b0 = smf[(SM_BX1 >> 2) + col];
                float b1 = smf[(SM_BX1 >> 2) + col + 1];
                float w0 = smf[(SM_WX2 >> 2) + col];
                float w1 = smf[(SM_WX2 >> 2) + col + 1];
                ps[0] += silu_f(acc[na][0] + b0) * w0
                       + silu_f(acc[na][1] + b1) * w1;
                ps[1] += silu_f(acc[na][2] + b0) * w0
                       + silu_f(acc[na][3] + b1) * w1;
            }
            #pragma unroll
            for (int q = 0; q < 2; q++) {
                ps[q] += __shfl_xor_sync(0xffffffffu, ps[q], 1);
                ps[q] += __shfl_xor_sync(0xffffffffu, ps[q], 2);
            }
            if ((lane & 3) == 0) {
                int base = (warp >> 2) * 64;
                int rA = m0 + (lane >> 2);
                ppart[base + rA]     = ps[0];
                ppart[base + rA + 8] = ps[1];
            }
        }
        __syncthreads();

        if (tid < TILE_M && vreg) {
            float p = ppart[tid] + ppart[64 + tid] + smf[SM_BX2 >> 2];
            atomicAdd(&g_num[dreg*3 + 0], relx * p);
            atomicAdd(&g_num[dreg*3 + 1], rely * p);
            atomicAdd(&g_num[dreg*3 + 2], relz * p);
            atomicAdd(&g_cnt[dreg], 1.0f);
        }
        __syncthreads();
    }
}

// ---------------- node-side HMMA kernels ----------------
// Shared smem template: W(32K) + AHI(16K) + ALO(16K) + stat bufs
#define SMN_W    0
#define SMN_AHI  32768
#define SMN_ALO  49152
#define SMN_S1   65536   // 2*64 f32
#define SMN_S2   66048   // 2*64 f32
#define SMN_TOTAL 66560

// stage 64 rows x 128 cols of src (f32) into split A buffers (fragment smem)
__device__ __forceinline__ void stage_split(
    char* smem, const float* __restrict__ src, int nbase, int Nn,
    int rw0, int c0)
{
    const int chunk = c0 >> 3;
    const int sub   = (c0 & 7) * 2;
    #pragma unroll
    for (int i = 0; i < 8; i++) {
        int r = rw0 + i;
        int n = nbase + r;
        int nc = (n < Nn) ? n : 0;
        float4 hv = *(const float4*)(src + (size_t)nc * D + c0);
        uint32_t h0, l0, h1, l1;
        split2h(hv.x, hv.y, h0, l0);
        split2h(hv.z, hv.w, h1, l1);
        uint32_t off = r * 256 + ((chunk ^ (r & 15)) << 4) + sub;
        *(uint2*)(smem + SMN_AHI + off) = make_uint2(h0, h1);
        *(uint2*)(smem + SMN_ALO + off) = make_uint2(l0, l1);
    }
}

// Precompute: U = h @ We1top + be1, V = h @ We1bot. Also zeros agg/num/cnt.
__global__ __launch_bounds__(256, 3) void precompute_mma_kernel(
    const float* __restrict__ h, const float* __restrict__ be1, int Nn)
{
    extern __shared__ char smem[];
    const uint32_t sb = smem_u32(smem);
    const int tid  = threadIdx.x;
    const int warp = tid >> 5;
    const int lane = tid & 31;
    const int m0   = (warp & 3) * 16;
    const int nb   = (warp >> 2) * 64;
    const int rw0  = warp * 8;
    const int c0   = lane * 4;
    const int nbase = blockIdx.x * TILE_M;
    const uint4* gB = (const uint4*)g_B;

    // stage h -> A; fill W = We1top; zero scratch for this tile
    stage_split(smem, h, nbase, Nn, rw0, c0);
    for (int i = tid; i < 2048; i += 256)
        ((uint4*)(smem + SMN_W))[i] = gB[2 * 2048 + i];
    {
        float4 z4 = make_float4(0.f, 0.f, 0.f, 0.f);
        for (int i = tid; i < 64 * 32; i += 256) {
            int r = i >> 5;
            int n = nbase + r;
            if (n < Nn)
                ((float4*)(g_agg + (size_t)n * D))[i & 31] = z4;
        }
        if (tid < TILE_M) {
            int n = nbase + tid;
            if (n < Nn) {
                g_num[n*3+0] = 0.f; g_num[n*3+1] = 0.f; g_num[n*3+2] = 0.f;
                g_cnt[n] = 0.f;
            }
        }
    }
    __syncthreads();

    float acc[8][4];
    const int colb = nb + (lane & 3) * 2;
    const int rA = m0 + (lane >> 2);
    const int rB = rA + 8;

    // U = h @ We1top + be1
    #pragma unroll
    for (int na = 0; na < 8; na++) {
        int col = colb + na * 8;
        float b0 = be1[col], b1 = be1[col + 1];
        acc[na][0] = b0; acc[na][1] = b1; acc[na][2] = b0; acc[na][3] = b1;
    }
    gemm_acc16(sb + SMN_AHI, sb + SMN_ALO, sb + SMN_W, lane, m0, nb, acc);
    #pragma unroll
    for (int na = 0; na < 8; na++) {
        int col = colb + na * 8;
        if (nbase + rA < Nn)
            *(float2*)(g_U + (size_t)(nbase + rA) * D + col) =
                make_float2(acc[na][0], acc[na][1]);
        if (nbase + rB < Nn)
            *(float2*)(g_U + (size_t)(nbase + rB) * D + col) =
                make_float2(acc[na][2], acc[na][3]);
    }
    __syncthreads();   // W reads done
    for (int i = tid; i < 2048; i += 256)
        ((uint4*)(smem + SMN_W))[i] = gB[3 * 2048 + i];   // We1bot
    __syncthreads();

    // V = h @ We1bot
    gemm_tile16(sb + SMN_AHI, sb + SMN_ALO, sb + SMN_W, lane, m0, nb, acc);
    #pragma unroll
    for (int na = 0; na < 8; na++) {
        int col = colb + na * 8;
        if (nbase + rA < Nn)
            *(float2*)(g_V + (size_t)(nbase + rA) * D + col) =
                make_float2(acc[na][0], acc[na][1]);
        if (nbase + rB < Nn)
            *(float2*)(g_V + (size_t)(nbase + rB) * D + col) =
                make_float2(acc[na][2], acc[na][3]);
    }
}

// Node: dh = silu(h@Wh1top + agg@Wh1bot + bh1) @ Wh2 + bh2; h' = LN(h + dh).
__global__ __launch_bounds__(256, 3) void node_mma_kernel(
    const float* __restrict__ h, const float* __restrict__ x,
    const float* __restrict__ bh1, const float* __restrict__ bh2,
    const float* __restrict__ gamma, const float* __restrict__ beta,
    float* __restrict__ out_h, float* __restrict__ out_x, int Nn)
{
    extern __shared__ char smem[];
    float* smf = (float*)smem;
    const uint32_t sb = smem_u32(smem);
    const int tid  = threadIdx.x;
    const int warp = tid >> 5;
    const int lane = tid & 31;
    const int m0   = (warp & 3) * 16;
    const int nb   = (warp >> 2) * 64;
    const int rw0  = warp * 8;
    const int c0   = lane * 4;
    const int nbase = blockIdx.x * TILE_M;
    const uint4* gB = (const uint4*)g_B;
    const int wg = warp >> 2;

    // stage h -> A; fill W = Wh1top
    stage_split(smem, h, nbase, Nn, rw0, c0);
    for (int i = tid; i < 2048; i += 256)
        ((uint4*)(smem + SMN_W))[i] = gB[4 * 2048 + i];
    __syncthreads();

    float acc[8][4];
    const int colb = nb + (lane & 3) * 2;
    const int rA = m0 + (lane >> 2);
    const int rB = rA + 8;
    const int nA = nbase + rA;
    const int nB = nbase + rB;
    const int nAc = (nA < Nn) ? nA : 0;
    const int nBc = (nB < Nn) ? nB : 0;

    // acc = bh1; += h @ Wh1top
    #pragma unroll
    for (int na = 0; na < 8; na++) {
        int col = colb + na * 8;
        float b0 = bh1[col], b1 = bh1[col + 1];
        acc[na][0] = b0; acc[na][1] = b1; acc[na][2] = b0; acc[na][3] = b1;
    }
    gemm_acc16(sb + SMN_AHI, sb + SMN_ALO, sb + SMN_W, lane, m0, nb, acc);
    __syncthreads();

    // stage agg -> A; fill W = Wh1bot
    stage_split(smem, g_agg, nbase, Nn, rw0, c0);
    for (int i = tid; i < 2048; i += 256)
        ((uint4*)(smem + SMN_W))[i] = gB[5 * 2048 + i];
    __syncthreads();

    // acc += agg @ Wh1bot
    gemm_acc16(sb + SMN_AHI, sb + SMN_ALO, sb + SMN_W, lane, m0, nb, acc);
    __syncthreads();

    // epilogue: y = silu(acc) -> A (fragment layout); fill W = Wh2
    #pragma unroll
    for (int na = 0; na < 8; na++) {
        int col = colb + na * 8;
        float v0 = silu_f(acc[na][0]);
        float v1 = silu_f(acc[na][1]);
        float v2 = silu_f(acc[na][2]);
        float v3 = silu_f(acc[na][3]);
        uint32_t hA, lA, hB, lB;
        split2h(v0, v1, hA, lA);
        split2h(v2, v3, hB, lB);
        uint32_t offA = rA * 256 + (((col >> 3) ^ (rA & 15)) << 4) + (col & 7) * 2;
        uint32_t offB = rB * 256 + (((col >> 3) ^ (rB & 15)) << 4) + (col & 7) * 2;
        *(uint32_t*)(smem + SMN_AHI + offA) = hA;
        *(uint32_t*)(smem + SMN_ALO + offA) = lA;
        *(uint32_t*)(smem + SMN_AHI + offB) = hB;
        *(uint32_t*)(smem + SMN_ALO + offB) = lB;
    }
    for (int i = tid; i < 2048; i += 256)
        ((uint4*)(smem + SMN_W))[i] = gB[6 * 2048 + i];
    __syncthreads();

    // acc = bh2; += y @ Wh2  -> dh
    #pragma unroll
    for (int na = 0; na < 8; na++) {
        int col = colb + na * 8;
        float b0 = bh2[col], b1 = bh2[col + 1];
        acc[na][0] = b0; acc[na][1] = b1; acc[na][2] = b0; acc[na][3] = b1;
    }
    gemm_acc16(sb + SMN_AHI, sb + SMN_ALO, sb + SMN_W, lane, m0, nb, acc);

    // residual: hn = h + dh (in fragments); row sums for LN
    float hv[8][4];
    float s1A = 0.f, s2A = 0.f, s1B = 0.f, s2B = 0.f;
    #pragma unroll
    for (int na = 0; na < 8; na++) {
        int col = colb + na * 8;
        float2 ha = *(const float2*)(h + (size_t)nAc * D + col);
        float2 hb = *(const float2*)(h + (size_t)nBc * D + col);
        hv[na][0] = ha.x + acc[na][0];
        hv[na][1] = ha.y + acc[na][1];
        hv[na][2] = hb.x + acc[na][2];
        hv[na][3] = hb.y + acc[na][3];
        s1A += hv[na][0] + hv[na][1];
        s2A += hv[na][0]*hv[na][0] + hv[na][1]*hv[na][1];
        s1B += hv[na][2] + hv[na][3];
        s2B += hv[na][2]*hv[na][2] + hv[na][3]*hv[na][3];
    }
    // reduce over the 4 lanes sharing a row
    s1A += __shfl_xor_sync(0xffffffffu, s1A, 1);
    s1A += __shfl_xor_sync(0xffffffffu, s1A, 2);
    s2A += __shfl_xor_sync(0xffffffffu, s2A, 1);
    s2A += __shfl_xor_sync(0xffffffffu, s2A, 2);
    s1B += __shfl_xor_sync(0xffffffffu, s1B, 1);
    s1B += __shfl_xor_sync(0xffffffffu, s1B, 2);
    s2B += __shfl_xor_sync(0xffffffffu, s2B, 1);
    s2B += __shfl_xor_sync(0xffffffffu, s2B, 2);

    float* s1buf = smf + (SMN_S1 >> 2);
    float* s2buf = smf + (SMN_S2 >> 2);
    if ((lane & 3) == 0) {
        s1buf[wg * 64 + rA] = s1A;
        s1buf[wg * 64 + rB] = s1B;
        s2buf[wg * 64 + rA] = s2A;
        s2buf[wg * 64 + rB] = s2B;
    }
    __syncthreads();

    float s1t = s1buf[rA] + s1buf[64 + rA];
    float s2t = s2buf[rA] + s2buf[64 + rA];
    float muA = s1t * (1.0f / 128.0f);
    float rsA = rsqrtf(s2t * (1.0f / 128.0f) - muA * muA + 1e-5f);
    s1t = s1buf[rB] + s1buf[64 + rB];
    s2t = s2buf[rB] + s2buf[64 + rB];
    float muB = s1t * (1.0f / 128.0f);
    float rsB = rsqrtf(s2t * (1.0f / 128.0f) - muB * muB + 1e-5f);

    #pragma unroll
    for (int na = 0; na < 8; na++) {
        int col = colb + na * 8;
        float g0 = gamma[col], g1 = gamma[col + 1];
        float b0 = beta[col],  b1 = beta[col + 1];
        if (nA < Nn)
            *(float2*)(out_h + (size_t)nA * D + col) =
                make_float2((hv[na][0] - muA) * rsA * g0 + b0,
                            (hv[na][1] - muA) * rsA * g1 + b1);
        if (nB < Nn)
            *(float2*)(out_h + (size_t)nB * D + col) =
                make_float2((hv[na][2] - muB) * rsB * g0 + b0,
                            (hv[na][3] - muB) * rsB * g1 + b1);
    }

    // x update
    if (tid < TILE_M) {
        int n = nbase + tid;
        if (n < Nn) {
            float cnt = g_cnt[n];
            float inv = 1.0f / fmaxf(cnt, 1.0f);
            out_x[n*3 + 0] = x[n*3 + 0] + g_num[n*3 + 0] * inv;
            out_x[n*3 + 1] = x[n*3 + 1] + g_num[n*3 + 1] * inv;
            out_x[n*3 + 2] = x[n*3 + 2] + g_num[n*3 + 2] * inv;
        }
    }
}

extern "C" void kernel_launch(void* const* d_in, const int* in_sizes, int n_in,
                              void* d_out, int out_size) {
    const float* h    = (const float*)d_in[0];
    const float* x    = (const float*)d_in[1];
    const float* vel  = (const float*)d_in[2];
    const void*  eidx = d_in[3];
    const float* We1 = (const float*)d_in[4],  *be1 = (const float*)d_in[5];
    const float* We2 = (const float*)d_in[6],  *be2 = (const float*)d_in[7];
    const float* Wx1 = (const float*)d_in[8],  *bx1 = (const float*)d_in[9];
    const float* Wx2 = (const float*)d_in[10], *bx2 = (const float*)d_in[11];
    const float* Wh1 = (const float*)d_in[12], *bh1 = (const float*)d_in[13];
    const float* Wh2 = (const float*)d_in[14], *bh2 = (const float*)d_in[15];
    const float* gamma = (const float*)d_in[16], *beta = (const float*)d_in[17];

    int Nn = in_sizes[0] / D;
    int E  = in_sizes[3] / 2;

    float* out   = (float*)d_out;
    float* out_h = out;
    float* out_x = out + (size_t)Nn * D;
    float* out_m = out_x + (size_t)Nn * 3;

    static int smem_set = 0;
    if (!smem_set) {
        cudaFuncSetAttribute(edge_mma_kernel,
                             cudaFuncAttributeMaxDynamicSharedMemorySize, SM_TOTAL);
        cudaFuncSetAttribute(precompute_mma_kernel,
                             cudaFuncAttributeMaxDynamicSharedMemorySize, SMN_TOTAL);
        cudaFuncSetAttribute(node_mma_kernel,
                             cudaFuncAttributeMaxDynamicSharedMemorySize, SMN_TOTAL);
        smem_set = 1;
    }

    int ntile_n = (Nn + TILE_M - 1) / TILE_M;

    detect_kernel<<<1, 1>>>(eidx, E, Nn);
    prep_weights_kernel<<<(7 * 16384 + 255) / 256, 256>>>(We2, Wx1, We1, Wh1, Wh2);
    precompute_mma_kernel<<<ntile_n, 256, SMN_TOTAL>>>(h, be1, Nn);
    edge_mma_kernel<<<444, 256, SM_TOTAL>>>(x, vel, eidx, We1,
                                            be2, bx1, Wx2, bx2, out_m, E);
    node_mma_kernel<<<ntile_n, 256, SMN_TOTAL>>>(h, x, bh1, bh2,
                                                 gamma, beta, out_h, out_x, Nn);
}